// round 2
// baseline (speedup 1.0000x reference)
#include <cuda_runtime.h>
#include <stdint.h>

#define N_NODES 100000
#define N_EDGES 1600000
#define IN_F 50
#define HID 256
#define OUT_F 121

// ---------------- scratch (static __device__, no allocation) ----------------
__device__ int   g_flag;                              // 1 => edge_index is int32
__device__ int   g_row32[N_EDGES];
__device__ int   g_col32[N_EDGES];
__device__ int   g_deg[N_NODES];
__device__ float g_dinv[N_NODES];
__device__ int   g_off[N_NODES + 1];
__device__ int   g_cur[N_NODES];
__device__ int   g_csr[N_EDGES];
__device__ int   g_bsum[128];
__device__ float g_agg1[(size_t)N_NODES * IN_F];     // 20 MB
__device__ float g_h1  [(size_t)N_NODES * HID];      // 100 MB (reused: h1 then h2)
__device__ float g_agg2[(size_t)N_NODES * HID];      // 100 MB
__device__ float g_t3  [(size_t)N_NODES * OUT_F];    // 48 MB

// ---------------- edge dtype probe + canonicalize to int32 ------------------
// If the buffer is int32 (JAX x64 disabled), reading it as int64 yields
// lo|hi<<32 values far outside [0, N_NODES). Probe 4096 words (in bounds for
// both layouts: 4096*8B << 12.8MB).
__global__ void k_detect(const long long* __restrict__ ei64) {
    int e = blockIdx.x * blockDim.x + threadIdx.x;
    if (e == 0) { /* flag already zeroed by k_zero */ }
    if (e < 4096) {
        long long v = ei64[e];
        if (v < 0 || v >= N_NODES) atomicOr(&g_flag, 1);
    }
}

__global__ void k_zero_flag() { if (threadIdx.x == 0 && blockIdx.x == 0) g_flag = 0; }

__global__ void k_convert(const void* __restrict__ ei) {
    int e = blockIdx.x * blockDim.x + threadIdx.x;
    if (e >= N_EDGES) return;
    if (g_flag) {
        const int* p = (const int*)ei;
        g_row32[e] = p[e];
        g_col32[e] = p[N_EDGES + e];
    } else {
        const long long* p = (const long long*)ei;
        g_row32[e] = (int)p[e];
        g_col32[e] = (int)p[N_EDGES + e];
    }
}

// ---------------- graph preprocessing: degree, dinv, CSR by destination ----

__global__ void k_init() {
    int v = blockIdx.x * blockDim.x + threadIdx.x;
    if (v < N_NODES) { g_deg[v] = 1; g_cur[v] = 0; }  // deg starts at 1 (self loop)
}

__global__ void k_count() {
    int e = blockIdx.x * blockDim.x + threadIdx.x;
    if (e < N_EDGES) atomicAdd(&g_deg[g_col32[e]], 1);
}

__global__ void k_dinv() {
    int v = blockIdx.x * blockDim.x + threadIdx.x;
    if (v < N_NODES) g_dinv[v] = rsqrtf((float)g_deg[v]);
}

// exclusive scan of (deg-1) -> g_off.  3-phase: block-local, block sums, add.
__global__ void k_scan1() {
    __shared__ int s[1024];
    int tid = threadIdx.x;
    int v = blockIdx.x * 1024 + tid;
    int c = (v < N_NODES) ? (g_deg[v] - 1) : 0;
    s[tid] = c;
    __syncthreads();
    #pragma unroll
    for (int o = 1; o < 1024; o <<= 1) {
        int t = (tid >= o) ? s[tid - o] : 0;
        __syncthreads();
        if (tid >= o) s[tid] += t;
        __syncthreads();
    }
    if (v < N_NODES) g_off[v + 1] = s[tid];   // inclusive within block, shifted by 1
    if (tid == 1023) g_bsum[blockIdx.x] = s[1023];
}

__global__ void k_scan2(int nblk) {           // tiny serial scan of block sums
    if (threadIdx.x == 0 && blockIdx.x == 0) {
        int acc = 0;
        for (int b = 0; b < nblk; b++) { int t = g_bsum[b]; g_bsum[b] = acc; acc += t; }
    }
}

__global__ void k_scan3() {
    int tid = threadIdx.x;
    int v = blockIdx.x * 1024 + tid;
    if (v < N_NODES) g_off[v + 1] += g_bsum[blockIdx.x];
    if (v == 0) g_off[0] = 0;
}

__global__ void k_scatter() {
    int e = blockIdx.x * blockDim.x + threadIdx.x;
    if (e < N_EDGES) {
        int c = g_col32[e];
        int p = g_off[c] + atomicAdd(&g_cur[c], 1);
        g_csr[p] = g_row32[e];
    }
}

// ---------------- aggregation: out[v] = dinv[v]*(sum_{u->v} dinv[u]*X[u] + dinv[v]*X[v]) (+bias)
// warp handles (node, 32-feature chunk); neighbor index loads are warp-uniform.
template<int F, bool BIAS>
__global__ void k_agg(const float* __restrict__ X, float* __restrict__ OUT,
                      const float* __restrict__ bias) {
    constexpr int CH = (F + 31) / 32;
    int gw = (blockIdx.x * blockDim.x + threadIdx.x) >> 5;
    int lane = threadIdx.x & 31;
    int node = gw / CH;
    if (node >= N_NODES) return;
    int f = (gw % CH) * 32 + lane;
    bool act = f < F;
    int fb = act ? f : 0;                       // inactive lanes read col 0 (discarded)
    float dv = g_dinv[node];
    float acc = dv * X[(size_t)node * F + fb];  // self-loop term
    int beg = g_off[node], end = g_off[node + 1];
    int j = beg;
    for (; j + 4 <= end; j += 4) {              // 4-way MLP on the gather
        int u0 = g_csr[j], u1 = g_csr[j + 1], u2 = g_csr[j + 2], u3 = g_csr[j + 3];
        float d0 = g_dinv[u0], d1 = g_dinv[u1], d2 = g_dinv[u2], d3 = g_dinv[u3];
        float x0 = X[(size_t)u0 * F + fb];
        float x1 = X[(size_t)u1 * F + fb];
        float x2 = X[(size_t)u2 * F + fb];
        float x3 = X[(size_t)u3 * F + fb];
        acc += d0 * x0; acc += d1 * x1; acc += d2 * x2; acc += d3 * x3;
    }
    for (; j < end; j++) {
        int u = g_csr[j];
        acc += g_dinv[u] * X[(size_t)u * F + fb];
    }
    float r = dv * acc;
    if (BIAS) r += bias[fb];
    if (act) OUT[(size_t)node * F + f] = r;
}

// ---------------- tiled fp32 GEMM:  C[M,N] = A[M,K] @ B[K,N] (+bias)(+relu) ----
// BM=128 BN=64 BK=16, 256 threads, 8x4 microtile per thread.
template<bool RELU, bool BIAS>
__global__ void __launch_bounds__(256)
k_gemm(const float* __restrict__ A, const float* __restrict__ B,
       const float* __restrict__ bias, float* __restrict__ C,
       int M, int N, int K) {
    const int BM = 128, BN = 64, BK = 16;
    __shared__ float As[BK][BM + 4];
    __shared__ float Bs[BK][BN];
    int tid = threadIdx.x;
    int tx = tid & 15;          // 16 col-threads
    int ty = tid >> 4;          // 16 row-threads
    int m0 = blockIdx.y * BM, n0 = blockIdx.x * BN;

    float acc[8][4];
    #pragma unroll
    for (int i = 0; i < 8; i++)
        #pragma unroll
        for (int j = 0; j < 4; j++) acc[i][j] = 0.f;

    for (int k0 = 0; k0 < K; k0 += BK) {
        #pragma unroll
        for (int i = 0; i < 8; i++) {           // A: 2048 elems, transposed store
            int idx = i * 256 + tid;
            int ar = idx / BK, ac = idx % BK;
            int m = m0 + ar, k = k0 + ac;
            As[ac][ar] = (m < M && k < K) ? A[(size_t)m * K + k] : 0.f;
        }
        #pragma unroll
        for (int i = 0; i < 4; i++) {           // B: 1024 elems
            int idx = i * 256 + tid;
            int br = idx / BN, bc = idx % BN;
            int k = k0 + br, n = n0 + bc;
            Bs[br][bc] = (k < K && n < N) ? B[(size_t)k * N + n] : 0.f;
        }
        __syncthreads();
        #pragma unroll
        for (int kk = 0; kk < BK; kk++) {
            float a[8], b[4];
            #pragma unroll
            for (int i = 0; i < 8; i++) a[i] = As[kk][ty * 8 + i];
            #pragma unroll
            for (int j = 0; j < 4; j++) b[j] = Bs[kk][tx * 4 + j];
            #pragma unroll
            for (int i = 0; i < 8; i++)
                #pragma unroll
                for (int j = 0; j < 4; j++)
                    acc[i][j] += a[i] * b[j];
        }
        __syncthreads();
    }

    #pragma unroll
    for (int i = 0; i < 8; i++) {
        int m = m0 + ty * 8 + i;
        if (m >= M) continue;
        #pragma unroll
        for (int j = 0; j < 4; j++) {
            int n = n0 + tx * 4 + j;
            if (n < N) {
                float r = acc[i][j];
                if (BIAS) r += bias[n];
                if (RELU) r = fmaxf(r, 0.f);
                C[(size_t)m * N + n] = r;
            }
        }
    }
}

// ---------------- launch ----------------------------------------------------

static inline void* sym(const void* s) {
    void* p = nullptr;
    cudaGetSymbolAddress(&p, s);
    return p;
}

extern "C" void kernel_launch(void* const* d_in, const int* in_sizes, int n_in,
                              void* d_out, int out_size) {
    const float* x   = (const float*)d_in[0];
    const void*  ei  = d_in[1];
    const float* W1  = (const float*)d_in[2];
    const float* b1  = (const float*)d_in[3];
    const float* W2  = (const float*)d_in[4];
    const float* b2  = (const float*)d_in[5];
    const float* W3  = (const float*)d_in[6];
    const float* b3  = (const float*)d_in[7];
    float*       out = (float*)d_out;

    float* agg1 = (float*)sym(g_agg1);
    float* h1   = (float*)sym(g_h1);
    float* agg2 = (float*)sym(g_agg2);
    float* t3   = (float*)sym(g_t3);

    const int NB_N = (N_NODES + 255) / 256;
    const int NB_E = (N_EDGES + 255) / 256;
    const int NBLK = (N_NODES + 1023) / 1024;   // 98

    // edge dtype probe + canonicalization (rebuilds state every replay)
    k_zero_flag<<<1, 32>>>();
    k_detect   <<<16, 256>>>((const long long*)ei);
    k_convert  <<<NB_E, 256>>>(ei);

    // graph preprocessing
    k_init   <<<NB_N, 256>>>();
    k_count  <<<NB_E, 256>>>();
    k_dinv   <<<NB_N, 256>>>();
    k_scan1  <<<NBLK, 1024>>>();
    k_scan2  <<<1, 32>>>(NBLK);
    k_scan3  <<<NBLK, 1024>>>();
    k_scatter<<<NB_E, 256>>>();

    // Layer 1: aggregate x (F=50) then GEMM 50->256 (+b1, relu)
    {
        long long warps = (long long)N_NODES * ((IN_F + 31) / 32);
        int blocks = (int)((warps * 32 + 255) / 256);
        k_agg<IN_F, false><<<blocks, 256>>>(x, agg1, nullptr);
    }
    {
        dim3 grid((HID + 63) / 64, (N_NODES + 127) / 128);
        k_gemm<true, true><<<grid, 256>>>(agg1, W1, b1, h1, N_NODES, HID, IN_F);
    }

    // Layer 2: aggregate h1 (F=256) then GEMM 256->256 (+b2, relu) -> reuse h1
    {
        long long warps = (long long)N_NODES * (HID / 32);
        int blocks = (int)((warps * 32 + 255) / 256);
        k_agg<HID, false><<<blocks, 256>>>(h1, agg2, nullptr);
    }
    {
        dim3 grid((HID + 63) / 64, (N_NODES + 127) / 128);
        k_gemm<true, true><<<grid, 256>>>(agg2, W2, b2, h1, N_NODES, HID, HID);
    }

    // Layer 3: GEMM 256->121 (no bias/relu) then aggregate (F=121, +b3) -> out
    {
        dim3 grid((OUT_F + 63) / 64, (N_NODES + 127) / 128);
        k_gemm<false, false><<<grid, 256>>>(h1, W3, nullptr, t3, N_NODES, OUT_F, HID);
    }
    {
        long long warps = (long long)N_NODES * ((OUT_F + 31) / 32);
        int blocks = (int)((warps * 32 + 255) / 256);
        k_agg<OUT_F, true><<<blocks, 256>>>(t3, out, b3);
    }
}

// round 4
// speedup vs baseline: 1.4113x; 1.4113x over previous
#include <cuda_runtime.h>
#include <cuda_bf16.h>
#include <stdint.h>

#define N_NODES 100000
#define N_EDGES 1600000
#define IN_F 50
#define HID 256
#define OUT_F 121
#define M_TILES ((N_NODES + 127) / 128)   // 782

// ===================== scratch (static __device__) ==========================
__device__ int   g_flag;
__device__ int   g_row32[N_EDGES];
__device__ int   g_col32[N_EDGES];
__device__ int   g_deg[N_NODES];
__device__ float g_dinv[N_NODES];
__device__ int   g_off[N_NODES + 1];
__device__ int   g_cur[N_NODES];
__device__ int   g_csr[N_EDGES];
__device__ int   g_bsum[128];

__device__ __nv_bfloat16 g_B1h[256 * 64],  g_B1l[256 * 64];    // W1^T padded K->64
__device__ __nv_bfloat16 g_B2h[256 * 256], g_B2l[256 * 256];   // W2^T
__device__ __nv_bfloat16 g_B3h[128 * 256], g_B3l[128 * 256];   // W3^T padded N->128

__device__ __nv_bfloat16 g_A1h[(size_t)N_NODES * 64],  g_A1l[(size_t)N_NODES * 64];
__device__ __nv_bfloat16 g_A2h[(size_t)N_NODES * 256], g_A2l[(size_t)N_NODES * 256];
__device__ __nv_bfloat16 g_A3h[(size_t)N_NODES * 256], g_A3l[(size_t)N_NODES * 256];
__device__ float g_h1[(size_t)N_NODES * 256];
__device__ float g_t3[(size_t)N_NODES * 128];

// ===================== small PTX helpers (baseline features only) ===========
__device__ __forceinline__ uint32_t smem_u32(const void* p) {
    uint32_t a;
    asm("{ .reg .u64 t; cvta.to.shared.u64 t, %1; cvt.u32.u64 %0, t; }" : "=r"(a) : "l"(p));
    return a;
}

#define CP_ASYNC16(dst_u32, src_ptr) \
    asm volatile("cp.async.cg.shared.global [%0], [%1], 16;" :: "r"(dst_u32), "l"(src_ptr))
#define CP_COMMIT() asm volatile("cp.async.commit_group;" ::: "memory")
#define CP_WAIT0()  asm volatile("cp.async.wait_group 0;" ::: "memory")

__device__ __forceinline__ void mma16816(float* d, const uint32_t* a, const uint32_t* b) {
    asm volatile(
        "mma.sync.aligned.m16n8k16.row.col.f32.bf16.bf16.f32 "
        "{%0,%1,%2,%3}, {%4,%5,%6,%7}, {%8,%9}, {%0,%1,%2,%3};"
        : "+f"(d[0]), "+f"(d[1]), "+f"(d[2]), "+f"(d[3])
        : "r"(a[0]), "r"(a[1]), "r"(a[2]), "r"(a[3]), "r"(b[0]), "r"(b[1]));
}

// ===================== edge dtype probe + canonicalize ======================
__global__ void k_zero_flag() { if (threadIdx.x == 0 && blockIdx.x == 0) g_flag = 0; }

__global__ void k_detect(const long long* __restrict__ ei64) {
    int e = blockIdx.x * blockDim.x + threadIdx.x;
    if (e < 4096) {
        long long v = ei64[e];
        if (v < 0 || v >= N_NODES) atomicOr(&g_flag, 1);
    }
}

__global__ void k_convert(const void* __restrict__ ei) {
    int e = blockIdx.x * blockDim.x + threadIdx.x;
    if (e >= N_EDGES) return;
    if (g_flag) {
        const int* p = (const int*)ei;
        g_row32[e] = p[e];
        g_col32[e] = p[N_EDGES + e];
    } else {
        const long long* p = (const long long*)ei;
        g_row32[e] = (int)p[e];
        g_col32[e] = (int)p[N_EDGES + e];
    }
}

// ===================== graph preprocessing ==================================
__global__ void k_init() {
    int v = blockIdx.x * blockDim.x + threadIdx.x;
    if (v < N_NODES) { g_deg[v] = 1; g_cur[v] = 0; }
}

__global__ void k_count() {
    int e = blockIdx.x * blockDim.x + threadIdx.x;
    if (e < N_EDGES) atomicAdd(&g_deg[g_col32[e]], 1);
}

__global__ void k_dinv() {
    int v = blockIdx.x * blockDim.x + threadIdx.x;
    if (v < N_NODES) g_dinv[v] = rsqrtf((float)g_deg[v]);
}

__global__ void k_scan1() {
    __shared__ int s[1024];
    int tid = threadIdx.x;
    int v = blockIdx.x * 1024 + tid;
    int c = (v < N_NODES) ? (g_deg[v] - 1) : 0;
    s[tid] = c;
    __syncthreads();
    #pragma unroll
    for (int o = 1; o < 1024; o <<= 1) {
        int t = (tid >= o) ? s[tid - o] : 0;
        __syncthreads();
        if (tid >= o) s[tid] += t;
        __syncthreads();
    }
    if (v < N_NODES) g_off[v + 1] = s[tid];
    if (tid == 1023) g_bsum[blockIdx.x] = s[1023];
}

__global__ void k_scan2(int nblk) {
    if (threadIdx.x == 0 && blockIdx.x == 0) {
        int acc = 0;
        for (int b = 0; b < nblk; b++) { int t = g_bsum[b]; g_bsum[b] = acc; acc += t; }
    }
}

__global__ void k_scan3() {
    int tid = threadIdx.x;
    int v = blockIdx.x * 1024 + tid;
    if (v < N_NODES) g_off[v + 1] += g_bsum[blockIdx.x];
    if (v == 0) g_off[0] = 0;
}

__global__ void k_scatter() {
    int e = blockIdx.x * blockDim.x + threadIdx.x;
    if (e < N_EDGES) {
        int c = g_col32[e];
        int p = g_off[c] + atomicAdd(&g_cur[c], 1);
        g_csr[p] = g_row32[e];
    }
}

// ===================== weight prep: transpose + bf16 split ==================
__global__ void k_prepw(const float* __restrict__ W, __nv_bfloat16* __restrict__ Bh,
                        __nv_bfloat16* __restrict__ Bl, int K, int Nw, int KP, int NP) {
    int i = blockIdx.x * 256 + threadIdx.x;
    if (i >= NP * KP) return;
    int n = i / KP, k = i % KP;
    float v = (k < K && n < Nw) ? W[(size_t)k * Nw + n] : 0.f;
    __nv_bfloat16 h = __float2bfloat16(v);
    Bh[i] = h;
    Bl[i] = __float2bfloat16(v - __bfloat162float(h));
}

// ===================== aggregation ==========================================
template<int FIN, int FPAD>
__global__ void k_agg_pair(const float* __restrict__ X,
                           __nv_bfloat16* __restrict__ Oh,
                           __nv_bfloat16* __restrict__ Ol) {
    constexpr int CH = FPAD / 32;
    int gw = (blockIdx.x * blockDim.x + threadIdx.x) >> 5;
    int lane = threadIdx.x & 31;
    int node = gw / CH;
    if (node >= N_NODES) return;
    int f = (gw % CH) * 32 + lane;
    if (f >= FIN) {
        Oh[(size_t)node * FPAD + f] = __float2bfloat16(0.f);
        Ol[(size_t)node * FPAD + f] = __float2bfloat16(0.f);
        return;
    }
    float dv = g_dinv[node];
    float acc = dv * X[(size_t)node * FIN + f];
    int beg = g_off[node], end = g_off[node + 1];
    int j = beg;
    for (; j + 4 <= end; j += 4) {
        int u0 = g_csr[j], u1 = g_csr[j + 1], u2 = g_csr[j + 2], u3 = g_csr[j + 3];
        float d0 = g_dinv[u0], d1 = g_dinv[u1], d2 = g_dinv[u2], d3 = g_dinv[u3];
        float x0 = X[(size_t)u0 * FIN + f];
        float x1 = X[(size_t)u1 * FIN + f];
        float x2 = X[(size_t)u2 * FIN + f];
        float x3 = X[(size_t)u3 * FIN + f];
        acc += d0 * x0; acc += d1 * x1; acc += d2 * x2; acc += d3 * x3;
    }
    for (; j < end; j++) {
        int u = g_csr[j];
        acc += g_dinv[u] * X[(size_t)u * FIN + f];
    }
    float r = dv * acc;
    __nv_bfloat16 h = __float2bfloat16(r);
    Oh[(size_t)node * FPAD + f] = h;
    Ol[(size_t)node * FPAD + f] = __float2bfloat16(r - __bfloat162float(h));
}

__global__ void k_agg_out(const float* __restrict__ X, float* __restrict__ OUT,
                          const float* __restrict__ bias) {
    constexpr int CH = 4;
    int gw = (blockIdx.x * blockDim.x + threadIdx.x) >> 5;
    int lane = threadIdx.x & 31;
    int node = gw / CH;
    if (node >= N_NODES) return;
    int f = (gw % CH) * 32 + lane;
    bool act = f < OUT_F;
    int fb = act ? f : 0;
    float dv = g_dinv[node];
    float acc = dv * X[(size_t)node * 128 + fb];
    int beg = g_off[node], end = g_off[node + 1];
    int j = beg;
    for (; j + 4 <= end; j += 4) {
        int u0 = g_csr[j], u1 = g_csr[j + 1], u2 = g_csr[j + 2], u3 = g_csr[j + 3];
        float d0 = g_dinv[u0], d1 = g_dinv[u1], d2 = g_dinv[u2], d3 = g_dinv[u3];
        float x0 = X[(size_t)u0 * 128 + fb];
        float x1 = X[(size_t)u1 * 128 + fb];
        float x2 = X[(size_t)u2 * 128 + fb];
        float x3 = X[(size_t)u3 * 128 + fb];
        acc += d0 * x0; acc += d1 * x1; acc += d2 * x2; acc += d3 * x3;
    }
    for (; j < end; j++) {
        int u = g_csr[j];
        acc += g_dinv[u] * X[(size_t)u * 128 + fb];
    }
    float r = dv * acc + bias[fb];
    if (act) OUT[(size_t)node * OUT_F + f] = r;
}

// ===================== warp-MMA GEMM (baseline mma.sync, bf16 split) ========
// C[M, NNTOT] (+bias,relu) = A[M, KT*32] @ B[NNTOT, KT*32]^T,  hh + hl + lh.
// Block: 128(M) x 128(N) x BK=32. 8 warps = 4(M) x 2(N); warp tile 32x64.
// OMODE 0: fp32 C.  OMODE 1: bf16 hi/lo pair C.
template<int KT, int NNTOT, bool BIAS, bool RELU, int OMODE>
__global__ void __launch_bounds__(256)
k_mma(const __nv_bfloat16* __restrict__ Ah, const __nv_bfloat16* __restrict__ Al,
      const __nv_bfloat16* __restrict__ Bh, const __nv_bfloat16* __restrict__ Bl,
      const float* __restrict__ bias,
      float* __restrict__ Cf, __nv_bfloat16* __restrict__ Ch, __nv_bfloat16* __restrict__ Cl) {
    constexpr int ASTR = KT * 32;           // element stride of A and B rows
    constexpr int PAD = 40;                 // row stride in smem (conflict-free)
    __shared__ __align__(16) __nv_bfloat16 sAh[128][PAD];
    __shared__ __align__(16) __nv_bfloat16 sAl[128][PAD];
    __shared__ __align__(16) __nv_bfloat16 sBh[128][PAD];
    __shared__ __align__(16) __nv_bfloat16 sBl[128][PAD];

    const int tid = threadIdx.x;
    const int wid = tid >> 5, lane = tid & 31;
    const int wm = wid & 3, wn = wid >> 2;          // warp -> (M quad, N half)
    const int m0 = blockIdx.x * 128;
    const int n0 = blockIdx.y * 128;

    float acc[2][8][4];
    #pragma unroll
    for (int mt = 0; mt < 2; mt++)
        #pragma unroll
        for (int nt = 0; nt < 8; nt++)
            #pragma unroll
            for (int q = 0; q < 4; q++) acc[mt][nt][q] = 0.f;

    for (int c = 0; c < KT; c++) {
        // ---- stage: 4 arrays x 128 rows x 2 chunks(16B) via cp.async ----
        #pragma unroll
        for (int it = 0; it < 2; it++) {
            int idx = it * 256 + tid;               // 0..511: row=idx>>2 ch=idx&3
            int row = idx >> 2, chk = idx & 3;
            int m = m0 + row; if (m >= N_NODES) m = N_NODES - 1;
            size_t goA = (size_t)m * ASTR + c * 32 + chk * 8;
            size_t goB = (size_t)(n0 + row) * ASTR + c * 32 + chk * 8;
            CP_ASYNC16(smem_u32(&sAh[row][chk * 8]), Ah + goA);
            CP_ASYNC16(smem_u32(&sAl[row][chk * 8]), Al + goA);
            CP_ASYNC16(smem_u32(&sBh[row][chk * 8]), Bh + goB);
            CP_ASYNC16(smem_u32(&sBl[row][chk * 8]), Bl + goB);
        }
        CP_COMMIT();
        CP_WAIT0();
        __syncthreads();

        #pragma unroll
        for (int ks = 0; ks < 2; ks++) {            // two k16 steps
            const int kc = ks * 16 + (lane & 3) * 2;
            uint32_t ah[2][4], al[2][4];
            #pragma unroll
            for (int mt = 0; mt < 2; mt++) {
                int r = wm * 32 + mt * 16 + (lane >> 2);
                ah[mt][0] = *(const uint32_t*)&sAh[r][kc];
                ah[mt][1] = *(const uint32_t*)&sAh[r + 8][kc];
                ah[mt][2] = *(const uint32_t*)&sAh[r][kc + 8];
                ah[mt][3] = *(const uint32_t*)&sAh[r + 8][kc + 8];
                al[mt][0] = *(const uint32_t*)&sAl[r][kc];
                al[mt][1] = *(const uint32_t*)&sAl[r + 8][kc];
                al[mt][2] = *(const uint32_t*)&sAl[r][kc + 8];
                al[mt][3] = *(const uint32_t*)&sAl[r + 8][kc + 8];
            }
            #pragma unroll
            for (int nt = 0; nt < 8; nt++) {
                int br = wn * 64 + nt * 8 + (lane >> 2);
                uint32_t bh[2], bl[2];
                bh[0] = *(const uint32_t*)&sBh[br][kc];
                bh[1] = *(const uint32_t*)&sBh[br][kc + 8];
                bl[0] = *(const uint32_t*)&sBl[br][kc];
                bl[1] = *(const uint32_t*)&sBl[br][kc + 8];
                #pragma unroll
                for (int mt = 0; mt < 2; mt++) {
                    mma16816(acc[mt][nt], ah[mt], bh);   // hi*hi
                    mma16816(acc[mt][nt], ah[mt], bl);   // hi*lo
                    mma16816(acc[mt][nt], al[mt], bh);   // lo*hi
                }
            }
        }
        __syncthreads();
    }

    // ---- epilogue ----
    #pragma unroll
    for (int mt = 0; mt < 2; mt++) {
        int mrow = m0 + wm * 32 + mt * 16 + (lane >> 2);
        #pragma unroll
        for (int nt = 0; nt < 8; nt++) {
            int n = n0 + wn * 64 + nt * 8 + (lane & 3) * 2;
            float v0 = acc[mt][nt][0], v1 = acc[mt][nt][1];
            float v2 = acc[mt][nt][2], v3 = acc[mt][nt][3];
            if (BIAS) {
                float bb0 = bias[n], bb1 = bias[n + 1];
                v0 += bb0; v1 += bb1; v2 += bb0; v3 += bb1;
            }
            if (RELU) {
                v0 = fmaxf(v0, 0.f); v1 = fmaxf(v1, 0.f);
                v2 = fmaxf(v2, 0.f); v3 = fmaxf(v3, 0.f);
            }
            if (OMODE == 0) {
                if (mrow < N_NODES)
                    *(float2*)(Cf + (size_t)mrow * NNTOT + n) = make_float2(v0, v1);
                if (mrow + 8 < N_NODES)
                    *(float2*)(Cf + (size_t)(mrow + 8) * NNTOT + n) = make_float2(v2, v3);
            } else {
                if (mrow < N_NODES) {
                    __nv_bfloat16 h0 = __float2bfloat16(v0), h1 = __float2bfloat16(v1);
                    *(__nv_bfloat162*)(Ch + (size_t)mrow * NNTOT + n) = __halves2bfloat162(h0, h1);
                    *(__nv_bfloat162*)(Cl + (size_t)mrow * NNTOT + n) = __halves2bfloat162(
                        __float2bfloat16(v0 - __bfloat162float(h0)),
                        __float2bfloat16(v1 - __bfloat162float(h1)));
                }
                if (mrow + 8 < N_NODES) {
                    __nv_bfloat16 h2 = __float2bfloat16(v2), h3 = __float2bfloat16(v3);
                    *(__nv_bfloat162*)(Ch + (size_t)(mrow + 8) * NNTOT + n) = __halves2bfloat162(h2, h3);
                    *(__nv_bfloat162*)(Cl + (size_t)(mrow + 8) * NNTOT + n) = __halves2bfloat162(
                        __float2bfloat16(v2 - __bfloat162float(h2)),
                        __float2bfloat16(v3 - __bfloat162float(h3)));
                }
            }
        }
    }
}

// ===================== launch ===============================================
static inline void* sym(const void* s) {
    void* p = nullptr;
    cudaGetSymbolAddress(&p, s);
    return p;
}

extern "C" void kernel_launch(void* const* d_in, const int* in_sizes, int n_in,
                              void* d_out, int out_size) {
    const float* x   = (const float*)d_in[0];
    const void*  ei  = d_in[1];
    const float* W1  = (const float*)d_in[2];
    const float* b1  = (const float*)d_in[3];
    const float* W2  = (const float*)d_in[4];
    const float* b2  = (const float*)d_in[5];
    const float* W3  = (const float*)d_in[6];
    const float* b3  = (const float*)d_in[7];
    float*       out = (float*)d_out;

    __nv_bfloat16* B1h = (__nv_bfloat16*)sym(g_B1h); __nv_bfloat16* B1l = (__nv_bfloat16*)sym(g_B1l);
    __nv_bfloat16* B2h = (__nv_bfloat16*)sym(g_B2h); __nv_bfloat16* B2l = (__nv_bfloat16*)sym(g_B2l);
    __nv_bfloat16* B3h = (__nv_bfloat16*)sym(g_B3h); __nv_bfloat16* B3l = (__nv_bfloat16*)sym(g_B3l);
    __nv_bfloat16* A1h = (__nv_bfloat16*)sym(g_A1h); __nv_bfloat16* A1l = (__nv_bfloat16*)sym(g_A1l);
    __nv_bfloat16* A2h = (__nv_bfloat16*)sym(g_A2h); __nv_bfloat16* A2l = (__nv_bfloat16*)sym(g_A2l);
    __nv_bfloat16* A3h = (__nv_bfloat16*)sym(g_A3h); __nv_bfloat16* A3l = (__nv_bfloat16*)sym(g_A3l);
    float* h1 = (float*)sym(g_h1);
    float* t3 = (float*)sym(g_t3);

    const int NB_N = (N_NODES + 255) / 256;
    const int NB_E = (N_EDGES + 255) / 256;
    const int NBLK = (N_NODES + 1023) / 1024;

    // edge canonicalization + graph preprocessing
    k_zero_flag<<<1, 32>>>();
    k_detect   <<<16, 256>>>((const long long*)ei);
    k_convert  <<<NB_E, 256>>>(ei);
    k_init     <<<NB_N, 256>>>();
    k_count    <<<NB_E, 256>>>();
    k_dinv     <<<NB_N, 256>>>();
    k_scan1    <<<NBLK, 1024>>>();
    k_scan2    <<<1, 32>>>(NBLK);
    k_scan3    <<<NBLK, 1024>>>();
    k_scatter  <<<NB_E, 256>>>();

    // weight prep (transpose + split + pad)
    k_prepw<<<(256 * 64  + 255) / 256, 256>>>(W1, B1h, B1l, IN_F, 256, 64,  256);
    k_prepw<<<(256 * 256 + 255) / 256, 256>>>(W2, B2h, B2l, 256,  256, 256, 256);
    k_prepw<<<(128 * 256 + 255) / 256, 256>>>(W3, B3h, B3l, 256,  OUT_F, 256, 128);

    // Layer 1: agg(x) -> A1 pair; GEMM K=64 N=256 (+b1, relu) -> h1 fp32
    {
        long long warps = (long long)N_NODES * 2;
        k_agg_pair<IN_F, 64><<<(int)((warps * 32 + 255) / 256), 256>>>(x, A1h, A1l);
    }
    {
        dim3 grid(M_TILES, 2);
        k_mma<2, 256, true, true, 0><<<grid, 256>>>(A1h, A1l, B1h, B1l, b1, h1, nullptr, nullptr);
    }

    // Layer 2: agg(h1) -> A2 pair; GEMM K=256 N=256 (+b2, relu) -> A3 pair
    {
        long long warps = (long long)N_NODES * 8;
        k_agg_pair<256, 256><<<(int)((warps * 32 + 255) / 256), 256>>>(h1, A2h, A2l);
    }
    {
        dim3 grid(M_TILES, 2);
        k_mma<8, 256, true, true, 1><<<grid, 256>>>(A2h, A2l, B2h, B2l, b2, nullptr, A3h, A3l);
    }

    // Layer 3: GEMM K=256 N=128(pad of 121) -> t3 fp32; agg(t3)+b3 -> out
    {
        dim3 grid(M_TILES, 1);
        k_mma<8, 128, false, false, 0><<<grid, 256>>>(A3h, A3l, B3h, B3l, nullptr, t3, nullptr, nullptr);
    }
    {
        long long warps = (long long)N_NODES * 4;
        k_agg_out<<<(int)((warps * 32 + 255) / 256), 256>>>(t3, out, b3);
    }
}

// round 5
// speedup vs baseline: 1.6569x; 1.1741x over previous
#include <cuda_runtime.h>
#include <cuda_bf16.h>
#include <stdint.h>

#define N_NODES 100000
#define N_EDGES 1600000
#define IN_F 50
#define HID 256
#define OUT_F 121
#define M_TILES ((N_NODES + 127) / 128)   // 782

// ===================== scratch (static __device__) ==========================
__device__ int   g_flag;
__device__ int   g_row32[N_EDGES];
__device__ int   g_col32[N_EDGES];
__device__ int   g_deg[N_NODES];
__device__ float g_dinv[N_NODES];
__device__ int   g_off[N_NODES + 1];
__device__ int   g_cur[N_NODES];
__device__ int   g_csr[N_EDGES];
__device__ int   g_bsum[128];

__device__ __nv_bfloat16 g_B1h[256 * 64],  g_B1l[256 * 64];    // W1^T padded K->64
__device__ __nv_bfloat16 g_B2h[256 * 256], g_B2l[256 * 256];   // W2^T
__device__ __nv_bfloat16 g_B3h[128 * 256], g_B3l[128 * 256];   // W3^T padded N->128

__device__ __nv_bfloat16 g_A1h[(size_t)N_NODES * 64],  g_A1l[(size_t)N_NODES * 64];
__device__ __nv_bfloat16 g_A2h[(size_t)N_NODES * 256], g_A2l[(size_t)N_NODES * 256];
__device__ __nv_bfloat16 g_A3h[(size_t)N_NODES * 256], g_A3l[(size_t)N_NODES * 256];
__device__ float g_h1[(size_t)N_NODES * 256];
__device__ float g_t3[(size_t)N_NODES * 128];

// ===================== small PTX helpers (baseline features only) ===========
__device__ __forceinline__ uint32_t smem_u32(const void* p) {
    uint32_t a;
    asm("{ .reg .u64 t; cvta.to.shared.u64 t, %1; cvt.u32.u64 %0, t; }" : "=r"(a) : "l"(p));
    return a;
}

#define CP_ASYNC16(dst_u32, src_ptr) \
    asm volatile("cp.async.cg.shared.global [%0], [%1], 16;" :: "r"(dst_u32), "l"(src_ptr))
#define CP_COMMIT() asm volatile("cp.async.commit_group;" ::: "memory")

#define LDM_X4(R, ADDR) \
    asm volatile("ldmatrix.sync.aligned.m8n8.x4.shared.b16 {%0,%1,%2,%3}, [%4];" \
        : "=r"((R)[0]), "=r"((R)[1]), "=r"((R)[2]), "=r"((R)[3]) : "r"(ADDR))

__device__ __forceinline__ void mma16816(float* d, const uint32_t* a, const uint32_t* b) {
    asm volatile(
        "mma.sync.aligned.m16n8k16.row.col.f32.bf16.bf16.f32 "
        "{%0,%1,%2,%3}, {%4,%5,%6,%7}, {%8,%9}, {%0,%1,%2,%3};"
        : "+f"(d[0]), "+f"(d[1]), "+f"(d[2]), "+f"(d[3])
        : "r"(a[0]), "r"(a[1]), "r"(a[2]), "r"(a[3]), "r"(b[0]), "r"(b[1]));
}

// ===================== edge dtype probe + canonicalize ======================
__global__ void k_zero_flag() { if (threadIdx.x == 0 && blockIdx.x == 0) g_flag = 0; }

__global__ void k_detect(const long long* __restrict__ ei64) {
    int e = blockIdx.x * blockDim.x + threadIdx.x;
    if (e < 4096) {
        long long v = ei64[e];
        if (v < 0 || v >= N_NODES) atomicOr(&g_flag, 1);
    }
}

__global__ void k_init() {
    int v = blockIdx.x * blockDim.x + threadIdx.x;
    if (v < N_NODES) { g_deg[v] = 1; g_cur[v] = 0; }
}

// convert + degree-count fused (k_init must run first)
__global__ void k_convert(const void* __restrict__ ei) {
    int e = blockIdx.x * blockDim.x + threadIdx.x;
    if (e >= N_EDGES) return;
    int r, c;
    if (g_flag) {
        const int* p = (const int*)ei;
        r = p[e]; c = p[N_EDGES + e];
    } else {
        const long long* p = (const long long*)ei;
        r = (int)p[e]; c = (int)p[N_EDGES + e];
    }
    g_row32[e] = r;
    g_col32[e] = c;
    atomicAdd(&g_deg[c], 1);
}

// ===================== graph preprocessing ==================================
__global__ void k_dinv() {
    int v = blockIdx.x * blockDim.x + threadIdx.x;
    if (v < N_NODES) g_dinv[v] = rsqrtf((float)g_deg[v]);
}

__global__ void k_scan1() {
    __shared__ int s[1024];
    int tid = threadIdx.x;
    int v = blockIdx.x * 1024 + tid;
    int c = (v < N_NODES) ? (g_deg[v] - 1) : 0;
    s[tid] = c;
    __syncthreads();
    #pragma unroll
    for (int o = 1; o < 1024; o <<= 1) {
        int t = (tid >= o) ? s[tid - o] : 0;
        __syncthreads();
        if (tid >= o) s[tid] += t;
        __syncthreads();
    }
    if (v < N_NODES) g_off[v + 1] = s[tid];
    if (tid == 1023) g_bsum[blockIdx.x] = s[1023];
}

__global__ void k_scan2(int nblk) {
    if (threadIdx.x == 0 && blockIdx.x == 0) {
        int acc = 0;
        for (int b = 0; b < nblk; b++) { int t = g_bsum[b]; g_bsum[b] = acc; acc += t; }
    }
}

__global__ void k_scan3() {
    int tid = threadIdx.x;
    int v = blockIdx.x * 1024 + tid;
    if (v < N_NODES) g_off[v + 1] += g_bsum[blockIdx.x];
    if (v == 0) g_off[0] = 0;
}

__global__ void k_scatter() {
    int e = blockIdx.x * blockDim.x + threadIdx.x;
    if (e < N_EDGES) {
        int c = g_col32[e];
        int p = g_off[c] + atomicAdd(&g_cur[c], 1);
        g_csr[p] = g_row32[e];
    }
}

// ===================== weight prep: transpose + bf16 split ==================
__global__ void k_prepw(const float* __restrict__ W, __nv_bfloat16* __restrict__ Bh,
                        __nv_bfloat16* __restrict__ Bl, int K, int Nw, int KP, int NP) {
    int i = blockIdx.x * 256 + threadIdx.x;
    if (i >= NP * KP) return;
    int n = i / KP, k = i % KP;
    float v = (k < K && n < Nw) ? W[(size_t)k * Nw + n] : 0.f;
    __nv_bfloat16 h = __float2bfloat16(v);
    Bh[i] = h;
    Bl[i] = __float2bfloat16(v - __bfloat162float(h));
}

// ===================== aggregation (CHUNK-MAJOR for L2 slice residency) =====
template<int FIN, int FPAD>
__global__ void k_agg_pair(const float* __restrict__ X,
                           __nv_bfloat16* __restrict__ Oh,
                           __nv_bfloat16* __restrict__ Ol) {
    constexpr int CH = FPAD / 32;
    int gw = (blockIdx.x * blockDim.x + threadIdx.x) >> 5;
    int lane = threadIdx.x & 31;
    if (gw >= CH * N_NODES) return;
    int chunk = gw / N_NODES;            // slow index: all concurrent warps share a slice
    int node = gw - chunk * N_NODES;
    int f = chunk * 32 + lane;
    if (f >= FIN) {
        Oh[(size_t)node * FPAD + f] = __float2bfloat16(0.f);
        Ol[(size_t)node * FPAD + f] = __float2bfloat16(0.f);
        return;
    }
    float dv = g_dinv[node];
    float acc = dv * X[(size_t)node * FIN + f];
    int beg = g_off[node], end = g_off[node + 1];
    int j = beg;
    for (; j + 4 <= end; j += 4) {
        int u0 = g_csr[j], u1 = g_csr[j + 1], u2 = g_csr[j + 2], u3 = g_csr[j + 3];
        float d0 = g_dinv[u0], d1 = g_dinv[u1], d2 = g_dinv[u2], d3 = g_dinv[u3];
        float x0 = X[(size_t)u0 * FIN + f];
        float x1 = X[(size_t)u1 * FIN + f];
        float x2 = X[(size_t)u2 * FIN + f];
        float x3 = X[(size_t)u3 * FIN + f];
        acc += d0 * x0; acc += d1 * x1; acc += d2 * x2; acc += d3 * x3;
    }
    for (; j < end; j++) {
        int u = g_csr[j];
        acc += g_dinv[u] * X[(size_t)u * FIN + f];
    }
    float r = dv * acc;
    __nv_bfloat16 h = __float2bfloat16(r);
    Oh[(size_t)node * FPAD + f] = h;
    Ol[(size_t)node * FPAD + f] = __float2bfloat16(r - __bfloat162float(h));
}

__global__ void k_agg_out(const float* __restrict__ X, float* __restrict__ OUT,
                          const float* __restrict__ bias) {
    constexpr int CH = 4;
    int gw = (blockIdx.x * blockDim.x + threadIdx.x) >> 5;
    int lane = threadIdx.x & 31;
    if (gw >= CH * N_NODES) return;
    int chunk = gw / N_NODES;
    int node = gw - chunk * N_NODES;
    int f = chunk * 32 + lane;
    bool act = f < OUT_F;
    int fb = act ? f : 0;
    float dv = g_dinv[node];
    float acc = dv * X[(size_t)node * 128 + fb];
    int beg = g_off[node], end = g_off[node + 1];
    int j = beg;
    for (; j + 4 <= end; j += 4) {
        int u0 = g_csr[j], u1 = g_csr[j + 1], u2 = g_csr[j + 2], u3 = g_csr[j + 3];
        float d0 = g_dinv[u0], d1 = g_dinv[u1], d2 = g_dinv[u2], d3 = g_dinv[u3];
        float x0 = X[(size_t)u0 * 128 + fb];
        float x1 = X[(size_t)u1 * 128 + fb];
        float x2 = X[(size_t)u2 * 128 + fb];
        float x3 = X[(size_t)u3 * 128 + fb];
        acc += d0 * x0; acc += d1 * x1; acc += d2 * x2; acc += d3 * x3;
    }
    for (; j < end; j++) {
        int u = g_csr[j];
        acc += g_dinv[u] * X[(size_t)u * 128 + fb];
    }
    float r = dv * acc + bias[fb];
    if (act) OUT[(size_t)node * OUT_F + f] = r;
}

// ===================== warp-MMA GEMM (2-stage cp.async + ldmatrix) ==========
// C[M, NNTOT] (+bias,relu) = A[M, KT*32] @ B[NNTOT, KT*32]^T,  hh + hl + lh.
// Block 128x128xBK=32, 8 warps (4M x 2N), warp tile 32x64. Dynamic smem:
// 2 stages x {Ah, Al, Bh, Bl} x [128][40] bf16.
template<int KT, int NNTOT, bool BIAS, bool RELU, int OMODE>
__global__ void __launch_bounds__(256)
k_mma(const __nv_bfloat16* __restrict__ Ah, const __nv_bfloat16* __restrict__ Al,
      const __nv_bfloat16* __restrict__ Bh, const __nv_bfloat16* __restrict__ Bl,
      const float* __restrict__ bias,
      float* __restrict__ Cf, __nv_bfloat16* __restrict__ Ch, __nv_bfloat16* __restrict__ Cl) {
    constexpr int ASTR = KT * 32;
    constexpr int PAD = 40;
    constexpr int ST = 128 * PAD;            // elements per array per stage
    extern __shared__ __nv_bfloat16 dsm[];

    const int tid = threadIdx.x;
    const int wid = tid >> 5, lane = tid & 31;
    const int wm = wid & 3, wn = wid >> 2;
    const int m0 = blockIdx.x * 128;
    const int n0 = blockIdx.y * 128;

    float acc[2][8][4];
    #pragma unroll
    for (int mt = 0; mt < 2; mt++)
        #pragma unroll
        for (int nt = 0; nt < 8; nt++)
            #pragma unroll
            for (int q = 0; q < 4; q++) acc[mt][nt][q] = 0.f;

    auto stage = [&](int s, int c) {
        __nv_bfloat16* base = dsm + s * 4 * ST;
        #pragma unroll
        for (int it = 0; it < 2; it++) {
            int idx = it * 256 + tid;
            int row = idx >> 2, chk = idx & 3;
            int m = m0 + row; if (m >= N_NODES) m = N_NODES - 1;
            size_t goA = (size_t)m * ASTR + c * 32 + chk * 8;
            size_t goB = (size_t)(n0 + row) * ASTR + c * 32 + chk * 8;
            int so = row * PAD + chk * 8;
            CP_ASYNC16(smem_u32(base + 0 * ST + so), Ah + goA);
            CP_ASYNC16(smem_u32(base + 1 * ST + so), Al + goA);
            CP_ASYNC16(smem_u32(base + 2 * ST + so), Bh + goB);
            CP_ASYNC16(smem_u32(base + 3 * ST + so), Bl + goB);
        }
        CP_COMMIT();
    };

    stage(0, 0);
    for (int c = 0; c < KT; c++) {
        if (c + 1 < KT) {
            stage((c + 1) & 1, c + 1);
            asm volatile("cp.async.wait_group 1;" ::: "memory");
        } else {
            asm volatile("cp.async.wait_group 0;" ::: "memory");
        }
        __syncthreads();

        const __nv_bfloat16* Sb = dsm + (c & 1) * 4 * ST;
        const __nv_bfloat16* sAh = Sb;
        const __nv_bfloat16* sAl = Sb + ST;
        const __nv_bfloat16* sBh = Sb + 2 * ST;
        const __nv_bfloat16* sBl = Sb + 3 * ST;

        #pragma unroll
        for (int ks = 0; ks < 2; ks++) {
            const int kc = ks * 16;
            // A fragments via ldmatrix.x4 (16x16 tile)
            uint32_t a_h[2][4], a_l[2][4];
            #pragma unroll
            for (int mt = 0; mt < 2; mt++) {
                int r = wm * 32 + mt * 16 + (lane & 15);
                int cA = kc + ((lane >> 4) << 3);
                LDM_X4(a_h[mt], smem_u32(sAh + r * PAD + cA));
                LDM_X4(a_l[mt], smem_u32(sAl + r * PAD + cA));
            }
            // B fragments: x4 covers two adjacent n8 tiles
            #pragma unroll
            for (int ntp = 0; ntp < 4; ntp++) {
                int br = wn * 64 + ntp * 16 + (lane & 7) + ((lane & 16) ? 8 : 0);
                int cB = kc + ((lane & 8) ? 8 : 0);
                uint32_t b_h[4], b_l[4];
                LDM_X4(b_h, smem_u32(sBh + br * PAD + cB));
                LDM_X4(b_l, smem_u32(sBl + br * PAD + cB));
                #pragma unroll
                for (int half = 0; half < 2; half++) {
                    int nt = ntp * 2 + half;
                    #pragma unroll
                    for (int mt = 0; mt < 2; mt++) {
                        mma16816(acc[mt][nt], a_h[mt], b_h + 2 * half);  // hi*hi
                        mma16816(acc[mt][nt], a_h[mt], b_l + 2 * half);  // hi*lo
                        mma16816(acc[mt][nt], a_l[mt], b_h + 2 * half);  // lo*hi
                    }
                }
            }
        }
        __syncthreads();
    }

    // ---- epilogue ----
    #pragma unroll
    for (int mt = 0; mt < 2; mt++) {
        int mrow = m0 + wm * 32 + mt * 16 + (lane >> 2);
        #pragma unroll
        for (int nt = 0; nt < 8; nt++) {
            int n = n0 + wn * 64 + nt * 8 + (lane & 3) * 2;
            float v0 = acc[mt][nt][0], v1 = acc[mt][nt][1];
            float v2 = acc[mt][nt][2], v3 = acc[mt][nt][3];
            if (BIAS) {
                float bb0 = bias[n], bb1 = bias[n + 1];
                v0 += bb0; v1 += bb1; v2 += bb0; v3 += bb1;
            }
            if (RELU) {
                v0 = fmaxf(v0, 0.f); v1 = fmaxf(v1, 0.f);
                v2 = fmaxf(v2, 0.f); v3 = fmaxf(v3, 0.f);
            }
            if (OMODE == 0) {
                if (mrow < N_NODES)
                    *(float2*)(Cf + (size_t)mrow * NNTOT + n) = make_float2(v0, v1);
                if (mrow + 8 < N_NODES)
                    *(float2*)(Cf + (size_t)(mrow + 8) * NNTOT + n) = make_float2(v2, v3);
            } else {
                if (mrow < N_NODES) {
                    __nv_bfloat16 h0 = __float2bfloat16(v0), h1 = __float2bfloat16(v1);
                    *(__nv_bfloat162*)(Ch + (size_t)mrow * NNTOT + n) = __halves2bfloat162(h0, h1);
                    *(__nv_bfloat162*)(Cl + (size_t)mrow * NNTOT + n) = __halves2bfloat162(
                        __float2bfloat16(v0 - __bfloat162float(h0)),
                        __float2bfloat16(v1 - __bfloat162float(h1)));
                }
                if (mrow + 8 < N_NODES) {
                    __nv_bfloat16 h2 = __float2bfloat16(v2), h3 = __float2bfloat16(v3);
                    *(__nv_bfloat162*)(Ch + (size_t)(mrow + 8) * NNTOT + n) = __halves2bfloat162(h2, h3);
                    *(__nv_bfloat162*)(Cl + (size_t)(mrow + 8) * NNTOT + n) = __halves2bfloat162(
                        __float2bfloat16(v2 - __bfloat162float(h2)),
                        __float2bfloat16(v3 - __bfloat162float(h3)));
                }
            }
        }
    }
}

// ===================== launch ===============================================
static inline void* sym(const void* s) {
    void* p = nullptr;
    cudaGetSymbolAddress(&p, s);
    return p;
}

extern "C" void kernel_launch(void* const* d_in, const int* in_sizes, int n_in,
                              void* d_out, int out_size) {
    const float* x   = (const float*)d_in[0];
    const void*  ei  = d_in[1];
    const float* W1  = (const float*)d_in[2];
    const float* b1  = (const float*)d_in[3];
    const float* W2  = (const float*)d_in[4];
    const float* b2  = (const float*)d_in[5];
    const float* W3  = (const float*)d_in[6];
    const float* b3  = (const float*)d_in[7];
    float*       out = (float*)d_out;

    __nv_bfloat16* B1h = (__nv_bfloat16*)sym(g_B1h); __nv_bfloat16* B1l = (__nv_bfloat16*)sym(g_B1l);
    __nv_bfloat16* B2h = (__nv_bfloat16*)sym(g_B2h); __nv_bfloat16* B2l = (__nv_bfloat16*)sym(g_B2l);
    __nv_bfloat16* B3h = (__nv_bfloat16*)sym(g_B3h); __nv_bfloat16* B3l = (__nv_bfloat16*)sym(g_B3l);
    __nv_bfloat16* A1h = (__nv_bfloat16*)sym(g_A1h); __nv_bfloat16* A1l = (__nv_bfloat16*)sym(g_A1l);
    __nv_bfloat16* A2h = (__nv_bfloat16*)sym(g_A2h); __nv_bfloat16* A2l = (__nv_bfloat16*)sym(g_A2l);
    __nv_bfloat16* A3h = (__nv_bfloat16*)sym(g_A3h); __nv_bfloat16* A3l = (__nv_bfloat16*)sym(g_A3l);
    float* h1 = (float*)sym(g_h1);
    float* t3 = (float*)sym(g_t3);

    const int NB_N = (N_NODES + 255) / 256;
    const int NB_E = (N_EDGES + 255) / 256;
    const int NBLK = (N_NODES + 1023) / 1024;

    const int SMEM_MMA = 2 * 4 * 128 * 40 * (int)sizeof(__nv_bfloat16);  // 81920
    static int attr_done = 0;
    cudaFuncSetAttribute(k_mma<2, 256, true,  true,  0>, cudaFuncAttributeMaxDynamicSharedMemorySize, SMEM_MMA);
    cudaFuncSetAttribute(k_mma<8, 256, true,  true,  1>, cudaFuncAttributeMaxDynamicSharedMemorySize, SMEM_MMA);
    cudaFuncSetAttribute(k_mma<8, 128, false, false, 0>, cudaFuncAttributeMaxDynamicSharedMemorySize, SMEM_MMA);
    (void)attr_done;

    // edge canonicalization + graph preprocessing
    k_zero_flag<<<1, 32>>>();
    k_detect   <<<16, 256>>>((const long long*)ei);
    k_init     <<<NB_N, 256>>>();
    k_convert  <<<NB_E, 256>>>(ei);   // fused convert + degree count
    k_dinv     <<<NB_N, 256>>>();
    k_scan1    <<<NBLK, 1024>>>();
    k_scan2    <<<1, 32>>>(NBLK);
    k_scan3    <<<NBLK, 1024>>>();
    k_scatter  <<<NB_E, 256>>>();

    // weight prep (transpose + split + pad)
    k_prepw<<<(256 * 64  + 255) / 256, 256>>>(W1, B1h, B1l, IN_F, 256, 64,  256);
    k_prepw<<<(256 * 256 + 255) / 256, 256>>>(W2, B2h, B2l, 256,  256, 256, 256);
    k_prepw<<<(128 * 256 + 255) / 256, 256>>>(W3, B3h, B3l, 256,  OUT_F, 256, 128);

    // Layer 1: agg(x) -> A1 pair; GEMM K=64 N=256 (+b1, relu) -> h1 fp32
    {
        long long warps = (long long)N_NODES * 2;
        k_agg_pair<IN_F, 64><<<(int)((warps * 32 + 255) / 256), 256>>>(x, A1h, A1l);
    }
    {
        dim3 grid(M_TILES, 2);
        k_mma<2, 256, true, true, 0><<<grid, 256, SMEM_MMA>>>(A1h, A1l, B1h, B1l, b1, h1, nullptr, nullptr);
    }

    // Layer 2: agg(h1) -> A2 pair; GEMM K=256 N=256 (+b2, relu) -> A3 pair
    {
        long long warps = (long long)N_NODES * 8;
        k_agg_pair<256, 256><<<(int)((warps * 32 + 255) / 256), 256>>>(h1, A2h, A2l);
    }
    {
        dim3 grid(M_TILES, 2);
        k_mma<8, 256, true, true, 1><<<grid, 256, SMEM_MMA>>>(A2h, A2l, B2h, B2l, b2, nullptr, A3h, A3l);
    }

    // Layer 3: GEMM K=256 N=128(pad of 121) -> t3 fp32; agg(t3)+b3 -> out
    {
        dim3 grid(M_TILES, 1);
        k_mma<8, 128, false, false, 0><<<grid, 256, SMEM_MMA>>>(A3h, A3l, B3h, B3l, nullptr, t3, nullptr, nullptr);
    }
    {
        long long warps = (long long)N_NODES * 4;
        k_agg_out<<<(int)((warps * 32 + 255) / 256), 256>>>(t3, out, b3);
    }
}

// round 6
// speedup vs baseline: 2.5567x; 1.5431x over previous
#include <cuda_runtime.h>
#include <cuda_bf16.h>
#include <stdint.h>

#define N_NODES 100000
#define N_EDGES 1600000
#define IN_F 50
#define HID 256
#define OUT_F 121
#define M_TILES ((N_NODES + 127) / 128)   // 782

// ===================== scratch (static __device__) ==========================
__device__ int   g_flag;
__device__ int   g_row32[N_EDGES];
__device__ int   g_col32[N_EDGES];
__device__ int   g_deg[N_NODES];
__device__ float g_dinv[N_NODES];
__device__ int   g_off[N_NODES + 1];
__device__ int   g_cur[N_NODES];
__device__ int   g_csr[N_EDGES];
__device__ int   g_bsum[128];

__device__ __nv_bfloat16 g_B1h[256 * 64],  g_B1l[256 * 64];    // W1^T padded K->64
__device__ __nv_bfloat16 g_B2h[256 * 256], g_B2l[256 * 256];   // W2^T
__device__ __nv_bfloat16 g_B3h[128 * 256], g_B3l[128 * 256];   // W3^T padded N->128

__device__ __nv_bfloat16 g_A1h[(size_t)N_NODES * 64],  g_A1l[(size_t)N_NODES * 64];
__device__ __nv_bfloat16 g_A2h[(size_t)N_NODES * 256], g_A2l[(size_t)N_NODES * 256];
__device__ __nv_bfloat16 g_A3h[(size_t)N_NODES * 256], g_A3l[(size_t)N_NODES * 256];
__device__ float g_h1[(size_t)N_NODES * 256];
__device__ float g_t3[(size_t)N_NODES * 128];

// ===================== small PTX helpers (baseline features only) ===========
__device__ __forceinline__ uint32_t smem_u32(const void* p) {
    uint32_t a;
    asm("{ .reg .u64 t; cvta.to.shared.u64 t, %1; cvt.u32.u64 %0, t; }" : "=r"(a) : "l"(p));
    return a;
}

#define CP_ASYNC16(dst_u32, src_ptr) \
    asm volatile("cp.async.cg.shared.global [%0], [%1], 16;" :: "r"(dst_u32), "l"(src_ptr))
#define CP_COMMIT() asm volatile("cp.async.commit_group;" ::: "memory")

#define LDM_X4(R, ADDR) \
    asm volatile("ldmatrix.sync.aligned.m8n8.x4.shared.b16 {%0,%1,%2,%3}, [%4];" \
        : "=r"((R)[0]), "=r"((R)[1]), "=r"((R)[2]), "=r"((R)[3]) : "r"(ADDR))

__device__ __forceinline__ void mma16816(float* d, const uint32_t* a, const uint32_t* b) {
    asm volatile(
        "mma.sync.aligned.m16n8k16.row.col.f32.bf16.bf16.f32 "
        "{%0,%1,%2,%3}, {%4,%5,%6,%7}, {%8,%9}, {%0,%1,%2,%3};"
        : "+f"(d[0]), "+f"(d[1]), "+f"(d[2]), "+f"(d[3])
        : "r"(a[0]), "r"(a[1]), "r"(a[2]), "r"(a[3]), "r"(b[0]), "r"(b[1]));
}

// ===================== edge dtype probe (single block, no pre-zero) =========
__global__ void k_detect1(const long long* __restrict__ ei64) {
    __shared__ int bad;
    if (threadIdx.x == 0) bad = 0;
    __syncthreads();
    int ok = 1;
    for (int i = threadIdx.x; i < 4096; i += 1024) {
        long long v = ei64[i];
        if (v < 0 || v >= N_NODES) ok = 0;
    }
    if (!ok) atomicOr(&bad, 1);
    __syncthreads();
    if (threadIdx.x == 0) g_flag = bad;
}

__global__ void k_init() {
    int v = blockIdx.x * blockDim.x + threadIdx.x;
    if (v < N_NODES) { g_deg[v] = 1; g_cur[v] = 0; }
}

// convert + degree-count fused (k_init must run first)
__global__ void k_convert(const void* __restrict__ ei) {
    int e = blockIdx.x * blockDim.x + threadIdx.x;
    if (e >= N_EDGES) return;
    int r, c;
    if (g_flag) {
        const int* p = (const int*)ei;
        r = p[e]; c = p[N_EDGES + e];
    } else {
        const long long* p = (const long long*)ei;
        r = (int)p[e]; c = (int)p[N_EDGES + e];
    }
    g_row32[e] = r;
    g_col32[e] = c;
    atomicAdd(&g_deg[c], 1);
}

// ===================== scan (+dinv fused) ===================================
__global__ void k_scan1() {
    __shared__ int s[1024];
    int tid = threadIdx.x;
    int v = blockIdx.x * 1024 + tid;
    int d = (v < N_NODES) ? g_deg[v] : 1;
    if (v < N_NODES) g_dinv[v] = rsqrtf((float)d);
    int c = (v < N_NODES) ? (d - 1) : 0;
    s[tid] = c;
    __syncthreads();
    #pragma unroll
    for (int o = 1; o < 1024; o <<= 1) {
        int t = (tid >= o) ? s[tid - o] : 0;
        __syncthreads();
        if (tid >= o) s[tid] += t;
        __syncthreads();
    }
    if (v < N_NODES) g_off[v + 1] = s[tid];
    if (tid == 1023) g_bsum[blockIdx.x] = s[1023];
}

__global__ void k_scan2(int nblk) {
    if (threadIdx.x == 0 && blockIdx.x == 0) {
        int acc = 0;
        for (int b = 0; b < nblk; b++) { int t = g_bsum[b]; g_bsum[b] = acc; acc += t; }
    }
}

__global__ void k_scan3() {
    int tid = threadIdx.x;
    int v = blockIdx.x * 1024 + tid;
    if (v < N_NODES) g_off[v + 1] += g_bsum[blockIdx.x];
    if (v == 0) g_off[0] = 0;
}

__global__ void k_scatter() {
    int e = blockIdx.x * blockDim.x + threadIdx.x;
    if (e < N_EDGES) {
        int c = g_col32[e];
        int p = g_off[c] + atomicAdd(&g_cur[c], 1);
        g_csr[p] = g_row32[e];
    }
}

// ===================== weight prep: all three, one kernel ===================
__global__ void k_prepw_all(const float* __restrict__ W1, const float* __restrict__ W2,
                            const float* __restrict__ W3) {
    int i = blockIdx.x * 256 + threadIdx.x;
    float v;
    __nv_bfloat16 *ph, *pl;
    int idx;
    if (i < 256 * 64) {                       // B1: [256][64], W1 is [50][256]
        int n = i >> 6, k = i & 63;
        v = (k < IN_F) ? W1[(size_t)k * 256 + n] : 0.f;
        ph = g_B1h; pl = g_B1l; idx = i;
    } else if (i < 256 * 64 + 256 * 256) {    // B2: [256][256], W2 is [256][256]
        int j = i - 256 * 64;
        int n = j >> 8, k = j & 255;
        v = W2[(size_t)k * 256 + n];
        ph = g_B2h; pl = g_B2l; idx = j;
    } else if (i < 256 * 64 + 256 * 256 + 128 * 256) {  // B3: [128][256], W3 is [256][121]
        int j = i - 256 * 64 - 256 * 256;
        int n = j >> 8, k = j & 255;
        v = (n < OUT_F) ? W3[(size_t)k * OUT_F + n] : 0.f;
        ph = g_B3h; pl = g_B3l; idx = j;
    } else return;
    __nv_bfloat16 h = __float2bfloat16(v);
    ph[idx] = h;
    pl[idx] = __float2bfloat16(v - __bfloat162float(h));
}

// ===================== aggregation (vectorized, chunk-major) ================
__device__ __forceinline__ void pair_store2(__nv_bfloat16* Oh, __nv_bfloat16* Ol,
                                            size_t off, float v0, float v1) {
    __nv_bfloat16 h0 = __float2bfloat16(v0), h1 = __float2bfloat16(v1);
    *(__nv_bfloat162*)(Oh + off) = __halves2bfloat162(h0, h1);
    *(__nv_bfloat162*)(Ol + off) = __halves2bfloat162(
        __float2bfloat16(v0 - __bfloat162float(h0)),
        __float2bfloat16(v1 - __bfloat162float(h1)));
}

// layer-1 agg: X[N][50] fp32 (read as float2, row stride 25), out pair [N][64]
__global__ void k_agg1(const float2* __restrict__ X2,
                       __nv_bfloat16* __restrict__ Oh, __nv_bfloat16* __restrict__ Ol) {
    int gw = (blockIdx.x * blockDim.x + threadIdx.x) >> 5;
    int lane = threadIdx.x & 31;
    if (gw >= N_NODES) return;
    int node = gw;
    bool act = lane < 25;
    int c2 = act ? lane : 0;
    float dv = g_dinv[node];
    float2 xv = X2[(size_t)node * 25 + c2];
    float ax = dv * xv.x, ay = dv * xv.y;
    int beg = g_off[node], end = g_off[node + 1];
    int j = beg;
    for (; j + 4 <= end; j += 4) {
        int u0 = g_csr[j], u1 = g_csr[j + 1], u2 = g_csr[j + 2], u3 = g_csr[j + 3];
        float d0 = g_dinv[u0], d1 = g_dinv[u1], d2 = g_dinv[u2], d3 = g_dinv[u3];
        float2 a0 = X2[(size_t)u0 * 25 + c2];
        float2 a1 = X2[(size_t)u1 * 25 + c2];
        float2 a2 = X2[(size_t)u2 * 25 + c2];
        float2 a3 = X2[(size_t)u3 * 25 + c2];
        ax += d0 * a0.x; ay += d0 * a0.y;
        ax += d1 * a1.x; ay += d1 * a1.y;
        ax += d2 * a2.x; ay += d2 * a2.y;
        ax += d3 * a3.x; ay += d3 * a3.y;
    }
    for (; j < end; j++) {
        int u = g_csr[j];
        float d = g_dinv[u];
        float2 a = X2[(size_t)u * 25 + c2];
        ax += d * a.x; ay += d * a.y;
    }
    float v0 = act ? dv * ax : 0.f;
    float v1 = act ? dv * ay : 0.f;
    pair_store2(Oh, Ol, (size_t)node * 64 + lane * 2, v0, v1);
}

// layer-2 agg: X[N][256] fp32 (float4, row stride 64), out pair [N][256]
__global__ void k_agg2(const float4* __restrict__ X4,
                       __nv_bfloat16* __restrict__ Oh, __nv_bfloat16* __restrict__ Ol) {
    int gw = (blockIdx.x * blockDim.x + threadIdx.x) >> 5;
    int lane = threadIdx.x & 31;
    if (gw >= 2 * N_NODES) return;
    int chunk = gw >= N_NODES ? 1 : 0;       // chunk-major: 12.8MB slice L2-resident
    int node = gw - chunk * N_NODES;
    int c4 = chunk * 32 + lane;              // float4 column (0..63)
    float dv = g_dinv[node];
    float4 xv = X4[(size_t)node * 64 + c4];
    float a0 = dv * xv.x, a1 = dv * xv.y, a2 = dv * xv.z, a3 = dv * xv.w;
    int beg = g_off[node], end = g_off[node + 1];
    int j = beg;
    for (; j + 4 <= end; j += 4) {
        int u0 = g_csr[j], u1 = g_csr[j + 1], u2 = g_csr[j + 2], u3 = g_csr[j + 3];
        float d0 = g_dinv[u0], d1 = g_dinv[u1], d2 = g_dinv[u2], d3 = g_dinv[u3];
        float4 p0 = X4[(size_t)u0 * 64 + c4];
        float4 p1 = X4[(size_t)u1 * 64 + c4];
        float4 p2 = X4[(size_t)u2 * 64 + c4];
        float4 p3 = X4[(size_t)u3 * 64 + c4];
        a0 += d0 * p0.x; a1 += d0 * p0.y; a2 += d0 * p0.z; a3 += d0 * p0.w;
        a0 += d1 * p1.x; a1 += d1 * p1.y; a2 += d1 * p1.z; a3 += d1 * p1.w;
        a0 += d2 * p2.x; a1 += d2 * p2.y; a2 += d2 * p2.z; a3 += d2 * p2.w;
        a0 += d3 * p3.x; a1 += d3 * p3.y; a2 += d3 * p3.z; a3 += d3 * p3.w;
    }
    for (; j < end; j++) {
        int u = g_csr[j];
        float d = g_dinv[u];
        float4 p = X4[(size_t)u * 64 + c4];
        a0 += d * p.x; a1 += d * p.y; a2 += d * p.z; a3 += d * p.w;
    }
    a0 *= dv; a1 *= dv; a2 *= dv; a3 *= dv;
    size_t off = (size_t)node * 256 + c4 * 4;
    pair_store2(Oh, Ol, off, a0, a1);
    pair_store2(Oh, Ol, off + 2, a2, a3);
}

// final agg: X = t3 [N][128] fp32 (float4, stride 32), +bias, out [N][121] fp32
__global__ void k_agg_out(const float4* __restrict__ X4, float* __restrict__ OUT,
                          const float* __restrict__ bias) {
    int gw = (blockIdx.x * blockDim.x + threadIdx.x) >> 5;
    int lane = threadIdx.x & 31;
    if (gw >= N_NODES) return;
    int node = gw;
    float dv = g_dinv[node];
    float4 xv = X4[(size_t)node * 32 + lane];
    float a0 = dv * xv.x, a1 = dv * xv.y, a2 = dv * xv.z, a3 = dv * xv.w;
    int beg = g_off[node], end = g_off[node + 1];
    int j = beg;
    for (; j + 4 <= end; j += 4) {
        int u0 = g_csr[j], u1 = g_csr[j + 1], u2 = g_csr[j + 2], u3 = g_csr[j + 3];
        float d0 = g_dinv[u0], d1 = g_dinv[u1], d2 = g_dinv[u2], d3 = g_dinv[u3];
        float4 p0 = X4[(size_t)u0 * 32 + lane];
        float4 p1 = X4[(size_t)u1 * 32 + lane];
        float4 p2 = X4[(size_t)u2 * 32 + lane];
        float4 p3 = X4[(size_t)u3 * 32 + lane];
        a0 += d0 * p0.x; a1 += d0 * p0.y; a2 += d0 * p0.z; a3 += d0 * p0.w;
        a0 += d1 * p1.x; a1 += d1 * p1.y; a2 += d1 * p1.z; a3 += d1 * p1.w;
        a0 += d2 * p2.x; a1 += d2 * p2.y; a2 += d2 * p2.z; a3 += d2 * p2.w;
        a0 += d3 * p3.x; a1 += d3 * p3.y; a2 += d3 * p3.z; a3 += d3 * p3.w;
    }
    for (; j < end; j++) {
        int u = g_csr[j];
        float d = g_dinv[u];
        float4 p = X4[(size_t)u * 32 + lane];
        a0 += d * p.x; a1 += d * p.y; a2 += d * p.z; a3 += d * p.w;
    }
    int c = lane * 4;
    float* dst = OUT + (size_t)node * OUT_F;
    if (c + 0 < OUT_F) dst[c + 0] = dv * a0 + bias[c + 0];
    if (c + 1 < OUT_F) dst[c + 1] = dv * a1 + bias[c + 1];
    if (c + 2 < OUT_F) dst[c + 2] = dv * a2 + bias[c + 2];
    if (c + 3 < OUT_F) dst[c + 3] = dv * a3 + bias[c + 3];
}

// ===================== warp-MMA GEMM (2-stage cp.async + ldmatrix) ==========
template<int KT, int NNTOT, bool BIAS, bool RELU, int OMODE>
__global__ void __launch_bounds__(256)
k_mma(const __nv_bfloat16* __restrict__ Ah, const __nv_bfloat16* __restrict__ Al,
      const __nv_bfloat16* __restrict__ Bh, const __nv_bfloat16* __restrict__ Bl,
      const float* __restrict__ bias,
      float* __restrict__ Cf, __nv_bfloat16* __restrict__ Ch, __nv_bfloat16* __restrict__ Cl) {
    constexpr int ASTR = KT * 32;
    constexpr int PAD = 40;
    constexpr int ST = 128 * PAD;
    extern __shared__ __nv_bfloat16 dsm[];

    const int tid = threadIdx.x;
    const int wid = tid >> 5, lane = tid & 31;
    const int wm = wid & 3, wn = wid >> 2;
    const int m0 = blockIdx.x * 128;
    const int n0 = blockIdx.y * 128;

    float acc[2][8][4];
    #pragma unroll
    for (int mt = 0; mt < 2; mt++)
        #pragma unroll
        for (int nt = 0; nt < 8; nt++)
            #pragma unroll
            for (int q = 0; q < 4; q++) acc[mt][nt][q] = 0.f;

    auto stage = [&](int s, int c) {
        __nv_bfloat16* base = dsm + s * 4 * ST;
        #pragma unroll
        for (int it = 0; it < 2; it++) {
            int idx = it * 256 + tid;
            int row = idx >> 2, chk = idx & 3;
            int m = m0 + row; if (m >= N_NODES) m = N_NODES - 1;
            size_t goA = (size_t)m * ASTR + c * 32 + chk * 8;
            size_t goB = (size_t)(n0 + row) * ASTR + c * 32 + chk * 8;
            int so = row * PAD + chk * 8;
            CP_ASYNC16(smem_u32(base + 0 * ST + so), Ah + goA);
            CP_ASYNC16(smem_u32(base + 1 * ST + so), Al + goA);
            CP_ASYNC16(smem_u32(base + 2 * ST + so), Bh + goB);
            CP_ASYNC16(smem_u32(base + 3 * ST + so), Bl + goB);
        }
        CP_COMMIT();
    };

    stage(0, 0);
    for (int c = 0; c < KT; c++) {
        if (c + 1 < KT) {
            stage((c + 1) & 1, c + 1);
            asm volatile("cp.async.wait_group 1;" ::: "memory");
        } else {
            asm volatile("cp.async.wait_group 0;" ::: "memory");
        }
        __syncthreads();

        const __nv_bfloat16* Sb = dsm + (c & 1) * 4 * ST;
        const __nv_bfloat16* sAh = Sb;
        const __nv_bfloat16* sAl = Sb + ST;
        const __nv_bfloat16* sBh = Sb + 2 * ST;
        const __nv_bfloat16* sBl = Sb + 3 * ST;

        #pragma unroll
        for (int ks = 0; ks < 2; ks++) {
            const int kc = ks * 16;
            uint32_t a_h[2][4], a_l[2][4];
            #pragma unroll
            for (int mt = 0; mt < 2; mt++) {
                int r = wm * 32 + mt * 16 + (lane & 15);
                int cA = kc + ((lane >> 4) << 3);
                LDM_X4(a_h[mt], smem_u32(sAh + r * PAD + cA));
                LDM_X4(a_l[mt], smem_u32(sAl + r * PAD + cA));
            }
            #pragma unroll
            for (int ntp = 0; ntp < 4; ntp++) {
                int br = wn * 64 + ntp * 16 + (lane & 7) + ((lane & 16) ? 8 : 0);
                int cB = kc + ((lane & 8) ? 8 : 0);
                uint32_t b_h[4], b_l[4];
                LDM_X4(b_h, smem_u32(sBh + br * PAD + cB));
                LDM_X4(b_l, smem_u32(sBl + br * PAD + cB));
                #pragma unroll
                for (int half = 0; half < 2; half++) {
                    int nt = ntp * 2 + half;
                    #pragma unroll
                    for (int mt = 0; mt < 2; mt++) {
                        mma16816(acc[mt][nt], a_h[mt], b_h + 2 * half);
                        mma16816(acc[mt][nt], a_h[mt], b_l + 2 * half);
                        mma16816(acc[mt][nt], a_l[mt], b_h + 2 * half);
                    }
                }
            }
        }
        __syncthreads();
    }

    #pragma unroll
    for (int mt = 0; mt < 2; mt++) {
        int mrow = m0 + wm * 32 + mt * 16 + (lane >> 2);
        #pragma unroll
        for (int nt = 0; nt < 8; nt++) {
            int n = n0 + wn * 64 + nt * 8 + (lane & 3) * 2;
            float v0 = acc[mt][nt][0], v1 = acc[mt][nt][1];
            float v2 = acc[mt][nt][2], v3 = acc[mt][nt][3];
            if (BIAS) {
                float bb0 = bias[n], bb1 = bias[n + 1];
                v0 += bb0; v1 += bb1; v2 += bb0; v3 += bb1;
            }
            if (RELU) {
                v0 = fmaxf(v0, 0.f); v1 = fmaxf(v1, 0.f);
                v2 = fmaxf(v2, 0.f); v3 = fmaxf(v3, 0.f);
            }
            if (OMODE == 0) {
                if (mrow < N_NODES)
                    *(float2*)(Cf + (size_t)mrow * NNTOT + n) = make_float2(v0, v1);
                if (mrow + 8 < N_NODES)
                    *(float2*)(Cf + (size_t)(mrow + 8) * NNTOT + n) = make_float2(v2, v3);
            } else {
                if (mrow < N_NODES)
                    pair_store2(Ch, Cl, (size_t)mrow * NNTOT + n, v0, v1);
                if (mrow + 8 < N_NODES)
                    pair_store2(Ch, Cl, (size_t)(mrow + 8) * NNTOT + n, v2, v3);
            }
        }
    }
}

// ===================== launch ===============================================
static inline void* sym(const void* s) {
    void* p = nullptr;
    cudaGetSymbolAddress(&p, s);
    return p;
}

extern "C" void kernel_launch(void* const* d_in, const int* in_sizes, int n_in,
                              void* d_out, int out_size) {
    const float* x   = (const float*)d_in[0];
    const void*  ei  = d_in[1];
    const float* W1  = (const float*)d_in[2];
    const float* b1  = (const float*)d_in[3];
    const float* W2  = (const float*)d_in[4];
    const float* b2  = (const float*)d_in[5];
    const float* W3  = (const float*)d_in[6];
    const float* b3  = (const float*)d_in[7];
    float*       out = (float*)d_out;

    __nv_bfloat16* B1h = (__nv_bfloat16*)sym(g_B1h); __nv_bfloat16* B1l = (__nv_bfloat16*)sym(g_B1l);
    __nv_bfloat16* B2h = (__nv_bfloat16*)sym(g_B2h); __nv_bfloat16* B2l = (__nv_bfloat16*)sym(g_B2l);
    __nv_bfloat16* B3h = (__nv_bfloat16*)sym(g_B3h); __nv_bfloat16* B3l = (__nv_bfloat16*)sym(g_B3l);
    __nv_bfloat16* A1h = (__nv_bfloat16*)sym(g_A1h); __nv_bfloat16* A1l = (__nv_bfloat16*)sym(g_A1l);
    __nv_bfloat16* A2h = (__nv_bfloat16*)sym(g_A2h); __nv_bfloat16* A2l = (__nv_bfloat16*)sym(g_A2l);
    __nv_bfloat16* A3h = (__nv_bfloat16*)sym(g_A3h); __nv_bfloat16* A3l = (__nv_bfloat16*)sym(g_A3l);
    float* h1 = (float*)sym(g_h1);
    float* t3 = (float*)sym(g_t3);

    const int NB_N = (N_NODES + 255) / 256;
    const int NB_E = (N_EDGES + 255) / 256;
    const int NBLK = (N_NODES + 1023) / 1024;

    const int SMEM_MMA = 2 * 4 * 128 * 40 * (int)sizeof(__nv_bfloat16);  // 81920
    cudaFuncSetAttribute(k_mma<2, 256, true,  true,  0>, cudaFuncAttributeMaxDynamicSharedMemorySize, SMEM_MMA);
    cudaFuncSetAttribute(k_mma<8, 256, true,  true,  1>, cudaFuncAttributeMaxDynamicSharedMemorySize, SMEM_MMA);
    cudaFuncSetAttribute(k_mma<8, 128, false, false, 0>, cudaFuncAttributeMaxDynamicSharedMemorySize, SMEM_MMA);

    // preprocessing
    k_detect1  <<<1, 1024>>>((const long long*)ei);
    k_init     <<<NB_N, 256>>>();
    k_convert  <<<NB_E, 256>>>(ei);
    k_scan1    <<<NBLK, 1024>>>();          // also computes dinv
    k_scan2    <<<1, 32>>>(NBLK);
    k_scan3    <<<NBLK, 1024>>>();
    k_scatter  <<<NB_E, 256>>>();
    k_prepw_all<<<(256*64 + 256*256 + 128*256 + 255) / 256, 256>>>(W1, W2, W3);

    // Layer 1
    k_agg1<<<(N_NODES * 32 + 255) / 256, 256>>>((const float2*)x, A1h, A1l);
    {
        dim3 grid(M_TILES, 2);
        k_mma<2, 256, true, true, 0><<<grid, 256, SMEM_MMA>>>(A1h, A1l, B1h, B1l, b1, h1, nullptr, nullptr);
    }

    // Layer 2
    k_agg2<<<(2 * N_NODES * 32 + 255) / 256, 256>>>((const float4*)h1, A2h, A2l);
    {
        dim3 grid(M_TILES, 2);
        k_mma<8, 256, true, true, 1><<<grid, 256, SMEM_MMA>>>(A2h, A2l, B2h, B2l, b2, nullptr, A3h, A3l);
    }

    // Layer 3
    {
        dim3 grid(M_TILES, 1);
        k_mma<8, 128, false, false, 0><<<grid, 256, SMEM_MMA>>>(A3h, A3l, B3h, B3l, nullptr, t3, nullptr, nullptr);
    }
    k_agg_out<<<(N_NODES * 32 + 255) / 256, 256>>>((const float4*)t3, out, b3);
}

// round 7
// speedup vs baseline: 2.6059x; 1.0192x over previous
#include <cuda_runtime.h>
#include <cuda_bf16.h>
#include <stdint.h>

#define N_NODES 100000
#define N_EDGES 1600000
#define IN_F 50
#define HID 256
#define OUT_F 121
#define M_TILES ((N_NODES + 127) / 128)   // 782

// ===================== scratch (static __device__) ==========================
__device__ int   g_flag;
__device__ int   g_row32[N_EDGES];
__device__ int   g_col32[N_EDGES];
__device__ int   g_deg[N_NODES];
__device__ float g_dinv[N_NODES];
__device__ int   g_off[N_NODES + 1];
__device__ int   g_cur[N_NODES];
__device__ int   g_csr[N_EDGES];
__device__ int   g_bsum[128];

__device__ __nv_bfloat16 g_B1h[256 * 64],  g_B1l[256 * 64];    // W1^T padded K->64
__device__ __nv_bfloat16 g_B2h[256 * 256], g_B2l[256 * 256];   // W2^T
__device__ __nv_bfloat16 g_B3h[128 * 256], g_B3l[128 * 256];   // W3^T padded N->128

__device__ __nv_bfloat16 g_A1h[(size_t)N_NODES * 64],  g_A1l[(size_t)N_NODES * 64];
__device__ __nv_bfloat16 g_A2h[(size_t)N_NODES * 256], g_A2l[(size_t)N_NODES * 256];
__device__ __nv_bfloat16 g_A3h[(size_t)N_NODES * 256], g_A3l[(size_t)N_NODES * 256];
__device__ float g_h1[(size_t)N_NODES * 256];
__device__ float g_t3[(size_t)N_NODES * 128];

// ===================== small PTX helpers (baseline features only) ===========
__device__ __forceinline__ uint32_t smem_u32(const void* p) {
    uint32_t a;
    asm("{ .reg .u64 t; cvta.to.shared.u64 t, %1; cvt.u32.u64 %0, t; }" : "=r"(a) : "l"(p));
    return a;
}

#define CP_ASYNC16(dst_u32, src_ptr) \
    asm volatile("cp.async.cg.shared.global [%0], [%1], 16;" :: "r"(dst_u32), "l"(src_ptr))
#define CP_COMMIT() asm volatile("cp.async.commit_group;" ::: "memory")

#define LDM_X4(R, ADDR) \
    asm volatile("ldmatrix.sync.aligned.m8n8.x4.shared.b16 {%0,%1,%2,%3}, [%4];" \
        : "=r"((R)[0]), "=r"((R)[1]), "=r"((R)[2]), "=r"((R)[3]) : "r"(ADDR))

__device__ __forceinline__ void mma16816(float* d, const uint32_t* a, const uint32_t* b) {
    asm volatile(
        "mma.sync.aligned.m16n8k16.row.col.f32.bf16.bf16.f32 "
        "{%0,%1,%2,%3}, {%4,%5,%6,%7}, {%8,%9}, {%0,%1,%2,%3};"
        : "+f"(d[0]), "+f"(d[1]), "+f"(d[2]), "+f"(d[3])
        : "r"(a[0]), "r"(a[1]), "r"(a[2]), "r"(a[3]), "r"(b[0]), "r"(b[1]));
}

// ===================== edge dtype probe (single block) ======================
__global__ void k_detect1(const long long* __restrict__ ei64) {
    __shared__ int bad;
    if (threadIdx.x == 0) bad = 0;
    __syncthreads();
    int ok = 1;
    for (int i = threadIdx.x; i < 4096; i += 1024) {
        long long v = ei64[i];
        if (v < 0 || v >= N_NODES) ok = 0;
    }
    if (!ok) atomicOr(&bad, 1);
    __syncthreads();
    if (threadIdx.x == 0) g_flag = bad;
}

__global__ void k_init() {
    int v = blockIdx.x * blockDim.x + threadIdx.x;
    if (v < N_NODES) { g_deg[v] = 1; g_cur[v] = 0; }
}

// convert + degree-count fused (k_init must run first)
__global__ void k_convert(const void* __restrict__ ei) {
    int e = blockIdx.x * blockDim.x + threadIdx.x;
    if (e >= N_EDGES) return;
    int r, c;
    if (g_flag) {
        const int* p = (const int*)ei;
        r = p[e]; c = p[N_EDGES + e];
    } else {
        const long long* p = (const long long*)ei;
        r = (int)p[e]; c = (int)p[N_EDGES + e];
    }
    g_row32[e] = r;
    g_col32[e] = c;
    atomicAdd(&g_deg[c], 1);
}

// ===================== scan (+dinv fused) ===================================
__global__ void k_scan1() {
    __shared__ int s[1024];
    int tid = threadIdx.x;
    int v = blockIdx.x * 1024 + tid;
    int d = (v < N_NODES) ? g_deg[v] : 1;
    if (v < N_NODES) g_dinv[v] = rsqrtf((float)d);
    int c = (v < N_NODES) ? (d - 1) : 0;
    s[tid] = c;
    __syncthreads();
    #pragma unroll
    for (int o = 1; o < 1024; o <<= 1) {
        int t = (tid >= o) ? s[tid - o] : 0;
        __syncthreads();
        if (tid >= o) s[tid] += t;
        __syncthreads();
    }
    if (v < N_NODES) g_off[v + 1] = s[tid];
    if (tid == 1023) g_bsum[blockIdx.x] = s[1023];
}

__global__ void k_scan2(int nblk) {
    if (threadIdx.x == 0 && blockIdx.x == 0) {
        int acc = 0;
        for (int b = 0; b < nblk; b++) { int t = g_bsum[b]; g_bsum[b] = acc; acc += t; }
    }
}

__global__ void k_scan3() {
    int tid = threadIdx.x;
    int v = blockIdx.x * 1024 + tid;
    if (v < N_NODES) g_off[v + 1] += g_bsum[blockIdx.x];
    if (v == 0) g_off[0] = 0;
}

__global__ void k_scatter() {
    int e = blockIdx.x * blockDim.x + threadIdx.x;
    if (e < N_EDGES) {
        int c = g_col32[e];
        int p = g_off[c] + atomicAdd(&g_cur[c], 1);
        g_csr[p] = g_row32[e];
    }
}

// ===================== weight prep: all three, one kernel ===================
__global__ void k_prepw_all(const float* __restrict__ W1, const float* __restrict__ W2,
                            const float* __restrict__ W3) {
    int i = blockIdx.x * 256 + threadIdx.x;
    float v;
    __nv_bfloat16 *ph, *pl;
    int idx;
    if (i < 256 * 64) {
        int n = i >> 6, k = i & 63;
        v = (k < IN_F) ? W1[(size_t)k * 256 + n] : 0.f;
        ph = g_B1h; pl = g_B1l; idx = i;
    } else if (i < 256 * 64 + 256 * 256) {
        int j = i - 256 * 64;
        int n = j >> 8, k = j & 255;
        v = W2[(size_t)k * 256 + n];
        ph = g_B2h; pl = g_B2l; idx = j;
    } else if (i < 256 * 64 + 256 * 256 + 128 * 256) {
        int j = i - 256 * 64 - 256 * 256;
        int n = j >> 8, k = j & 255;
        v = (n < OUT_F) ? W3[(size_t)k * OUT_F + n] : 0.f;
        ph = g_B3h; pl = g_B3l; idx = j;
    } else return;
    __nv_bfloat16 h = __float2bfloat16(v);
    ph[idx] = h;
    pl[idx] = __float2bfloat16(v - __bfloat162float(h));
}

// ===================== aggregation (vectorized, chunk-major, MLP=8) =========
__device__ __forceinline__ void pair_store2(__nv_bfloat16* Oh, __nv_bfloat16* Ol,
                                            size_t off, float v0, float v1) {
    __nv_bfloat16 h0 = __float2bfloat16(v0), h1 = __float2bfloat16(v1);
    *(__nv_bfloat162*)(Oh + off) = __halves2bfloat162(h0, h1);
    *(__nv_bfloat162*)(Ol + off) = __halves2bfloat162(
        __float2bfloat16(v0 - __bfloat162float(h0)),
        __float2bfloat16(v1 - __bfloat162float(h1)));
}

// layer-1 agg: X[N][50] fp32 (float2 lanes, row stride 25), out pair [N][64]
__global__ void k_agg1(const float2* __restrict__ X2,
                       __nv_bfloat16* __restrict__ Oh, __nv_bfloat16* __restrict__ Ol) {
    int gw = (blockIdx.x * blockDim.x + threadIdx.x) >> 5;
    int lane = threadIdx.x & 31;
    if (gw >= N_NODES) return;
    int node = gw;
    bool act = lane < 25;
    int c2 = act ? lane : 0;
    float dv = g_dinv[node];
    float2 xv = X2[(size_t)node * 25 + c2];
    float ax = dv * xv.x, ay = dv * xv.y;
    int beg = g_off[node], end = g_off[node + 1];
    int j = beg;
    for (; j + 8 <= end; j += 8) {
        int   u[8]; float dd[8]; float2 p[8];
        #pragma unroll
        for (int q = 0; q < 8; q++) u[q] = g_csr[j + q];
        #pragma unroll
        for (int q = 0; q < 8; q++) dd[q] = g_dinv[u[q]];
        #pragma unroll
        for (int q = 0; q < 8; q++) p[q] = X2[(size_t)u[q] * 25 + c2];
        #pragma unroll
        for (int q = 0; q < 8; q++) { ax += dd[q] * p[q].x; ay += dd[q] * p[q].y; }
    }
    for (; j < end; j++) {
        int u = g_csr[j];
        float d = g_dinv[u];
        float2 a = X2[(size_t)u * 25 + c2];
        ax += d * a.x; ay += d * a.y;
    }
    float v0 = act ? dv * ax : 0.f;
    float v1 = act ? dv * ay : 0.f;
    pair_store2(Oh, Ol, (size_t)node * 64 + lane * 2, v0, v1);
}

// layer-2 agg: X[N][256] fp32 (float4 lanes, row stride 64), out pair [N][256]
__global__ void k_agg2(const float4* __restrict__ X4,
                       __nv_bfloat16* __restrict__ Oh, __nv_bfloat16* __restrict__ Ol) {
    int gw = (blockIdx.x * blockDim.x + threadIdx.x) >> 5;
    int lane = threadIdx.x & 31;
    if (gw >= 2 * N_NODES) return;
    int chunk = gw >= N_NODES ? 1 : 0;       // chunk-major: half-slice L2-resident
    int node = gw - chunk * N_NODES;
    int c4 = chunk * 32 + lane;
    float dv = g_dinv[node];
    float4 xv = X4[(size_t)node * 64 + c4];
    float a0 = dv * xv.x, a1 = dv * xv.y, a2 = dv * xv.z, a3 = dv * xv.w;
    int beg = g_off[node], end = g_off[node + 1];
    int j = beg;
    for (; j + 8 <= end; j += 8) {
        int u[8]; float dd[8]; float4 p[8];
        #pragma unroll
        for (int q = 0; q < 8; q++) u[q] = g_csr[j + q];
        #pragma unroll
        for (int q = 0; q < 8; q++) dd[q] = g_dinv[u[q]];
        #pragma unroll
        for (int q = 0; q < 8; q++) p[q] = X4[(size_t)u[q] * 64 + c4];
        #pragma unroll
        for (int q = 0; q < 8; q++) {
            a0 += dd[q] * p[q].x; a1 += dd[q] * p[q].y;
            a2 += dd[q] * p[q].z; a3 += dd[q] * p[q].w;
        }
    }
    for (; j < end; j++) {
        int u = g_csr[j];
        float d = g_dinv[u];
        float4 p = X4[(size_t)u * 64 + c4];
        a0 += d * p.x; a1 += d * p.y; a2 += d * p.z; a3 += d * p.w;
    }
    a0 *= dv; a1 *= dv; a2 *= dv; a3 *= dv;
    size_t off = (size_t)node * 256 + c4 * 4;
    pair_store2(Oh, Ol, off, a0, a1);
    pair_store2(Oh, Ol, off + 2, a2, a3);
}

// final agg: X = t3 [N][128] fp32 (float4 lanes, stride 32), +bias, out [N][121]
__global__ void k_agg_out(const float4* __restrict__ X4, float* __restrict__ OUT,
                          const float* __restrict__ bias) {
    int gw = (blockIdx.x * blockDim.x + threadIdx.x) >> 5;
    int lane = threadIdx.x & 31;
    if (gw >= N_NODES) return;
    int node = gw;
    float dv = g_dinv[node];
    float4 xv = X4[(size_t)node * 32 + lane];
    float a0 = dv * xv.x, a1 = dv * xv.y, a2 = dv * xv.z, a3 = dv * xv.w;
    int beg = g_off[node], end = g_off[node + 1];
    int j = beg;
    for (; j + 8 <= end; j += 8) {
        int u[8]; float dd[8]; float4 p[8];
        #pragma unroll
        for (int q = 0; q < 8; q++) u[q] = g_csr[j + q];
        #pragma unroll
        for (int q = 0; q < 8; q++) dd[q] = g_dinv[u[q]];
        #pragma unroll
        for (int q = 0; q < 8; q++) p[q] = X4[(size_t)u[q] * 32 + lane];
        #pragma unroll
        for (int q = 0; q < 8; q++) {
            a0 += dd[q] * p[q].x; a1 += dd[q] * p[q].y;
            a2 += dd[q] * p[q].z; a3 += dd[q] * p[q].w;
        }
    }
    for (; j < end; j++) {
        int u = g_csr[j];
        float d = g_dinv[u];
        float4 p = X4[(size_t)u * 32 + lane];
        a0 += d * p.x; a1 += d * p.y; a2 += d * p.z; a3 += d * p.w;
    }
    int c = lane * 4;
    float* dst = OUT + (size_t)node * OUT_F;
    if (c + 0 < OUT_F) dst[c + 0] = dv * a0 + bias[c + 0];
    if (c + 1 < OUT_F) dst[c + 1] = dv * a1 + bias[c + 1];
    if (c + 2 < OUT_F) dst[c + 2] = dv * a2 + bias[c + 2];
    if (c + 3 < OUT_F) dst[c + 3] = dv * a3 + bias[c + 3];
}

// ===================== warp-MMA GEMM (2-stage cp.async + ldmatrix) ==========
// __launch_bounds__(256, 2): 2 CTAs/SM -> 16 warps to hide sync/load bubbles.
template<int KT, int NNTOT, bool BIAS, bool RELU, int OMODE>
__global__ void __launch_bounds__(256, 2)
k_mma(const __nv_bfloat16* __restrict__ Ah, const __nv_bfloat16* __restrict__ Al,
      const __nv_bfloat16* __restrict__ Bh, const __nv_bfloat16* __restrict__ Bl,
      const float* __restrict__ bias,
      float* __restrict__ Cf, __nv_bfloat16* __restrict__ Ch, __nv_bfloat16* __restrict__ Cl) {
    constexpr int ASTR = KT * 32;
    constexpr int PAD = 40;
    constexpr int ST = 128 * PAD;
    extern __shared__ __nv_bfloat16 dsm[];

    const int tid = threadIdx.x;
    const int wid = tid >> 5, lane = tid & 31;
    const int wm = wid & 3, wn = wid >> 2;
    const int m0 = blockIdx.x * 128;
    const int n0 = blockIdx.y * 128;

    float acc[2][8][4];
    #pragma unroll
    for (int mt = 0; mt < 2; mt++)
        #pragma unroll
        for (int nt = 0; nt < 8; nt++)
            #pragma unroll
            for (int q = 0; q < 4; q++) acc[mt][nt][q] = 0.f;

    auto stage = [&](int s, int c) {
        __nv_bfloat16* base = dsm + s * 4 * ST;
        #pragma unroll
        for (int it = 0; it < 2; it++) {
            int idx = it * 256 + tid;
            int row = idx >> 2, chk = idx & 3;
            int m = m0 + row; if (m >= N_NODES) m = N_NODES - 1;
            size_t goA = (size_t)m * ASTR + c * 32 + chk * 8;
            size_t goB = (size_t)(n0 + row) * ASTR + c * 32 + chk * 8;
            int so = row * PAD + chk * 8;
            CP_ASYNC16(smem_u32(base + 0 * ST + so), Ah + goA);
            CP_ASYNC16(smem_u32(base + 1 * ST + so), Al + goA);
            CP_ASYNC16(smem_u32(base + 2 * ST + so), Bh + goB);
            CP_ASYNC16(smem_u32(base + 3 * ST + so), Bl + goB);
        }
        CP_COMMIT();
    };

    stage(0, 0);
    for (int c = 0; c < KT; c++) {
        if (c + 1 < KT) {
            stage((c + 1) & 1, c + 1);
            asm volatile("cp.async.wait_group 1;" ::: "memory");
        } else {
            asm volatile("cp.async.wait_group 0;" ::: "memory");
        }
        __syncthreads();

        const __nv_bfloat16* Sb = dsm + (c & 1) * 4 * ST;
        const __nv_bfloat16* sAh = Sb;
        const __nv_bfloat16* sAl = Sb + ST;
        const __nv_bfloat16* sBh = Sb + 2 * ST;
        const __nv_bfloat16* sBl = Sb + 3 * ST;

        #pragma unroll
        for (int ks = 0; ks < 2; ks++) {
            const int kc = ks * 16;
            uint32_t a_h[2][4], a_l[2][4];
            #pragma unroll
            for (int mt = 0; mt < 2; mt++) {
                int r = wm * 32 + mt * 16 + (lane & 15);
                int cA = kc + ((lane >> 4) << 3);
                LDM_X4(a_h[mt], smem_u32(sAh + r * PAD + cA));
                LDM_X4(a_l[mt], smem_u32(sAl + r * PAD + cA));
            }
            #pragma unroll
            for (int ntp = 0; ntp < 4; ntp++) {
                int br = wn * 64 + ntp * 16 + (lane & 7) + ((lane & 16) ? 8 : 0);
                int cB = kc + ((lane & 8) ? 8 : 0);
                uint32_t b_h[4], b_l[4];
                LDM_X4(b_h, smem_u32(sBh + br * PAD + cB));
                LDM_X4(b_l, smem_u32(sBl + br * PAD + cB));
                #pragma unroll
                for (int half = 0; half < 2; half++) {
                    int nt = ntp * 2 + half;
                    #pragma unroll
                    for (int mt = 0; mt < 2; mt++) {
                        mma16816(acc[mt][nt], a_h[mt], b_h + 2 * half);
                        mma16816(acc[mt][nt], a_h[mt], b_l + 2 * half);
                        mma16816(acc[mt][nt], a_l[mt], b_h + 2 * half);
                    }
                }
            }
        }
        __syncthreads();
    }

    #pragma unroll
    for (int mt = 0; mt < 2; mt++) {
        int mrow = m0 + wm * 32 + mt * 16 + (lane >> 2);
        #pragma unroll
        for (int nt = 0; nt < 8; nt++) {
            int n = n0 + wn * 64 + nt * 8 + (lane & 3) * 2;
            float v0 = acc[mt][nt][0], v1 = acc[mt][nt][1];
            float v2 = acc[mt][nt][2], v3 = acc[mt][nt][3];
            if (BIAS) {
                float bb0 = bias[n], bb1 = bias[n + 1];
                v0 += bb0; v1 += bb1; v2 += bb0; v3 += bb1;
            }
            if (RELU) {
                v0 = fmaxf(v0, 0.f); v1 = fmaxf(v1, 0.f);
                v2 = fmaxf(v2, 0.f); v3 = fmaxf(v3, 0.f);
            }
            if (OMODE == 0) {
                if (mrow < N_NODES)
                    *(float2*)(Cf + (size_t)mrow * NNTOT + n) = make_float2(v0, v1);
                if (mrow + 8 < N_NODES)
                    *(float2*)(Cf + (size_t)(mrow + 8) * NNTOT + n) = make_float2(v2, v3);
            } else {
                if (mrow < N_NODES)
                    pair_store2(Ch, Cl, (size_t)mrow * NNTOT + n, v0, v1);
                if (mrow + 8 < N_NODES)
                    pair_store2(Ch, Cl, (size_t)(mrow + 8) * NNTOT + n, v2, v3);
            }
        }
    }
}

// ===================== launch ===============================================
static inline void* sym(const void* s) {
    void* p = nullptr;
    cudaGetSymbolAddress(&p, s);
    return p;
}

extern "C" void kernel_launch(void* const* d_in, const int* in_sizes, int n_in,
                              void* d_out, int out_size) {
    const float* x   = (const float*)d_in[0];
    const void*  ei  = d_in[1];
    const float* W1  = (const float*)d_in[2];
    const float* b1  = (const float*)d_in[3];
    const float* W2  = (const float*)d_in[4];
    const float* b2  = (const float*)d_in[5];
    const float* W3  = (const float*)d_in[6];
    const float* b3  = (const float*)d_in[7];
    float*       out = (float*)d_out;

    __nv_bfloat16* B1h = (__nv_bfloat16*)sym(g_B1h); __nv_bfloat16* B1l = (__nv_bfloat16*)sym(g_B1l);
    __nv_bfloat16* B2h = (__nv_bfloat16*)sym(g_B2h); __nv_bfloat16* B2l = (__nv_bfloat16*)sym(g_B2l);
    __nv_bfloat16* B3h = (__nv_bfloat16*)sym(g_B3h); __nv_bfloat16* B3l = (__nv_bfloat16*)sym(g_B3l);
    __nv_bfloat16* A1h = (__nv_bfloat16*)sym(g_A1h); __nv_bfloat16* A1l = (__nv_bfloat16*)sym(g_A1l);
    __nv_bfloat16* A2h = (__nv_bfloat16*)sym(g_A2h); __nv_bfloat16* A2l = (__nv_bfloat16*)sym(g_A2l);
    __nv_bfloat16* A3h = (__nv_bfloat16*)sym(g_A3h); __nv_bfloat16* A3l = (__nv_bfloat16*)sym(g_A3l);
    float* h1 = (float*)sym(g_h1);
    float* t3 = (float*)sym(g_t3);

    const int NB_N = (N_NODES + 255) / 256;
    const int NB_E = (N_EDGES + 255) / 256;
    const int NBLK = (N_NODES + 1023) / 1024;

    const int SMEM_MMA = 2 * 4 * 128 * 40 * (int)sizeof(__nv_bfloat16);  // 81920
    cudaFuncSetAttribute(k_mma<2, 256, true,  true,  0>, cudaFuncAttributeMaxDynamicSharedMemorySize, SMEM_MMA);
    cudaFuncSetAttribute(k_mma<8, 256, true,  true,  1>, cudaFuncAttributeMaxDynamicSharedMemorySize, SMEM_MMA);
    cudaFuncSetAttribute(k_mma<8, 128, false, false, 0>, cudaFuncAttributeMaxDynamicSharedMemorySize, SMEM_MMA);

    // preprocessing
    k_detect1  <<<1, 1024>>>((const long long*)ei);
    k_init     <<<NB_N, 256>>>();
    k_convert  <<<NB_E, 256>>>(ei);
    k_scan1    <<<NBLK, 1024>>>();          // also computes dinv
    k_scan2    <<<1, 32>>>(NBLK);
    k_scan3    <<<NBLK, 1024>>>();
    k_scatter  <<<NB_E, 256>>>();
    k_prepw_all<<<(256*64 + 256*256 + 128*256 + 255) / 256, 256>>>(W1, W2, W3);

    // Layer 1
    k_agg1<<<(N_NODES * 32 + 255) / 256, 256>>>((const float2*)x, A1h, A1l);
    {
        dim3 grid(M_TILES, 2);
        k_mma<2, 256, true, true, 0><<<grid, 256, SMEM_MMA>>>(A1h, A1l, B1h, B1l, b1, h1, nullptr, nullptr);
    }

    // Layer 2
    k_agg2<<<(2 * N_NODES * 32 + 255) / 256, 256>>>((const float4*)h1, A2h, A2l);
    {
        dim3 grid(M_TILES, 2);
        k_mma<8, 256, true, true, 1><<<grid, 256, SMEM_MMA>>>(A2h, A2l, B2h, B2l, b2, nullptr, A3h, A3l);
    }

    // Layer 3
    {
        dim3 grid(M_TILES, 1);
        k_mma<8, 128, false, false, 0><<<grid, 256, SMEM_MMA>>>(A3h, A3l, B3h, B3l, nullptr, t3, nullptr, nullptr);
    }
    k_agg_out<<<(N_NODES * 32 + 255) / 256, 256>>>((const float4*)t3, out, b3);
}

// round 8
// speedup vs baseline: 2.7585x; 1.0586x over previous
#include <cuda_runtime.h>
#include <cuda_bf16.h>
#include <cuda_fp16.h>
#include <stdint.h>

#define N_NODES 100000
#define N_EDGES 1600000
#define IN_F 50
#define HID 256
#define OUT_F 121
#define M_TILES ((N_NODES + 127) / 128)   // 782

// ===================== scratch (static __device__) ==========================
__device__ int   g_flag;
__device__ int   g_row32[N_EDGES];
__device__ int   g_col32[N_EDGES];
__device__ int   g_deg[N_NODES];
__device__ float g_dinv[N_NODES];
__device__ int   g_off[N_NODES + 1];
__device__ int   g_cur[N_NODES];
__device__ int   g_csr[N_EDGES];
__device__ int   g_bsum[128];

__device__ __nv_bfloat16 g_B1h[256 * 64],  g_B1l[256 * 64];    // W1^T padded K->64
__device__ __nv_bfloat16 g_B2h[256 * 256], g_B2l[256 * 256];   // W2^T
__device__ __nv_bfloat16 g_B3h[128 * 256], g_B3l[128 * 256];   // W3^T padded N->128

__device__ __nv_bfloat16 g_A1h[(size_t)N_NODES * 64],  g_A1l[(size_t)N_NODES * 64];
__device__ __nv_bfloat16 g_A2h[(size_t)N_NODES * 256], g_A2l[(size_t)N_NODES * 256];
__device__ __nv_bfloat16 g_A3h[(size_t)N_NODES * 256], g_A3l[(size_t)N_NODES * 256];
__device__ __half g_xh [(size_t)N_NODES * 52];    // x in fp16, padded 50->52
__device__ __half g_h1h[(size_t)N_NODES * 256];   // h1 in fp16
__device__ __half g_t3h[(size_t)N_NODES * 128];   // t3 in fp16

// ===================== small PTX helpers (baseline features only) ===========
__device__ __forceinline__ uint32_t smem_u32(const void* p) {
    uint32_t a;
    asm("{ .reg .u64 t; cvta.to.shared.u64 t, %1; cvt.u32.u64 %0, t; }" : "=r"(a) : "l"(p));
    return a;
}

#define CP_ASYNC16(dst_u32, src_ptr) \
    asm volatile("cp.async.cg.shared.global [%0], [%1], 16;" :: "r"(dst_u32), "l"(src_ptr))
#define CP_COMMIT() asm volatile("cp.async.commit_group;" ::: "memory")

#define LDM_X4(R, ADDR) \
    asm volatile("ldmatrix.sync.aligned.m8n8.x4.shared.b16 {%0,%1,%2,%3}, [%4];" \
        : "=r"((R)[0]), "=r"((R)[1]), "=r"((R)[2]), "=r"((R)[3]) : "r"(ADDR))

__device__ __forceinline__ void mma16816(float* d, const uint32_t* a, const uint32_t* b) {
    asm volatile(
        "mma.sync.aligned.m16n8k16.row.col.f32.bf16.bf16.f32 "
        "{%0,%1,%2,%3}, {%4,%5,%6,%7}, {%8,%9}, {%0,%1,%2,%3};"
        : "+f"(d[0]), "+f"(d[1]), "+f"(d[2]), "+f"(d[3])
        : "r"(a[0]), "r"(a[1]), "r"(a[2]), "r"(a[3]), "r"(b[0]), "r"(b[1]));
}

// ===================== edge dtype probe (single block) ======================
__global__ void k_detect1(const long long* __restrict__ ei64) {
    __shared__ int bad;
    if (threadIdx.x == 0) bad = 0;
    __syncthreads();
    int ok = 1;
    for (int i = threadIdx.x; i < 4096; i += 1024) {
        long long v = ei64[i];
        if (v < 0 || v >= N_NODES) ok = 0;
    }
    if (!ok) atomicOr(&bad, 1);
    __syncthreads();
    if (threadIdx.x == 0) g_flag = bad;
}

__global__ void k_init() {
    int v = blockIdx.x * blockDim.x + threadIdx.x;
    if (v < N_NODES) { g_deg[v] = 1; g_cur[v] = 0; }
}

// convert + degree-count fused (k_init must run first)
__global__ void k_convert(const void* __restrict__ ei) {
    int e = blockIdx.x * blockDim.x + threadIdx.x;
    if (e >= N_EDGES) return;
    int r, c;
    if (g_flag) {
        const int* p = (const int*)ei;
        r = p[e]; c = p[N_EDGES + e];
    } else {
        const long long* p = (const long long*)ei;
        r = (int)p[e]; c = (int)p[N_EDGES + e];
    }
    g_row32[e] = r;
    g_col32[e] = c;
    atomicAdd(&g_deg[c], 1);
}

// x -> fp16 padded [N][52]
__global__ void k_prepx(const float* __restrict__ x) {
    int i = blockIdx.x * blockDim.x + threadIdx.x;
    if (i >= N_NODES * 52) return;
    int node = i / 52, c = i - node * 52;
    g_xh[i] = __float2half(c < IN_F ? x[(size_t)node * IN_F + c] : 0.f);
}

// ===================== scan (+dinv fused) ===================================
__global__ void k_scan1() {
    __shared__ int s[1024];
    int tid = threadIdx.x;
    int v = blockIdx.x * 1024 + tid;
    int d = (v < N_NODES) ? g_deg[v] : 1;
    if (v < N_NODES) g_dinv[v] = rsqrtf((float)d);
    int c = (v < N_NODES) ? (d - 1) : 0;
    s[tid] = c;
    __syncthreads();
    #pragma unroll
    for (int o = 1; o < 1024; o <<= 1) {
        int t = (tid >= o) ? s[tid - o] : 0;
        __syncthreads();
        if (tid >= o) s[tid] += t;
        __syncthreads();
    }
    if (v < N_NODES) g_off[v + 1] = s[tid];
    if (tid == 1023) g_bsum[blockIdx.x] = s[1023];
}

__global__ void k_scan2(int nblk) {
    if (threadIdx.x == 0 && blockIdx.x == 0) {
        int acc = 0;
        for (int b = 0; b < nblk; b++) { int t = g_bsum[b]; g_bsum[b] = acc; acc += t; }
    }
}

__global__ void k_scan3() {
    int tid = threadIdx.x;
    int v = blockIdx.x * 1024 + tid;
    if (v < N_NODES) g_off[v + 1] += g_bsum[blockIdx.x];
    if (v == 0) g_off[0] = 0;
}

__global__ void k_scatter() {
    int e = blockIdx.x * blockDim.x + threadIdx.x;
    if (e < N_EDGES) {
        int c = g_col32[e];
        int p = g_off[c] + atomicAdd(&g_cur[c], 1);
        g_csr[p] = g_row32[e];
    }
}

// ===================== weight prep: all three, one kernel ===================
__global__ void k_prepw_all(const float* __restrict__ W1, const float* __restrict__ W2,
                            const float* __restrict__ W3) {
    int i = blockIdx.x * 256 + threadIdx.x;
    float v;
    __nv_bfloat16 *ph, *pl;
    int idx;
    if (i < 256 * 64) {
        int n = i >> 6, k = i & 63;
        v = (k < IN_F) ? W1[(size_t)k * 256 + n] : 0.f;
        ph = g_B1h; pl = g_B1l; idx = i;
    } else if (i < 256 * 64 + 256 * 256) {
        int j = i - 256 * 64;
        int n = j >> 8, k = j & 255;
        v = W2[(size_t)k * 256 + n];
        ph = g_B2h; pl = g_B2l; idx = j;
    } else if (i < 256 * 64 + 256 * 256 + 128 * 256) {
        int j = i - 256 * 64 - 256 * 256;
        int n = j >> 8, k = j & 255;
        v = (n < OUT_F) ? W3[(size_t)k * OUT_F + n] : 0.f;
        ph = g_B3h; pl = g_B3l; idx = j;
    } else return;
    __nv_bfloat16 h = __float2bfloat16(v);
    ph[idx] = h;
    pl[idx] = __float2bfloat16(v - __bfloat162float(h));
}

// ===================== aggregation (fp16 gather, chunk-major) ===============
__device__ __forceinline__ void pair_store2(__nv_bfloat16* Oh, __nv_bfloat16* Ol,
                                            size_t off, float v0, float v1) {
    __nv_bfloat16 h0 = __float2bfloat16(v0), h1 = __float2bfloat16(v1);
    *(__nv_bfloat162*)(Oh + off) = __halves2bfloat162(h0, h1);
    *(__nv_bfloat162*)(Ol + off) = __halves2bfloat162(
        __float2bfloat16(v0 - __bfloat162float(h0)),
        __float2bfloat16(v1 - __bfloat162float(h1)));
}

// layer-1 agg: xh fp16 [N][52] (half2 lanes), out pair [N][64]
__global__ void k_agg1(__nv_bfloat16* __restrict__ Oh, __nv_bfloat16* __restrict__ Ol) {
    const __half2* X2 = (const __half2*)g_xh;   // row stride 26
    int gw = (blockIdx.x * blockDim.x + threadIdx.x) >> 5;
    int lane = threadIdx.x & 31;
    if (gw >= N_NODES) return;
    int node = gw;
    bool act = lane < 25;
    int c2 = act ? lane : 0;
    float dv = g_dinv[node];
    float2 xv = __half22float2(X2[(size_t)node * 26 + c2]);
    float ax = dv * xv.x, ay = dv * xv.y;
    int beg = g_off[node], end = g_off[node + 1];
    int j = beg;
    for (; j + 4 <= end; j += 4) {
        int u0 = g_csr[j], u1 = g_csr[j + 1], u2 = g_csr[j + 2], u3 = g_csr[j + 3];
        float d0 = g_dinv[u0], d1 = g_dinv[u1], d2 = g_dinv[u2], d3 = g_dinv[u3];
        float2 a0 = __half22float2(X2[(size_t)u0 * 26 + c2]);
        float2 a1 = __half22float2(X2[(size_t)u1 * 26 + c2]);
        float2 a2 = __half22float2(X2[(size_t)u2 * 26 + c2]);
        float2 a3 = __half22float2(X2[(size_t)u3 * 26 + c2]);
        ax += d0 * a0.x; ay += d0 * a0.y;
        ax += d1 * a1.x; ay += d1 * a1.y;
        ax += d2 * a2.x; ay += d2 * a2.y;
        ax += d3 * a3.x; ay += d3 * a3.y;
    }
    for (; j < end; j++) {
        int u = g_csr[j];
        float d = g_dinv[u];
        float2 a = __half22float2(X2[(size_t)u * 26 + c2]);
        ax += d * a.x; ay += d * a.y;
    }
    float v0 = act ? dv * ax : 0.f;
    float v1 = act ? dv * ay : 0.f;
    pair_store2(Oh, Ol, (size_t)node * 64 + lane * 2, v0, v1);
}

// layer-2 agg: h1 fp16 [N][256] (uint2 = 4 halves per lane), out pair [N][256]
__global__ void k_agg2(__nv_bfloat16* __restrict__ Oh, __nv_bfloat16* __restrict__ Ol) {
    const uint2* X4 = (const uint2*)g_h1h;      // row stride 64 uint2
    int gw = (blockIdx.x * blockDim.x + threadIdx.x) >> 5;
    int lane = threadIdx.x & 31;
    if (gw >= 2 * N_NODES) return;
    int chunk = gw >= N_NODES ? 1 : 0;          // chunk-major: 6.4MB slice L2-resident
    int node = gw - chunk * N_NODES;
    int c4 = chunk * 32 + lane;                 // uint2 column (0..63) = 4 halves
    float dv = g_dinv[node];
    uint2 raw = X4[(size_t)node * 64 + c4];
    float2 f01 = __half22float2(*(__half2*)&raw.x);
    float2 f23 = __half22float2(*(__half2*)&raw.y);
    float a0 = dv * f01.x, a1 = dv * f01.y, a2 = dv * f23.x, a3 = dv * f23.y;
    int beg = g_off[node], end = g_off[node + 1];
    int j = beg;
    for (; j + 4 <= end; j += 4) {
        int u0 = g_csr[j], u1 = g_csr[j + 1], u2 = g_csr[j + 2], u3 = g_csr[j + 3];
        float d0 = g_dinv[u0], d1 = g_dinv[u1], d2 = g_dinv[u2], d3 = g_dinv[u3];
        uint2 r0 = X4[(size_t)u0 * 64 + c4];
        uint2 r1 = X4[(size_t)u1 * 64 + c4];
        uint2 r2 = X4[(size_t)u2 * 64 + c4];
        uint2 r3 = X4[(size_t)u3 * 64 + c4];
        float2 p0a = __half22float2(*(__half2*)&r0.x), p0b = __half22float2(*(__half2*)&r0.y);
        float2 p1a = __half22float2(*(__half2*)&r1.x), p1b = __half22float2(*(__half2*)&r1.y);
        float2 p2a = __half22float2(*(__half2*)&r2.x), p2b = __half22float2(*(__half2*)&r2.y);
        float2 p3a = __half22float2(*(__half2*)&r3.x), p3b = __half22float2(*(__half2*)&r3.y);
        a0 += d0 * p0a.x; a1 += d0 * p0a.y; a2 += d0 * p0b.x; a3 += d0 * p0b.y;
        a0 += d1 * p1a.x; a1 += d1 * p1a.y; a2 += d1 * p1b.x; a3 += d1 * p1b.y;
        a0 += d2 * p2a.x; a1 += d2 * p2a.y; a2 += d2 * p2b.x; a3 += d2 * p2b.y;
        a0 += d3 * p3a.x; a1 += d3 * p3a.y; a2 += d3 * p3b.x; a3 += d3 * p3b.y;
    }
    for (; j < end; j++) {
        int u = g_csr[j];
        float d = g_dinv[u];
        uint2 r = X4[(size_t)u * 64 + c4];
        float2 pa = __half22float2(*(__half2*)&r.x), pb = __half22float2(*(__half2*)&r.y);
        a0 += d * pa.x; a1 += d * pa.y; a2 += d * pb.x; a3 += d * pb.y;
    }
    a0 *= dv; a1 *= dv; a2 *= dv; a3 *= dv;
    size_t off = (size_t)node * 256 + c4 * 4;
    pair_store2(Oh, Ol, off, a0, a1);
    pair_store2(Oh, Ol, off + 2, a2, a3);
}

// final agg: t3 fp16 [N][128] (uint2 lanes), +bias, out [N][121] fp32
__global__ void k_agg_out(float* __restrict__ OUT, const float* __restrict__ bias) {
    const uint2* X4 = (const uint2*)g_t3h;      // row stride 32 uint2
    int gw = (blockIdx.x * blockDim.x + threadIdx.x) >> 5;
    int lane = threadIdx.x & 31;
    if (gw >= N_NODES) return;
    int node = gw;
    float dv = g_dinv[node];
    uint2 raw = X4[(size_t)node * 32 + lane];
    float2 f01 = __half22float2(*(__half2*)&raw.x);
    float2 f23 = __half22float2(*(__half2*)&raw.y);
    float a0 = dv * f01.x, a1 = dv * f01.y, a2 = dv * f23.x, a3 = dv * f23.y;
    int beg = g_off[node], end = g_off[node + 1];
    int j = beg;
    for (; j + 4 <= end; j += 4) {
        int u0 = g_csr[j], u1 = g_csr[j + 1], u2 = g_csr[j + 2], u3 = g_csr[j + 3];
        float d0 = g_dinv[u0], d1 = g_dinv[u1], d2 = g_dinv[u2], d3 = g_dinv[u3];
        uint2 r0 = X4[(size_t)u0 * 32 + lane];
        uint2 r1 = X4[(size_t)u1 * 32 + lane];
        uint2 r2 = X4[(size_t)u2 * 32 + lane];
        uint2 r3 = X4[(size_t)u3 * 32 + lane];
        float2 p0a = __half22float2(*(__half2*)&r0.x), p0b = __half22float2(*(__half2*)&r0.y);
        float2 p1a = __half22float2(*(__half2*)&r1.x), p1b = __half22float2(*(__half2*)&r1.y);
        float2 p2a = __half22float2(*(__half2*)&r2.x), p2b = __half22float2(*(__half2*)&r2.y);
        float2 p3a = __half22float2(*(__half2*)&r3.x), p3b = __half22float2(*(__half2*)&r3.y);
        a0 += d0 * p0a.x; a1 += d0 * p0a.y; a2 += d0 * p0b.x; a3 += d0 * p0b.y;
        a0 += d1 * p1a.x; a1 += d1 * p1a.y; a2 += d1 * p1b.x; a3 += d1 * p1b.y;
        a0 += d2 * p2a.x; a1 += d2 * p2a.y; a2 += d2 * p2b.x; a3 += d2 * p2b.y;
        a0 += d3 * p3a.x; a1 += d3 * p3a.y; a2 += d3 * p3b.x; a3 += d3 * p3b.y;
    }
    for (; j < end; j++) {
        int u = g_csr[j];
        float d = g_dinv[u];
        uint2 r = X4[(size_t)u * 32 + lane];
        float2 pa = __half22float2(*(__half2*)&r.x), pb = __half22float2(*(__half2*)&r.y);
        a0 += d * pa.x; a1 += d * pa.y; a2 += d * pb.x; a3 += d * pb.y;
    }
    int c = lane * 4;
    float* dst = OUT + (size_t)node * OUT_F;
    if (c + 0 < OUT_F) dst[c + 0] = dv * a0 + bias[c + 0];
    if (c + 1 < OUT_F) dst[c + 1] = dv * a1 + bias[c + 1];
    if (c + 2 < OUT_F) dst[c + 2] = dv * a2 + bias[c + 2];
    if (c + 3 < OUT_F) dst[c + 3] = dv * a3 + bias[c + 3];
}

// ===================== warp-MMA GEMM (2-stage cp.async + ldmatrix) ==========
// OMODE 0: fp32 C.  OMODE 1: bf16 hi/lo pair C.  OMODE 2: fp16 C.
template<int KT, int NNTOT, bool BIAS, bool RELU, int OMODE>
__global__ void __launch_bounds__(256, 2)
k_mma(const __nv_bfloat16* __restrict__ Ah, const __nv_bfloat16* __restrict__ Al,
      const __nv_bfloat16* __restrict__ Bh, const __nv_bfloat16* __restrict__ Bl,
      const float* __restrict__ bias,
      float* __restrict__ Cf, __nv_bfloat16* __restrict__ Ch, __nv_bfloat16* __restrict__ Cl,
      __half* __restrict__ Cx) {
    constexpr int ASTR = KT * 32;
    constexpr int PAD = 40;
    constexpr int ST = 128 * PAD;
    extern __shared__ __nv_bfloat16 dsm[];

    const int tid = threadIdx.x;
    const int wid = tid >> 5, lane = tid & 31;
    const int wm = wid & 3, wn = wid >> 2;
    const int m0 = blockIdx.x * 128;
    const int n0 = blockIdx.y * 128;

    float acc[2][8][4];
    #pragma unroll
    for (int mt = 0; mt < 2; mt++)
        #pragma unroll
        for (int nt = 0; nt < 8; nt++)
            #pragma unroll
            for (int q = 0; q < 4; q++) acc[mt][nt][q] = 0.f;

    auto stage = [&](int s, int c) {
        __nv_bfloat16* base = dsm + s * 4 * ST;
        #pragma unroll
        for (int it = 0; it < 2; it++) {
            int idx = it * 256 + tid;
            int row = idx >> 2, chk = idx & 3;
            int m = m0 + row; if (m >= N_NODES) m = N_NODES - 1;
            size_t goA = (size_t)m * ASTR + c * 32 + chk * 8;
            size_t goB = (size_t)(n0 + row) * ASTR + c * 32 + chk * 8;
            int so = row * PAD + chk * 8;
            CP_ASYNC16(smem_u32(base + 0 * ST + so), Ah + goA);
            CP_ASYNC16(smem_u32(base + 1 * ST + so), Al + goA);
            CP_ASYNC16(smem_u32(base + 2 * ST + so), Bh + goB);
            CP_ASYNC16(smem_u32(base + 3 * ST + so), Bl + goB);
        }
        CP_COMMIT();
    };

    stage(0, 0);
    for (int c = 0; c < KT; c++) {
        if (c + 1 < KT) {
            stage((c + 1) & 1, c + 1);
            asm volatile("cp.async.wait_group 1;" ::: "memory");
        } else {
            asm volatile("cp.async.wait_group 0;" ::: "memory");
        }
        __syncthreads();

        const __nv_bfloat16* Sb = dsm + (c & 1) * 4 * ST;
        const __nv_bfloat16* sAh = Sb;
        const __nv_bfloat16* sAl = Sb + ST;
        const __nv_bfloat16* sBh = Sb + 2 * ST;
        const __nv_bfloat16* sBl = Sb + 3 * ST;

        #pragma unroll
        for (int ks = 0; ks < 2; ks++) {
            const int kc = ks * 16;
            uint32_t a_h[2][4], a_l[2][4];
            #pragma unroll
            for (int mt = 0; mt < 2; mt++) {
                int r = wm * 32 + mt * 16 + (lane & 15);
                int cA = kc + ((lane >> 4) << 3);
                LDM_X4(a_h[mt], smem_u32(sAh + r * PAD + cA));
                LDM_X4(a_l[mt], smem_u32(sAl + r * PAD + cA));
            }
            #pragma unroll
            for (int ntp = 0; ntp < 4; ntp++) {
                int br = wn * 64 + ntp * 16 + (lane & 7) + ((lane & 16) ? 8 : 0);
                int cB = kc + ((lane & 8) ? 8 : 0);
                uint32_t b_h[4], b_l[4];
                LDM_X4(b_h, smem_u32(sBh + br * PAD + cB));
                LDM_X4(b_l, smem_u32(sBl + br * PAD + cB));
                #pragma unroll
                for (int half = 0; half < 2; half++) {
                    int nt = ntp * 2 + half;
                    #pragma unroll
                    for (int mt = 0; mt < 2; mt++) {
                        mma16816(acc[mt][nt], a_h[mt], b_h + 2 * half);
                        mma16816(acc[mt][nt], a_h[mt], b_l + 2 * half);
                        mma16816(acc[mt][nt], a_l[mt], b_h + 2 * half);
                    }
                }
            }
        }
        __syncthreads();
    }

    #pragma unroll
    for (int mt = 0; mt < 2; mt++) {
        int mrow = m0 + wm * 32 + mt * 16 + (lane >> 2);
        #pragma unroll
        for (int nt = 0; nt < 8; nt++) {
            int n = n0 + wn * 64 + nt * 8 + (lane & 3) * 2;
            float v0 = acc[mt][nt][0], v1 = acc[mt][nt][1];
            float v2 = acc[mt][nt][2], v3 = acc[mt][nt][3];
            if (BIAS) {
                float bb0 = bias[n], bb1 = bias[n + 1];
                v0 += bb0; v1 += bb1; v2 += bb0; v3 += bb1;
            }
            if (RELU) {
                v0 = fmaxf(v0, 0.f); v1 = fmaxf(v1, 0.f);
                v2 = fmaxf(v2, 0.f); v3 = fmaxf(v3, 0.f);
            }
            if (OMODE == 0) {
                if (mrow < N_NODES)
                    *(float2*)(Cf + (size_t)mrow * NNTOT + n) = make_float2(v0, v1);
                if (mrow + 8 < N_NODES)
                    *(float2*)(Cf + (size_t)(mrow + 8) * NNTOT + n) = make_float2(v2, v3);
            } else if (OMODE == 1) {
                if (mrow < N_NODES)
                    pair_store2(Ch, Cl, (size_t)mrow * NNTOT + n, v0, v1);
                if (mrow + 8 < N_NODES)
                    pair_store2(Ch, Cl, (size_t)(mrow + 8) * NNTOT + n, v2, v3);
            } else {
                if (mrow < N_NODES)
                    *(__half2*)(Cx + (size_t)mrow * NNTOT + n) = __floats2half2_rn(v0, v1);
                if (mrow + 8 < N_NODES)
                    *(__half2*)(Cx + (size_t)(mrow + 8) * NNTOT + n) = __floats2half2_rn(v2, v3);
            }
        }
    }
}

// ===================== launch ===============================================
static inline void* sym(const void* s) {
    void* p = nullptr;
    cudaGetSymbolAddress(&p, s);
    return p;
}

extern "C" void kernel_launch(void* const* d_in, const int* in_sizes, int n_in,
                              void* d_out, int out_size) {
    const float* x   = (const float*)d_in[0];
    const void*  ei  = d_in[1];
    const float* W1  = (const float*)d_in[2];
    const float* b1  = (const float*)d_in[3];
    const float* W2  = (const float*)d_in[4];
    const float* b2  = (const float*)d_in[5];
    const float* W3  = (const float*)d_in[6];
    const float* b3  = (const float*)d_in[7];
    float*       out = (float*)d_out;

    __nv_bfloat16* B1h = (__nv_bfloat16*)sym(g_B1h); __nv_bfloat16* B1l = (__nv_bfloat16*)sym(g_B1l);
    __nv_bfloat16* B2h = (__nv_bfloat16*)sym(g_B2h); __nv_bfloat16* B2l = (__nv_bfloat16*)sym(g_B2l);
    __nv_bfloat16* B3h = (__nv_bfloat16*)sym(g_B3h); __nv_bfloat16* B3l = (__nv_bfloat16*)sym(g_B3l);
    __nv_bfloat16* A1h = (__nv_bfloat16*)sym(g_A1h); __nv_bfloat16* A1l = (__nv_bfloat16*)sym(g_A1l);
    __nv_bfloat16* A2h = (__nv_bfloat16*)sym(g_A2h); __nv_bfloat16* A2l = (__nv_bfloat16*)sym(g_A2l);
    __nv_bfloat16* A3h = (__nv_bfloat16*)sym(g_A3h); __nv_bfloat16* A3l = (__nv_bfloat16*)sym(g_A3l);
    __half* h1h = (__half*)sym(g_h1h);
    __half* t3h = (__half*)sym(g_t3h);

    const int NB_N = (N_NODES + 255) / 256;
    const int NB_E = (N_EDGES + 255) / 256;
    const int NBLK = (N_NODES + 1023) / 1024;

    const int SMEM_MMA = 2 * 4 * 128 * 40 * (int)sizeof(__nv_bfloat16);  // 81920
    cudaFuncSetAttribute(k_mma<2, 256, true,  true,  2>, cudaFuncAttributeMaxDynamicSharedMemorySize, SMEM_MMA);
    cudaFuncSetAttribute(k_mma<8, 256, true,  true,  1>, cudaFuncAttributeMaxDynamicSharedMemorySize, SMEM_MMA);
    cudaFuncSetAttribute(k_mma<8, 128, false, false, 2>, cudaFuncAttributeMaxDynamicSharedMemorySize, SMEM_MMA);

    // preprocessing
    k_detect1  <<<1, 1024>>>((const long long*)ei);
    k_init     <<<NB_N, 256>>>();
    k_convert  <<<NB_E, 256>>>(ei);
    k_prepx    <<<(N_NODES * 52 + 255) / 256, 256>>>(x);
    k_scan1    <<<NBLK, 1024>>>();          // also computes dinv
    k_scan2    <<<1, 32>>>(NBLK);
    k_scan3    <<<NBLK, 1024>>>();
    k_scatter  <<<NB_E, 256>>>();
    k_prepw_all<<<(256*64 + 256*256 + 128*256 + 255) / 256, 256>>>(W1, W2, W3);

    // Layer 1: agg(xh) -> A1 pair; GEMM -> h1 fp16 (+b1, relu)
    k_agg1<<<(N_NODES * 32 + 255) / 256, 256>>>(A1h, A1l);
    {
        dim3 grid(M_TILES, 2);
        k_mma<2, 256, true, true, 2><<<grid, 256, SMEM_MMA>>>(
            A1h, A1l, B1h, B1l, b1, nullptr, nullptr, nullptr, h1h);
    }

    // Layer 2: agg(h1 fp16) -> A2 pair; GEMM -> A3 pair (+b2, relu)
    k_agg2<<<(2 * N_NODES * 32 + 255) / 256, 256>>>(A2h, A2l);
    {
        dim3 grid(M_TILES, 2);
        k_mma<8, 256, true, true, 1><<<grid, 256, SMEM_MMA>>>(
            A2h, A2l, B2h, B2l, b2, nullptr, A3h, A3l, nullptr);
    }

    // Layer 3: GEMM -> t3 fp16; agg(t3)+b3 -> out fp32
    {
        dim3 grid(M_TILES, 1);
        k_mma<8, 128, false, false, 2><<<grid, 256, SMEM_MMA>>>(
            A3h, A3l, B3h, B3l, nullptr, nullptr, nullptr, nullptr, t3h);
    }
    k_agg_out<<<(N_NODES * 32 + 255) / 256, 256>>>(out, b3);
}

// round 9
// speedup vs baseline: 3.7207x; 1.3488x over previous
#include <cuda_runtime.h>
#include <cuda_fp16.h>
#include <stdint.h>

#define N_NODES 100000
#define N_EDGES 1600000
#define IN_F 50
#define HID 256
#define OUT_F 121
#define M_TILES ((N_NODES + 127) / 128)   // 782

// ===================== scratch (static __device__) ==========================
__device__ int   g_flag;
__device__ int   g_row32[N_EDGES];
__device__ int   g_col32[N_EDGES];
__device__ int   g_deg[N_NODES];
__device__ float g_dinv[N_NODES];
__device__ int   g_off[N_NODES + 1];
__device__ int   g_cur[N_NODES];
__device__ int   g_csr[N_EDGES];
__device__ int   g_bsum[128];

__device__ __half g_W1[256 * 64];     // W1^T padded K->64  [n][k]
__device__ __half g_W2[256 * 256];    // W2^T
__device__ __half g_W3[128 * 256];    // W3^T padded N->128

__device__ __half g_A1[(size_t)N_NODES * 64];    // agg1 out (GEMM1 A)
__device__ __half g_A2[(size_t)N_NODES * 256];   // agg2 out (GEMM2 A)
__device__ __half g_A3[(size_t)N_NODES * 256];   // relu(GEMM2 out) (GEMM3 A)
__device__ __half g_xh [(size_t)N_NODES * 52];   // x fp16, padded 50->52
__device__ __half g_h1h[(size_t)N_NODES * 256];  // h1 fp16 (agg2 gather input)
__device__ __half g_t3h[(size_t)N_NODES * 128];  // t3 fp16 (agg_out gather input)

// ===================== small PTX helpers (baseline features only) ===========
__device__ __forceinline__ uint32_t smem_u32(const void* p) {
    uint32_t a;
    asm("{ .reg .u64 t; cvta.to.shared.u64 t, %1; cvt.u32.u64 %0, t; }" : "=r"(a) : "l"(p));
    return a;
}

#define CP_ASYNC16(dst_u32, src_ptr) \
    asm volatile("cp.async.cg.shared.global [%0], [%1], 16;" :: "r"(dst_u32), "l"(src_ptr))
#define CP_COMMIT() asm volatile("cp.async.commit_group;" ::: "memory")

#define LDM_X4(R, ADDR) \
    asm volatile("ldmatrix.sync.aligned.m8n8.x4.shared.b16 {%0,%1,%2,%3}, [%4];" \
        : "=r"((R)[0]), "=r"((R)[1]), "=r"((R)[2]), "=r"((R)[3]) : "r"(ADDR))

__device__ __forceinline__ void mma16816h(float* d, const uint32_t* a, const uint32_t* b) {
    asm volatile(
        "mma.sync.aligned.m16n8k16.row.col.f32.f16.f16.f32 "
        "{%0,%1,%2,%3}, {%4,%5,%6,%7}, {%8,%9}, {%0,%1,%2,%3};"
        : "+f"(d[0]), "+f"(d[1]), "+f"(d[2]), "+f"(d[3])
        : "r"(a[0]), "r"(a[1]), "r"(a[2]), "r"(a[3]), "r"(b[0]), "r"(b[1]));
}

// ===================== edge dtype probe (single block) ======================
__global__ void k_detect1(const long long* __restrict__ ei64) {
    __shared__ int bad;
    if (threadIdx.x == 0) bad = 0;
    __syncthreads();
    int ok = 1;
    for (int i = threadIdx.x; i < 4096; i += 1024) {
        long long v = ei64[i];
        if (v < 0 || v >= N_NODES) ok = 0;
    }
    if (!ok) atomicOr(&bad, 1);
    __syncthreads();
    if (threadIdx.x == 0) g_flag = bad;
}

__global__ void k_init() {
    int v = blockIdx.x * blockDim.x + threadIdx.x;
    if (v < N_NODES) { g_deg[v] = 1; g_cur[v] = 0; }
}

// convert + degree-count fused (k_init must run first)
__global__ void k_convert(const void* __restrict__ ei) {
    int e = blockIdx.x * blockDim.x + threadIdx.x;
    if (e >= N_EDGES) return;
    int r, c;
    if (g_flag) {
        const int* p = (const int*)ei;
        r = p[e]; c = p[N_EDGES + e];
    } else {
        const long long* p = (const long long*)ei;
        r = (int)p[e]; c = (int)p[N_EDGES + e];
    }
    g_row32[e] = r;
    g_col32[e] = c;
    atomicAdd(&g_deg[c], 1);
}

// x -> fp16 padded [N][52]
__global__ void k_prepx(const float* __restrict__ x) {
    int i = blockIdx.x * blockDim.x + threadIdx.x;
    if (i >= N_NODES * 52) return;
    int node = i / 52, c = i - node * 52;
    g_xh[i] = __float2half(c < IN_F ? x[(size_t)node * IN_F + c] : 0.f);
}

// ===================== scan (+dinv fused) ===================================
__global__ void k_scan1() {
    __shared__ int s[1024];
    int tid = threadIdx.x;
    int v = blockIdx.x * 1024 + tid;
    int d = (v < N_NODES) ? g_deg[v] : 1;
    if (v < N_NODES) g_dinv[v] = rsqrtf((float)d);
    int c = (v < N_NODES) ? (d - 1) : 0;
    s[tid] = c;
    __syncthreads();
    #pragma unroll
    for (int o = 1; o < 1024; o <<= 1) {
        int t = (tid >= o) ? s[tid - o] : 0;
        __syncthreads();
        if (tid >= o) s[tid] += t;
        __syncthreads();
    }
    if (v < N_NODES) g_off[v + 1] = s[tid];
    if (tid == 1023) g_bsum[blockIdx.x] = s[1023];
}

__global__ void k_scan2(int nblk) {
    if (threadIdx.x == 0 && blockIdx.x == 0) {
        int acc = 0;
        for (int b = 0; b < nblk; b++) { int t = g_bsum[b]; g_bsum[b] = acc; acc += t; }
    }
}

__global__ void k_scan3() {
    int tid = threadIdx.x;
    int v = blockIdx.x * 1024 + tid;
    if (v < N_NODES) g_off[v + 1] += g_bsum[blockIdx.x];
    if (v == 0) g_off[0] = 0;
}

__global__ void k_scatter() {
    int e = blockIdx.x * blockDim.x + threadIdx.x;
    if (e < N_EDGES) {
        int c = g_col32[e];
        int p = g_off[c] + atomicAdd(&g_cur[c], 1);
        g_csr[p] = g_row32[e];
    }
}

// ===================== weight prep: fp16, transposed, padded ================
__global__ void k_prepw_all(const float* __restrict__ W1, const float* __restrict__ W2,
                            const float* __restrict__ W3) {
    int i = blockIdx.x * 256 + threadIdx.x;
    if (i < 256 * 64) {
        int n = i >> 6, k = i & 63;
        g_W1[i] = __float2half((k < IN_F) ? W1[(size_t)k * 256 + n] : 0.f);
    } else if (i < 256 * 64 + 256 * 256) {
        int j = i - 256 * 64;
        int n = j >> 8, k = j & 255;
        g_W2[j] = __float2half(W2[(size_t)k * 256 + n]);
    } else if (i < 256 * 64 + 256 * 256 + 128 * 256) {
        int j = i - 256 * 64 - 256 * 256;
        int n = j >> 8, k = j & 255;
        g_W3[j] = __float2half((n < OUT_F) ? W3[(size_t)k * OUT_F + n] : 0.f);
    }
}

// ===================== aggregation (fp16 gather + fp16 out) =================
// layer-1 agg: xh fp16 [N][52] (half2 lanes), out fp16 [N][64]
__global__ void k_agg1() {
    const __half2* X2 = (const __half2*)g_xh;   // row stride 26
    int gw = (blockIdx.x * blockDim.x + threadIdx.x) >> 5;
    int lane = threadIdx.x & 31;
    if (gw >= N_NODES) return;
    int node = gw;
    bool act = lane < 25;
    int c2 = act ? lane : 0;
    float dv = g_dinv[node];
    float2 xv = __half22float2(X2[(size_t)node * 26 + c2]);
    float ax = dv * xv.x, ay = dv * xv.y;
    int beg = g_off[node], end = g_off[node + 1];
    int j = beg;
    for (; j + 4 <= end; j += 4) {
        int u0 = g_csr[j], u1 = g_csr[j + 1], u2 = g_csr[j + 2], u3 = g_csr[j + 3];
        float d0 = g_dinv[u0], d1 = g_dinv[u1], d2 = g_dinv[u2], d3 = g_dinv[u3];
        float2 a0 = __half22float2(X2[(size_t)u0 * 26 + c2]);
        float2 a1 = __half22float2(X2[(size_t)u1 * 26 + c2]);
        float2 a2 = __half22float2(X2[(size_t)u2 * 26 + c2]);
        float2 a3 = __half22float2(X2[(size_t)u3 * 26 + c2]);
        ax += d0 * a0.x; ay += d0 * a0.y;
        ax += d1 * a1.x; ay += d1 * a1.y;
        ax += d2 * a2.x; ay += d2 * a2.y;
        ax += d3 * a3.x; ay += d3 * a3.y;
    }
    for (; j < end; j++) {
        int u = g_csr[j];
        float d = g_dinv[u];
        float2 a = __half22float2(X2[(size_t)u * 26 + c2]);
        ax += d * a.x; ay += d * a.y;
    }
    float v0 = act ? dv * ax : 0.f;
    float v1 = act ? dv * ay : 0.f;
    *(__half2*)(g_A1 + (size_t)node * 64 + lane * 2) = __floats2half2_rn(v0, v1);
}

// layer-2 agg: h1 fp16 [N][256] (uint2 lanes = 4 halves), out fp16 [N][256]
__global__ void k_agg2() {
    const uint2* X4 = (const uint2*)g_h1h;      // row stride 64 uint2
    int gw = (blockIdx.x * blockDim.x + threadIdx.x) >> 5;
    int lane = threadIdx.x & 31;
    if (gw >= 2 * N_NODES) return;
    int chunk = gw >= N_NODES ? 1 : 0;          // chunk-major: 6.4MB slice L2-resident
    int node = gw - chunk * N_NODES;
    int c4 = chunk * 32 + lane;
    float dv = g_dinv[node];
    uint2 raw = X4[(size_t)node * 64 + c4];
    float2 f01 = __half22float2(*(__half2*)&raw.x);
    float2 f23 = __half22float2(*(__half2*)&raw.y);
    float a0 = dv * f01.x, a1 = dv * f01.y, a2 = dv * f23.x, a3 = dv * f23.y;
    int beg = g_off[node], end = g_off[node + 1];
    int j = beg;
    for (; j + 4 <= end; j += 4) {
        int u0 = g_csr[j], u1 = g_csr[j + 1], u2 = g_csr[j + 2], u3 = g_csr[j + 3];
        float d0 = g_dinv[u0], d1 = g_dinv[u1], d2 = g_dinv[u2], d3 = g_dinv[u3];
        uint2 r0 = X4[(size_t)u0 * 64 + c4];
        uint2 r1 = X4[(size_t)u1 * 64 + c4];
        uint2 r2 = X4[(size_t)u2 * 64 + c4];
        uint2 r3 = X4[(size_t)u3 * 64 + c4];
        float2 p0a = __half22float2(*(__half2*)&r0.x), p0b = __half22float2(*(__half2*)&r0.y);
        float2 p1a = __half22float2(*(__half2*)&r1.x), p1b = __half22float2(*(__half2*)&r1.y);
        float2 p2a = __half22float2(*(__half2*)&r2.x), p2b = __half22float2(*(__half2*)&r2.y);
        float2 p3a = __half22float2(*(__half2*)&r3.x), p3b = __half22float2(*(__half2*)&r3.y);
        a0 += d0 * p0a.x; a1 += d0 * p0a.y; a2 += d0 * p0b.x; a3 += d0 * p0b.y;
        a0 += d1 * p1a.x; a1 += d1 * p1a.y; a2 += d1 * p1b.x; a3 += d1 * p1b.y;
        a0 += d2 * p2a.x; a1 += d2 * p2a.y; a2 += d2 * p2b.x; a3 += d2 * p2b.y;
        a0 += d3 * p3a.x; a1 += d3 * p3a.y; a2 += d3 * p3b.x; a3 += d3 * p3b.y;
    }
    for (; j < end; j++) {
        int u = g_csr[j];
        float d = g_dinv[u];
        uint2 r = X4[(size_t)u * 64 + c4];
        float2 pa = __half22float2(*(__half2*)&r.x), pb = __half22float2(*(__half2*)&r.y);
        a0 += d * pa.x; a1 += d * pa.y; a2 += d * pb.x; a3 += d * pb.y;
    }
    a0 *= dv; a1 *= dv; a2 *= dv; a3 *= dv;
    uint2 outv;
    *(__half2*)&outv.x = __floats2half2_rn(a0, a1);
    *(__half2*)&outv.y = __floats2half2_rn(a2, a3);
    *(uint2*)(g_A2 + (size_t)node * 256 + c4 * 4) = outv;
}

// final agg: t3 fp16 [N][128] (uint2 lanes), +bias, out [N][121] fp32
__global__ void k_agg_out(float* __restrict__ OUT, const float* __restrict__ bias) {
    const uint2* X4 = (const uint2*)g_t3h;      // row stride 32 uint2
    int gw = (blockIdx.x * blockDim.x + threadIdx.x) >> 5;
    int lane = threadIdx.x & 31;
    if (gw >= N_NODES) return;
    int node = gw;
    float dv = g_dinv[node];
    uint2 raw = X4[(size_t)node * 32 + lane];
    float2 f01 = __half22float2(*(__half2*)&raw.x);
    float2 f23 = __half22float2(*(__half2*)&raw.y);
    float a0 = dv * f01.x, a1 = dv * f01.y, a2 = dv * f23.x, a3 = dv * f23.y;
    int beg = g_off[node], end = g_off[node + 1];
    int j = beg;
    for (; j + 4 <= end; j += 4) {
        int u0 = g_csr[j], u1 = g_csr[j + 1], u2 = g_csr[j + 2], u3 = g_csr[j + 3];
        float d0 = g_dinv[u0], d1 = g_dinv[u1], d2 = g_dinv[u2], d3 = g_dinv[u3];
        uint2 r0 = X4[(size_t)u0 * 32 + lane];
        uint2 r1 = X4[(size_t)u1 * 32 + lane];
        uint2 r2 = X4[(size_t)u2 * 32 + lane];
        uint2 r3 = X4[(size_t)u3 * 32 + lane];
        float2 p0a = __half22float2(*(__half2*)&r0.x), p0b = __half22float2(*(__half2*)&r0.y);
        float2 p1a = __half22float2(*(__half2*)&r1.x), p1b = __half22float2(*(__half2*)&r1.y);
        float2 p2a = __half22float2(*(__half2*)&r2.x), p2b = __half22float2(*(__half2*)&r2.y);
        float2 p3a = __half22float2(*(__half2*)&r3.x), p3b = __half22float2(*(__half2*)&r3.y);
        a0 += d0 * p0a.x; a1 += d0 * p0a.y; a2 += d0 * p0b.x; a3 += d0 * p0b.y;
        a0 += d1 * p1a.x; a1 += d1 * p1a.y; a2 += d1 * p1b.x; a3 += d1 * p1b.y;
        a0 += d2 * p2a.x; a1 += d2 * p2a.y; a2 += d2 * p2b.x; a3 += d2 * p2b.y;
        a0 += d3 * p3a.x; a1 += d3 * p3a.y; a2 += d3 * p3b.x; a3 += d3 * p3b.y;
    }
    for (; j < end; j++) {
        int u = g_csr[j];
        float d = g_dinv[u];
        uint2 r = X4[(size_t)u * 32 + lane];
        float2 pa = __half22float2(*(__half2*)&r.x), pb = __half22float2(*(__half2*)&r.y);
        a0 += d * pa.x; a1 += d * pa.y; a2 += d * pb.x; a3 += d * pb.y;
    }
    int c = lane * 4;
    float* dst = OUT + (size_t)node * OUT_F;
    if (c + 0 < OUT_F) dst[c + 0] = dv * a0 + bias[c + 0];
    if (c + 1 < OUT_F) dst[c + 1] = dv * a1 + bias[c + 1];
    if (c + 2 < OUT_F) dst[c + 2] = dv * a2 + bias[c + 2];
    if (c + 3 < OUT_F) dst[c + 3] = dv * a3 + bias[c + 3];
}

// ===================== warp-MMA GEMM (fp16 single-pass, 2-stage cp.async) ===
// C[M, NNTOT] (+bias,relu) = A[M, KT*32] @ B[NNTOT, KT*32]^T, fp32 accum.
// Block 128x128xBK=32, 8 warps (4M x 2N), warp tile 32x64. Output fp16.
template<int KT, int NNTOT, bool BIAS, bool RELU>
__global__ void __launch_bounds__(256, 2)
k_mma(const __half* __restrict__ A, const __half* __restrict__ B,
      const float* __restrict__ bias, __half* __restrict__ C) {
    constexpr int ASTR = KT * 32;
    constexpr int PAD = 40;
    constexpr int ST = 128 * PAD;
    extern __shared__ __half dsm[];

    const int tid = threadIdx.x;
    const int wid = tid >> 5, lane = tid & 31;
    const int wm = wid & 3, wn = wid >> 2;
    const int m0 = blockIdx.x * 128;
    const int n0 = blockIdx.y * 128;

    float acc[2][8][4];
    #pragma unroll
    for (int mt = 0; mt < 2; mt++)
        #pragma unroll
        for (int nt = 0; nt < 8; nt++)
            #pragma unroll
            for (int q = 0; q < 4; q++) acc[mt][nt][q] = 0.f;

    auto stage = [&](int s, int c) {
        __half* base = dsm + s * 2 * ST;
        #pragma unroll
        for (int it = 0; it < 2; it++) {
            int idx = it * 256 + tid;
            int row = idx >> 2, chk = idx & 3;
            int m = m0 + row; if (m >= N_NODES) m = N_NODES - 1;
            size_t goA = (size_t)m * ASTR + c * 32 + chk * 8;
            size_t goB = (size_t)(n0 + row) * ASTR + c * 32 + chk * 8;
            int so = row * PAD + chk * 8;
            CP_ASYNC16(smem_u32(base + so), A + goA);
            CP_ASYNC16(smem_u32(base + ST + so), B + goB);
        }
        CP_COMMIT();
    };

    stage(0, 0);
    for (int c = 0; c < KT; c++) {
        if (c + 1 < KT) {
            stage((c + 1) & 1, c + 1);
            asm volatile("cp.async.wait_group 1;" ::: "memory");
        } else {
            asm volatile("cp.async.wait_group 0;" ::: "memory");
        }
        __syncthreads();

        const __half* sA = dsm + (c & 1) * 2 * ST;
        const __half* sB = sA + ST;

        #pragma unroll
        for (int ks = 0; ks < 2; ks++) {
            const int kc = ks * 16;
            uint32_t a_f[2][4];
            #pragma unroll
            for (int mt = 0; mt < 2; mt++) {
                int r = wm * 32 + mt * 16 + (lane & 15);
                int cA = kc + ((lane >> 4) << 3);
                LDM_X4(a_f[mt], smem_u32(sA + r * PAD + cA));
            }
            #pragma unroll
            for (int ntp = 0; ntp < 4; ntp++) {
                int br = wn * 64 + ntp * 16 + (lane & 7) + ((lane & 16) ? 8 : 0);
                int cB = kc + ((lane & 8) ? 8 : 0);
                uint32_t b_f[4];
                LDM_X4(b_f, smem_u32(sB + br * PAD + cB));
                #pragma unroll
                for (int half = 0; half < 2; half++) {
                    int nt = ntp * 2 + half;
                    #pragma unroll
                    for (int mt = 0; mt < 2; mt++)
                        mma16816h(acc[mt][nt], a_f[mt], b_f + 2 * half);
                }
            }
        }
        __syncthreads();
    }

    #pragma unroll
    for (int mt = 0; mt < 2; mt++) {
        int mrow = m0 + wm * 32 + mt * 16 + (lane >> 2);
        #pragma unroll
        for (int nt = 0; nt < 8; nt++) {
            int n = n0 + wn * 64 + nt * 8 + (lane & 3) * 2;
            float v0 = acc[mt][nt][0], v1 = acc[mt][nt][1];
            float v2 = acc[mt][nt][2], v3 = acc[mt][nt][3];
            if (BIAS) {
                float bb0 = bias[n], bb1 = bias[n + 1];
                v0 += bb0; v1 += bb1; v2 += bb0; v3 += bb1;
            }
            if (RELU) {
                v0 = fmaxf(v0, 0.f); v1 = fmaxf(v1, 0.f);
                v2 = fmaxf(v2, 0.f); v3 = fmaxf(v3, 0.f);
            }
            if (mrow < N_NODES)
                *(__half2*)(C + (size_t)mrow * NNTOT + n) = __floats2half2_rn(v0, v1);
            if (mrow + 8 < N_NODES)
                *(__half2*)(C + (size_t)(mrow + 8) * NNTOT + n) = __floats2half2_rn(v2, v3);
        }
    }
}

// ===================== launch ===============================================
static inline void* sym(const void* s) {
    void* p = nullptr;
    cudaGetSymbolAddress(&p, s);
    return p;
}

extern "C" void kernel_launch(void* const* d_in, const int* in_sizes, int n_in,
                              void* d_out, int out_size) {
    const float* x   = (const float*)d_in[0];
    const void*  ei  = d_in[1];
    const float* W1  = (const float*)d_in[2];
    const float* b1  = (const float*)d_in[3];
    const float* W2  = (const float*)d_in[4];
    const float* b2  = (const float*)d_in[5];
    const float* W3  = (const float*)d_in[6];
    const float* b3  = (const float*)d_in[7];
    float*       out = (float*)d_out;

    __half* pW1 = (__half*)sym(g_W1);
    __half* pW2 = (__half*)sym(g_W2);
    __half* pW3 = (__half*)sym(g_W3);
    __half* A1  = (__half*)sym(g_A1);
    __half* A2  = (__half*)sym(g_A2);
    __half* A3  = (__half*)sym(g_A3);
    __half* h1h = (__half*)sym(g_h1h);
    __half* t3h = (__half*)sym(g_t3h);

    const int NB_N = (N_NODES + 255) / 256;
    const int NB_E = (N_EDGES + 255) / 256;
    const int NBLK = (N_NODES + 1023) / 1024;

    const int SMEM_MMA = 2 * 2 * 128 * 40 * (int)sizeof(__half);  // 40960
    cudaFuncSetAttribute(k_mma<2, 256, true,  true >, cudaFuncAttributeMaxDynamicSharedMemorySize, SMEM_MMA);
    cudaFuncSetAttribute(k_mma<8, 256, true,  true >, cudaFuncAttributeMaxDynamicSharedMemorySize, SMEM_MMA);
    cudaFuncSetAttribute(k_mma<8, 128, false, false>, cudaFuncAttributeMaxDynamicSharedMemorySize, SMEM_MMA);

    // preprocessing
    k_detect1  <<<1, 1024>>>((const long long*)ei);
    k_init     <<<NB_N, 256>>>();
    k_convert  <<<NB_E, 256>>>(ei);
    k_prepx    <<<(N_NODES * 52 + 255) / 256, 256>>>(x);
    k_scan1    <<<NBLK, 1024>>>();          // also computes dinv
    k_scan2    <<<1, 32>>>(NBLK);
    k_scan3    <<<NBLK, 1024>>>();
    k_scatter  <<<NB_E, 256>>>();
    k_prepw_all<<<(256*64 + 256*256 + 128*256 + 255) / 256, 256>>>(W1, W2, W3);

    // Layer 1: agg(xh) -> A1; GEMM -> h1 fp16 (+b1, relu)
    k_agg1<<<(N_NODES * 32 + 255) / 256, 256>>>();
    {
        dim3 grid(M_TILES, 2);
        k_mma<2, 256, true, true><<<grid, 256, SMEM_MMA>>>(A1, pW1, b1, h1h);
    }

    // Layer 2: agg(h1) -> A2; GEMM -> A3 fp16 (+b2, relu)
    k_agg2<<<(2 * N_NODES * 32 + 255) / 256, 256>>>();
    {
        dim3 grid(M_TILES, 2);
        k_mma<8, 256, true, true><<<grid, 256, SMEM_MMA>>>(A2, pW2, b2, A3);
    }

    // Layer 3: GEMM -> t3 fp16; agg(t3)+b3 -> out fp32
    {
        dim3 grid(M_TILES, 1);
        k_mma<8, 128, false, false><<<grid, 256, SMEM_MMA>>>(A3, pW3, nullptr, t3h);
    }
    k_agg_out<<<(N_NODES * 32 + 255) / 256, 256>>>(out, b3);
}

// round 10
// speedup vs baseline: 3.8048x; 1.0226x over previous
#include <cuda_runtime.h>
#include <cuda_fp16.h>
#include <stdint.h>

#define N_NODES 100000
#define N_EDGES 1600000
#define IN_F 50
#define HID 256
#define OUT_F 121
#define M_TILES ((N_NODES + 127) / 128)   // 782

// ===================== scratch (static __device__) ==========================
__device__ int   g_flag;
__device__ int   g_row32[N_EDGES];
__device__ int   g_col32[N_EDGES];
__device__ int   g_deg[N_NODES];
__device__ float g_dinv[N_NODES];
__device__ int   g_off[N_NODES + 1];
__device__ int   g_cur[N_NODES];
__device__ int   g_csr[N_EDGES];
__device__ int   g_bsum[128];

__device__ __half g_W1[256 * 64];     // W1^T padded K->64  [n][k]
__device__ __half g_W2[256 * 256];    // W2^T
__device__ __half g_W3[128 * 256];    // W3^T padded N->128

__device__ __half g_A1[(size_t)N_NODES * 64];    // agg1 out (GEMM1 A)
__device__ __half g_A2[(size_t)N_NODES * 256];   // agg2 out (GEMM2 A)
__device__ __half g_A3[(size_t)N_NODES * 256];   // relu(GEMM2 out) (GEMM3 A)
__device__ __half g_xh [(size_t)N_NODES * 52];   // x fp16, padded 50->52
__device__ __half g_h1h[(size_t)N_NODES * 256];  // h1 fp16 (agg2 gather input)
__device__ __half g_t3h[(size_t)N_NODES * 128];  // t3 fp16 (agg_out gather input)

// ===================== small PTX helpers (baseline features only) ===========
__device__ __forceinline__ uint32_t smem_u32(const void* p) {
    uint32_t a;
    asm("{ .reg .u64 t; cvta.to.shared.u64 t, %1; cvt.u32.u64 %0, t; }" : "=r"(a) : "l"(p));
    return a;
}

#define CP_ASYNC16(dst_u32, src_ptr) \
    asm volatile("cp.async.cg.shared.global [%0], [%1], 16;" :: "r"(dst_u32), "l"(src_ptr))
#define CP_COMMIT() asm volatile("cp.async.commit_group;" ::: "memory")

#define LDM_X4(R, ADDR) \
    asm volatile("ldmatrix.sync.aligned.m8n8.x4.shared.b16 {%0,%1,%2,%3}, [%4];" \
        : "=r"((R)[0]), "=r"((R)[1]), "=r"((R)[2]), "=r"((R)[3]) : "r"(ADDR))

__device__ __forceinline__ void mma16816h(float* d, const uint32_t* a, const uint32_t* b) {
    asm volatile(
        "mma.sync.aligned.m16n8k16.row.col.f32.f16.f16.f32 "
        "{%0,%1,%2,%3}, {%4,%5,%6,%7}, {%8,%9}, {%0,%1,%2,%3};"
        : "+f"(d[0]), "+f"(d[1]), "+f"(d[2]), "+f"(d[3])
        : "r"(a[0]), "r"(a[1]), "r"(a[2]), "r"(a[3]), "r"(b[0]), "r"(b[1]));
}

// ===================== kernel 1: detect (block 0) + init (all blocks) =======
__global__ void k_front(const long long* __restrict__ ei64) {
    int v = blockIdx.x * blockDim.x + threadIdx.x;
    if (v < N_NODES) { g_deg[v] = 1; g_cur[v] = 0; }
    if (blockIdx.x == 0) {
        __shared__ int bad;
        if (threadIdx.x == 0) bad = 0;
        __syncthreads();
        int ok = 1;
        for (int i = threadIdx.x; i < 4096; i += 256) {
            long long t = ei64[i];
            if (t < 0 || t >= N_NODES) ok = 0;
        }
        if (!ok) atomicOr(&bad, 1);
        __syncthreads();
        if (threadIdx.x == 0) g_flag = bad;
    }
}

// ===================== kernel 2: convert || prepx || prepw (block ranges) ===
#define NB_CONV ((N_EDGES / 2 + 255) / 256)            // 3125 (2 edges/thread)
#define NB_PX   ((N_NODES * 26 + 255) / 256)           // 10157 (1 half2/thread)
#define NB_PW   ((256*64 + 256*256 + 128*256 + 255) / 256)  // 480

__global__ void k_mid(const void* __restrict__ ei,
                      const float* __restrict__ x,
                      const float* __restrict__ W1, const float* __restrict__ W2,
                      const float* __restrict__ W3) {
    int b = blockIdx.x;
    if (b < NB_CONV) {
        // ---- convert + degree count, 2 edges per thread ----
        int e2 = b * 256 + threadIdx.x;
        int e = e2 * 2;
        if (e >= N_EDGES) return;
        int r0, c0, r1, c1;
        if (g_flag) {
            const int2* pr = (const int2*)((const int*)ei);
            const int2* pc = (const int2*)((const int*)ei + N_EDGES);
            int2 rr = pr[e2], cc = pc[e2];
            r0 = rr.x; r1 = rr.y; c0 = cc.x; c1 = cc.y;
        } else {
            const longlong2* pr = (const longlong2*)((const long long*)ei);
            const longlong2* pc = (const longlong2*)((const long long*)ei + N_EDGES);
            longlong2 rr = pr[e2], cc = pc[e2];
            r0 = (int)rr.x; r1 = (int)rr.y; c0 = (int)cc.x; c1 = (int)cc.y;
        }
        *(int2*)(g_row32 + e) = make_int2(r0, r1);
        *(int2*)(g_col32 + e) = make_int2(c0, c1);
        atomicAdd(&g_deg[c0], 1);
        atomicAdd(&g_deg[c1], 1);
    } else if (b < NB_CONV + NB_PX) {
        // ---- x -> fp16 padded [N][52], one half2 per thread ----
        int i = (b - NB_CONV) * 256 + threadIdx.x;    // half2 index over N*26
        if (i >= N_NODES * 26) return;
        int node = i / 26, c = i - node * 26;
        __half2 v;
        if (c < 25) {
            float2 f = *(const float2*)(x + (size_t)node * IN_F + c * 2);
            v = __floats2half2_rn(f.x, f.y);
        } else {
            v = __floats2half2_rn(0.f, 0.f);
        }
        *((__half2*)g_xh + i) = v;
    } else {
        // ---- weight prep fp16 transposed/padded ----
        int i = (b - NB_CONV - NB_PX) * 256 + threadIdx.x;
        if (i < 256 * 64) {
            int n = i >> 6, k = i & 63;
            g_W1[i] = __float2half((k < IN_F) ? W1[(size_t)k * 256 + n] : 0.f);
        } else if (i < 256 * 64 + 256 * 256) {
            int j = i - 256 * 64;
            int n = j >> 8, k = j & 255;
            g_W2[j] = __float2half(W2[(size_t)k * 256 + n]);
        } else if (i < 256 * 64 + 256 * 256 + 128 * 256) {
            int j = i - 256 * 64 - 256 * 256;
            int n = j >> 8, k = j & 255;
            g_W3[j] = __float2half((n < OUT_F) ? W3[(size_t)k * OUT_F + n] : 0.f);
        }
    }
}

// ===================== scan (+dinv fused), 2 kernels ========================
__global__ void k_scan1() {
    __shared__ int s[1024];
    int tid = threadIdx.x;
    int v = blockIdx.x * 1024 + tid;
    int d = (v < N_NODES) ? g_deg[v] : 1;
    if (v < N_NODES) g_dinv[v] = rsqrtf((float)d);
    int c = (v < N_NODES) ? (d - 1) : 0;
    s[tid] = c;
    __syncthreads();
    #pragma unroll
    for (int o = 1; o < 1024; o <<= 1) {
        int t = (tid >= o) ? s[tid - o] : 0;
        __syncthreads();
        if (tid >= o) s[tid] += t;
        __syncthreads();
    }
    if (v < N_NODES) g_off[v + 1] = s[tid];
    if (tid == 1023) g_bsum[blockIdx.x] = s[1023];
}

// scan3 with fused block-sum prefix (scan2 eliminated)
__global__ void k_scan3() {
    __shared__ int base;
    int tid = threadIdx.x;
    if (tid == 0) {
        int a = 0;
        for (int bb = 0; bb < (int)blockIdx.x; bb++) a += g_bsum[bb];
        base = a;
    }
    __syncthreads();
    int v = blockIdx.x * 1024 + tid;
    if (v < N_NODES) g_off[v + 1] += base;
    if (v == 0) g_off[0] = 0;
}

__global__ void k_scatter() {
    int e = blockIdx.x * blockDim.x + threadIdx.x;
    if (e < N_EDGES) {
        int c = g_col32[e];
        int p = g_off[c] + atomicAdd(&g_cur[c], 1);
        g_csr[p] = g_row32[e];
    }
}

// ===================== aggregation (fp16 gather + fp16 out) =================
// layer-1 agg: xh fp16 [N][52] (half2 lanes), out fp16 [N][64]
__global__ void k_agg1() {
    const __half2* X2 = (const __half2*)g_xh;   // row stride 26
    int gw = (blockIdx.x * blockDim.x + threadIdx.x) >> 5;
    int lane = threadIdx.x & 31;
    if (gw >= N_NODES) return;
    int node = gw;
    bool act = lane < 25;
    int c2 = act ? lane : 0;
    float dv = g_dinv[node];
    float2 xv = __half22float2(X2[(size_t)node * 26 + c2]);
    float ax = dv * xv.x, ay = dv * xv.y;
    int beg = g_off[node], end = g_off[node + 1];
    int j = beg;
    for (; j + 4 <= end; j += 4) {
        int u0 = g_csr[j], u1 = g_csr[j + 1], u2 = g_csr[j + 2], u3 = g_csr[j + 3];
        float d0 = g_dinv[u0], d1 = g_dinv[u1], d2 = g_dinv[u2], d3 = g_dinv[u3];
        float2 a0 = __half22float2(X2[(size_t)u0 * 26 + c2]);
        float2 a1 = __half22float2(X2[(size_t)u1 * 26 + c2]);
        float2 a2 = __half22float2(X2[(size_t)u2 * 26 + c2]);
        float2 a3 = __half22float2(X2[(size_t)u3 * 26 + c2]);
        ax += d0 * a0.x; ay += d0 * a0.y;
        ax += d1 * a1.x; ay += d1 * a1.y;
        ax += d2 * a2.x; ay += d2 * a2.y;
        ax += d3 * a3.x; ay += d3 * a3.y;
    }
    for (; j < end; j++) {
        int u = g_csr[j];
        float d = g_dinv[u];
        float2 a = __half22float2(X2[(size_t)u * 26 + c2]);
        ax += d * a.x; ay += d * a.y;
    }
    float v0 = act ? dv * ax : 0.f;
    float v1 = act ? dv * ay : 0.f;
    *(__half2*)(g_A1 + (size_t)node * 64 + lane * 2) = __floats2half2_rn(v0, v1);
}

// layer-2 agg: h1 fp16 [N][256] (uint2 lanes = 4 halves), out fp16 [N][256]
__global__ void k_agg2() {
    const uint2* X4 = (const uint2*)g_h1h;      // row stride 64 uint2
    int gw = (blockIdx.x * blockDim.x + threadIdx.x) >> 5;
    int lane = threadIdx.x & 31;
    if (gw >= 2 * N_NODES) return;
    int chunk = gw >= N_NODES ? 1 : 0;          // chunk-major: 6.4MB slice L2-resident
    int node = gw - chunk * N_NODES;
    int c4 = chunk * 32 + lane;
    float dv = g_dinv[node];
    uint2 raw = X4[(size_t)node * 64 + c4];
    float2 f01 = __half22float2(*(__half2*)&raw.x);
    float2 f23 = __half22float2(*(__half2*)&raw.y);
    float a0 = dv * f01.x, a1 = dv * f01.y, a2 = dv * f23.x, a3 = dv * f23.y;
    int beg = g_off[node], end = g_off[node + 1];
    int j = beg;
    for (; j + 4 <= end; j += 4) {
        int u0 = g_csr[j], u1 = g_csr[j + 1], u2 = g_csr[j + 2], u3 = g_csr[j + 3];
        float d0 = g_dinv[u0], d1 = g_dinv[u1], d2 = g_dinv[u2], d3 = g_dinv[u3];
        uint2 r0 = X4[(size_t)u0 * 64 + c4];
        uint2 r1 = X4[(size_t)u1 * 64 + c4];
        uint2 r2 = X4[(size_t)u2 * 64 + c4];
        uint2 r3 = X4[(size_t)u3 * 64 + c4];
        float2 p0a = __half22float2(*(__half2*)&r0.x), p0b = __half22float2(*(__half2*)&r0.y);
        float2 p1a = __half22float2(*(__half2*)&r1.x), p1b = __half22float2(*(__half2*)&r1.y);
        float2 p2a = __half22float2(*(__half2*)&r2.x), p2b = __half22float2(*(__half2*)&r2.y);
        float2 p3a = __half22float2(*(__half2*)&r3.x), p3b = __half22float2(*(__half2*)&r3.y);
        a0 += d0 * p0a.x; a1 += d0 * p0a.y; a2 += d0 * p0b.x; a3 += d0 * p0b.y;
        a0 += d1 * p1a.x; a1 += d1 * p1a.y; a2 += d1 * p1b.x; a3 += d1 * p1b.y;
        a0 += d2 * p2a.x; a1 += d2 * p2a.y; a2 += d2 * p2b.x; a3 += d2 * p2b.y;
        a0 += d3 * p3a.x; a1 += d3 * p3a.y; a2 += d3 * p3b.x; a3 += d3 * p3b.y;
    }
    for (; j < end; j++) {
        int u = g_csr[j];
        float d = g_dinv[u];
        uint2 r = X4[(size_t)u * 64 + c4];
        float2 pa = __half22float2(*(__half2*)&r.x), pb = __half22float2(*(__half2*)&r.y);
        a0 += d * pa.x; a1 += d * pa.y; a2 += d * pb.x; a3 += d * pb.y;
    }
    a0 *= dv; a1 *= dv; a2 *= dv; a3 *= dv;
    uint2 outv;
    *(__half2*)&outv.x = __floats2half2_rn(a0, a1);
    *(__half2*)&outv.y = __floats2half2_rn(a2, a3);
    *(uint2*)(g_A2 + (size_t)node * 256 + c4 * 4) = outv;
}

// final agg: t3 fp16 [N][128] (uint2 lanes), +bias, out [N][121] fp32
__global__ void k_agg_out(float* __restrict__ OUT, const float* __restrict__ bias) {
    const uint2* X4 = (const uint2*)g_t3h;      // row stride 32 uint2
    int gw = (blockIdx.x * blockDim.x + threadIdx.x) >> 5;
    int lane = threadIdx.x & 31;
    if (gw >= N_NODES) return;
    int node = gw;
    float dv = g_dinv[node];
    uint2 raw = X4[(size_t)node * 32 + lane];
    float2 f01 = __half22float2(*(__half2*)&raw.x);
    float2 f23 = __half22float2(*(__half2*)&raw.y);
    float a0 = dv * f01.x, a1 = dv * f01.y, a2 = dv * f23.x, a3 = dv * f23.y;
    int beg = g_off[node], end = g_off[node + 1];
    int j = beg;
    for (; j + 4 <= end; j += 4) {
        int u0 = g_csr[j], u1 = g_csr[j + 1], u2 = g_csr[j + 2], u3 = g_csr[j + 3];
        float d0 = g_dinv[u0], d1 = g_dinv[u1], d2 = g_dinv[u2], d3 = g_dinv[u3];
        uint2 r0 = X4[(size_t)u0 * 32 + lane];
        uint2 r1 = X4[(size_t)u1 * 32 + lane];
        uint2 r2 = X4[(size_t)u2 * 32 + lane];
        uint2 r3 = X4[(size_t)u3 * 32 + lane];
        float2 p0a = __half22float2(*(__half2*)&r0.x), p0b = __half22float2(*(__half2*)&r0.y);
        float2 p1a = __half22float2(*(__half2*)&r1.x), p1b = __half22float2(*(__half2*)&r1.y);
        float2 p2a = __half22float2(*(__half2*)&r2.x), p2b = __half22float2(*(__half2*)&r2.y);
        float2 p3a = __half22float2(*(__half2*)&r3.x), p3b = __half22float2(*(__half2*)&r3.y);
        a0 += d0 * p0a.x; a1 += d0 * p0a.y; a2 += d0 * p0b.x; a3 += d0 * p0b.y;
        a0 += d1 * p1a.x; a1 += d1 * p1a.y; a2 += d1 * p1b.x; a3 += d1 * p1b.y;
        a0 += d2 * p2a.x; a1 += d2 * p2a.y; a2 += d2 * p2b.x; a3 += d2 * p2b.y;
        a0 += d3 * p3a.x; a1 += d3 * p3a.y; a2 += d3 * p3b.x; a3 += d3 * p3b.y;
    }
    for (; j < end; j++) {
        int u = g_csr[j];
        float d = g_dinv[u];
        uint2 r = X4[(size_t)u * 32 + lane];
        float2 pa = __half22float2(*(__half2*)&r.x), pb = __half22float2(*(__half2*)&r.y);
        a0 += d * pa.x; a1 += d * pa.y; a2 += d * pb.x; a3 += d * pb.y;
    }
    int c = lane * 4;
    float* dst = OUT + (size_t)node * OUT_F;
    if (c + 0 < OUT_F) dst[c + 0] = dv * a0 + bias[c + 0];
    if (c + 1 < OUT_F) dst[c + 1] = dv * a1 + bias[c + 1];
    if (c + 2 < OUT_F) dst[c + 2] = dv * a2 + bias[c + 2];
    if (c + 3 < OUT_F) dst[c + 3] = dv * a3 + bias[c + 3];
}

// ===================== warp-MMA GEMM (fp16 single-pass, 2-stage cp.async) ===
template<int KT, int NNTOT, bool BIAS, bool RELU>
__global__ void __launch_bounds__(256, 2)
k_mma(const __half* __restrict__ A, const __half* __restrict__ B,
      const float* __restrict__ bias, __half* __restrict__ C) {
    constexpr int ASTR = KT * 32;
    constexpr int PAD = 40;
    constexpr int ST = 128 * PAD;
    extern __shared__ __half dsm[];

    const int tid = threadIdx.x;
    const int wid = tid >> 5, lane = tid & 31;
    const int wm = wid & 3, wn = wid >> 2;
    const int m0 = blockIdx.x * 128;
    const int n0 = blockIdx.y * 128;

    float acc[2][8][4];
    #pragma unroll
    for (int mt = 0; mt < 2; mt++)
        #pragma unroll
        for (int nt = 0; nt < 8; nt++)
            #pragma unroll
            for (int q = 0; q < 4; q++) acc[mt][nt][q] = 0.f;

    auto stage = [&](int s, int c) {
        __half* base = dsm + s * 2 * ST;
        #pragma unroll
        for (int it = 0; it < 2; it++) {
            int idx = it * 256 + tid;
            int row = idx >> 2, chk = idx & 3;
            int m = m0 + row; if (m >= N_NODES) m = N_NODES - 1;
            size_t goA = (size_t)m * ASTR + c * 32 + chk * 8;
            size_t goB = (size_t)(n0 + row) * ASTR + c * 32 + chk * 8;
            int so = row * PAD + chk * 8;
            CP_ASYNC16(smem_u32(base + so), A + goA);
            CP_ASYNC16(smem_u32(base + ST + so), B + goB);
        }
        CP_COMMIT();
    };

    stage(0, 0);
    for (int c = 0; c < KT; c++) {
        if (c + 1 < KT) {
            stage((c + 1) & 1, c + 1);
            asm volatile("cp.async.wait_group 1;" ::: "memory");
        } else {
            asm volatile("cp.async.wait_group 0;" ::: "memory");
        }
        __syncthreads();

        const __half* sA = dsm + (c & 1) * 2 * ST;
        const __half* sB = sA + ST;

        #pragma unroll
        for (int ks = 0; ks < 2; ks++) {
            const int kc = ks * 16;
            uint32_t a_f[2][4];
            #pragma unroll
            for (int mt = 0; mt < 2; mt++) {
                int r = wm * 32 + mt * 16 + (lane & 15);
                int cA = kc + ((lane >> 4) << 3);
                LDM_X4(a_f[mt], smem_u32(sA + r * PAD + cA));
            }
            #pragma unroll
            for (int ntp = 0; ntp < 4; ntp++) {
                int br = wn * 64 + ntp * 16 + (lane & 7) + ((lane & 16) ? 8 : 0);
                int cB = kc + ((lane & 8) ? 8 : 0);
                uint32_t b_f[4];
                LDM_X4(b_f, smem_u32(sB + br * PAD + cB));
                #pragma unroll
                for (int half = 0; half < 2; half++) {
                    int nt = ntp * 2 + half;
                    #pragma unroll
                    for (int mt = 0; mt < 2; mt++)
                        mma16816h(acc[mt][nt], a_f[mt], b_f + 2 * half);
                }
            }
        }
        __syncthreads();
    }

    #pragma unroll
    for (int mt = 0; mt < 2; mt++) {
        int mrow = m0 + wm * 32 + mt * 16 + (lane >> 2);
        #pragma unroll
        for (int nt = 0; nt < 8; nt++) {
            int n = n0 + wn * 64 + nt * 8 + (lane & 3) * 2;
            float v0 = acc[mt][nt][0], v1 = acc[mt][nt][1];
            float v2 = acc[mt][nt][2], v3 = acc[mt][nt][3];
            if (BIAS) {
                float bb0 = bias[n], bb1 = bias[n + 1];
                v0 += bb0; v1 += bb1; v2 += bb0; v3 += bb1;
            }
            if (RELU) {
                v0 = fmaxf(v0, 0.f); v1 = fmaxf(v1, 0.f);
                v2 = fmaxf(v2, 0.f); v3 = fmaxf(v3, 0.f);
            }
            if (mrow < N_NODES)
                *(__half2*)(C + (size_t)mrow * NNTOT + n) = __floats2half2_rn(v0, v1);
            if (mrow + 8 < N_NODES)
                *(__half2*)(C + (size_t)(mrow + 8) * NNTOT + n) = __floats2half2_rn(v2, v3);
        }
    }
}

// ===================== launch ===============================================
static inline void* sym(const void* s) {
    void* p = nullptr;
    cudaGetSymbolAddress(&p, s);
    return p;
}

extern "C" void kernel_launch(void* const* d_in, const int* in_sizes, int n_in,
                              void* d_out, int out_size) {
    const float* x   = (const float*)d_in[0];
    const void*  ei  = d_in[1];
    const float* W1  = (const float*)d_in[2];
    const float* b1  = (const float*)d_in[3];
    const float* W2  = (const float*)d_in[4];
    const float* b2  = (const float*)d_in[5];
    const float* W3  = (const float*)d_in[6];
    const float* b3  = (const float*)d_in[7];
    float*       out = (float*)d_out;

    __half* pW1 = (__half*)sym(g_W1);
    __half* pW2 = (__half*)sym(g_W2);
    __half* pW3 = (__half*)sym(g_W3);
    __half* A1  = (__half*)sym(g_A1);
    __half* A2  = (__half*)sym(g_A2);
    __half* A3  = (__half*)sym(g_A3);
    __half* h1h = (__half*)sym(g_h1h);
    __half* t3h = (__half*)sym(g_t3h);

    const int NB_N = (N_NODES + 255) / 256;
    const int NB_E = (N_EDGES + 255) / 256;
    const int NBLK = (N_NODES + 1023) / 1024;

    const int SMEM_MMA = 2 * 2 * 128 * 40 * (int)sizeof(__half);  // 40960
    cudaFuncSetAttribute(k_mma<2, 256, true,  true >, cudaFuncAttributeMaxDynamicSharedMemorySize, SMEM_MMA);
    cudaFuncSetAttribute(k_mma<8, 256, true,  true >, cudaFuncAttributeMaxDynamicSharedMemorySize, SMEM_MMA);
    cudaFuncSetAttribute(k_mma<8, 128, false, false>, cudaFuncAttributeMaxDynamicSharedMemorySize, SMEM_MMA);

    // preprocessing (fused): detect+init, then convert||prepx||prepw
    k_front  <<<NB_N, 256>>>((const long long*)ei);
    k_mid    <<<NB_CONV + NB_PX + NB_PW, 256>>>(ei, x, W1, W2, W3);
    k_scan1  <<<NBLK, 1024>>>();          // also computes dinv
    k_scan3  <<<NBLK, 1024>>>();          // fused block-prefix + add
    k_scatter<<<NB_E, 256>>>();

    // Layer 1: agg(xh) -> A1; GEMM -> h1 fp16 (+b1, relu)
    k_agg1<<<(N_NODES * 32 + 255) / 256, 256>>>();
    {
        dim3 grid(M_TILES, 2);
        k_mma<2, 256, true, true><<<grid, 256, SMEM_MMA>>>(A1, pW1, b1, h1h);
    }

    // Layer 2: agg(h1) -> A2; GEMM -> A3 fp16 (+b2, relu)
    k_agg2<<<(2 * N_NODES * 32 + 255) / 256, 256>>>();
    {
        dim3 grid(M_TILES, 2);
        k_mma<8, 256, true, true><<<grid, 256, SMEM_MMA>>>(A2, pW2, b2, A3);
    }

    // Layer 3: GEMM -> t3 fp16; agg(t3)+b3 -> out fp32
    {
        dim3 grid(M_TILES, 1);
        k_mma<8, 128, false, false><<<grid, 256, SMEM_MMA>>>(A3, pW3, nullptr, t3h);
    }
    k_agg_out<<<(N_NODES * 32 + 255) / 256, 256>>>(out, b3);
}

// round 11
// speedup vs baseline: 3.8501x; 1.0119x over previous
#include <cuda_runtime.h>
#include <cuda_fp16.h>
#include <stdint.h>

#define N_NODES 100000
#define N_EDGES 1600000
#define IN_F 50
#define HID 256
#define OUT_F 121
#define M_TILES ((N_NODES + 127) / 128)   // 782

// ===================== scratch (static __device__) ==========================
__device__ int   g_flag;
__device__ int   g_total;
__device__ int   g_deg[N_NODES];
__device__ int   g_beg[N_NODES];
__device__ float g_dinv[N_NODES];
__device__ int   g_cur[N_NODES];
__device__ int   g_csr[N_EDGES];

__device__ __half g_W1[256 * 64];     // W1^T padded K->64  [n][k]
__device__ __half g_W2[256 * 256];    // W2^T
__device__ __half g_W3[128 * 256];    // W3^T padded N->128

__device__ __half g_A1[(size_t)N_NODES * 64];    // agg1 out (GEMM1 A)
__device__ __half g_A2[(size_t)N_NODES * 256];   // agg2 out (GEMM2 A)
__device__ __half g_A3[(size_t)N_NODES * 256];   // relu(GEMM2 out) (GEMM3 A)
__device__ __half g_xh [(size_t)N_NODES * 52];   // x fp16, padded 50->52
__device__ __half g_h1h[(size_t)N_NODES * 256];  // h1 fp16 (agg2 gather input)
__device__ __half g_t3h[(size_t)N_NODES * 128];  // t3 fp16 (agg_out gather input)

// ===================== small PTX helpers (baseline features only) ===========
__device__ __forceinline__ uint32_t smem_u32(const void* p) {
    uint32_t a;
    asm("{ .reg .u64 t; cvta.to.shared.u64 t, %1; cvt.u32.u64 %0, t; }" : "=r"(a) : "l"(p));
    return a;
}

#define CP_ASYNC16(dst_u32, src_ptr) \
    asm volatile("cp.async.cg.shared.global [%0], [%1], 16;" :: "r"(dst_u32), "l"(src_ptr))
#define CP_COMMIT() asm volatile("cp.async.commit_group;" ::: "memory")

#define LDM_X4(R, ADDR) \
    asm volatile("ldmatrix.sync.aligned.m8n8.x4.shared.b16 {%0,%1,%2,%3}, [%4];" \
        : "=r"((R)[0]), "=r"((R)[1]), "=r"((R)[2]), "=r"((R)[3]) : "r"(ADDR))

__device__ __forceinline__ void mma16816h(float* d, const uint32_t* a, const uint32_t* b) {
    asm volatile(
        "mma.sync.aligned.m16n8k16.row.col.f32.f16.f16.f32 "
        "{%0,%1,%2,%3}, {%4,%5,%6,%7}, {%8,%9}, {%0,%1,%2,%3};"
        : "+f"(d[0]), "+f"(d[1]), "+f"(d[2]), "+f"(d[3])
        : "r"(a[0]), "r"(a[1]), "r"(a[2]), "r"(a[3]), "r"(b[0]), "r"(b[1]));
}

// ===================== kernel 1: detect (block 0) + init (all blocks) =======
__global__ void k_front(const long long* __restrict__ ei64) {
    int v = blockIdx.x * blockDim.x + threadIdx.x;
    if (v < N_NODES) { g_deg[v] = 1; g_cur[v] = 0; }
    if (blockIdx.x == 0) {
        __shared__ int bad;
        if (threadIdx.x == 0) { bad = 0; g_total = 0; }
        __syncthreads();
        int ok = 1;
        for (int i = threadIdx.x; i < 4096; i += 256) {
            long long t = ei64[i];
            if (t < 0 || t >= N_NODES) ok = 0;
        }
        if (!ok) atomicOr(&bad, 1);
        __syncthreads();
        if (threadIdx.x == 0) g_flag = bad;
    }
}

// ===================== kernel 2: degcount || prepx || prepw (block ranges) ==
#define NB_CONV ((N_EDGES / 2 + 255) / 256)            // 3125 (2 edges/thread)
#define NB_PX   ((N_NODES * 26 + 255) / 256)           // 10157 (1 half2/thread)
#define NB_PW   ((256*64 + 256*256 + 128*256 + 255) / 256)  // 480

__global__ void k_mid(const void* __restrict__ ei,
                      const float* __restrict__ x,
                      const float* __restrict__ W1, const float* __restrict__ W2,
                      const float* __restrict__ W3) {
    int b = blockIdx.x;
    if (b < NB_CONV) {
        // ---- degree count only (read col half of ei), 2 edges per thread ----
        int e2 = b * 256 + threadIdx.x;
        if (e2 * 2 >= N_EDGES) return;
        int c0, c1;
        if (g_flag) {
            int2 cc = ((const int2*)((const int*)ei + N_EDGES))[e2];
            c0 = cc.x; c1 = cc.y;
        } else {
            longlong2 cc = ((const longlong2*)((const long long*)ei + N_EDGES))[e2];
            c0 = (int)cc.x; c1 = (int)cc.y;
        }
        atomicAdd(&g_deg[c0], 1);
        atomicAdd(&g_deg[c1], 1);
    } else if (b < NB_CONV + NB_PX) {
        // ---- x -> fp16 padded [N][52], one half2 per thread ----
        int i = (b - NB_CONV) * 256 + threadIdx.x;
        if (i >= N_NODES * 26) return;
        int node = i / 26, c = i - node * 26;
        __half2 v;
        if (c < 25) {
            float2 f = *(const float2*)(x + (size_t)node * IN_F + c * 2);
            v = __floats2half2_rn(f.x, f.y);
        } else {
            v = __floats2half2_rn(0.f, 0.f);
        }
        *((__half2*)g_xh + i) = v;
    } else {
        // ---- weight prep fp16 transposed/padded ----
        int i = (b - NB_CONV - NB_PX) * 256 + threadIdx.x;
        if (i < 256 * 64) {
            int n = i >> 6, k = i & 63;
            g_W1[i] = __float2half((k < IN_F) ? W1[(size_t)k * 256 + n] : 0.f);
        } else if (i < 256 * 64 + 256 * 256) {
            int j = i - 256 * 64;
            int n = j >> 8, k = j & 255;
            g_W2[j] = __float2half(W2[(size_t)k * 256 + n]);
        } else if (i < 256 * 64 + 256 * 256 + 128 * 256) {
            int j = i - 256 * 64 - 256 * 256;
            int n = j >> 8, k = j & 255;
            g_W3[j] = __float2half((n < OUT_F) ? W3[(size_t)k * OUT_F + n] : 0.f);
        }
    }
}

// ===================== CSR range allocation (no scan): warp-agg atomic ======
__global__ void k_alloc() {
    int v = blockIdx.x * blockDim.x + threadIdx.x;
    int lane = threadIdx.x & 31;
    int d = (v < N_NODES) ? g_deg[v] : 1;
    if (v < N_NODES) g_dinv[v] = rsqrtf((float)d);
    int cnt = (v < N_NODES) ? (d - 1) : 0;
    int pre = cnt;
    #pragma unroll
    for (int o = 1; o < 32; o <<= 1) {
        int t = __shfl_up_sync(0xFFFFFFFFu, pre, o);
        if (lane >= o) pre += t;
    }
    int total = __shfl_sync(0xFFFFFFFFu, pre, 31);
    int base = 0;
    if (lane == 31 && total > 0) base = atomicAdd(&g_total, total);
    base = __shfl_sync(0xFFFFFFFFu, base, 31);
    if (v < N_NODES) g_beg[v] = base + pre - cnt;
}

// ===================== scatter: read ei directly ============================
__global__ void k_scatter(const void* __restrict__ ei) {
    int e = blockIdx.x * blockDim.x + threadIdx.x;
    if (e >= N_EDGES) return;
    int r, c;
    if (g_flag) {
        const int* p = (const int*)ei;
        r = p[e]; c = p[N_EDGES + e];
    } else {
        const long long* p = (const long long*)ei;
        r = (int)p[e]; c = (int)p[N_EDGES + e];
    }
    int pos = g_beg[c] + atomicAdd(&g_cur[c], 1);
    g_csr[pos] = r;
}

// ===================== aggregation (fp16 gather + fp16 out) =================
// layer-1 agg: xh fp16 [N][52] (half2 lanes), out fp16 [N][64]
__global__ void k_agg1() {
    const __half2* X2 = (const __half2*)g_xh;   // row stride 26
    int gw = (blockIdx.x * blockDim.x + threadIdx.x) >> 5;
    int lane = threadIdx.x & 31;
    if (gw >= N_NODES) return;
    int node = gw;
    bool act = lane < 25;
    int c2 = act ? lane : 0;
    float dv = g_dinv[node];
    float2 xv = __half22float2(X2[(size_t)node * 26 + c2]);
    float ax = dv * xv.x, ay = dv * xv.y;
    int beg = g_beg[node], end = beg + g_deg[node] - 1;
    int j = beg;
    for (; j + 4 <= end; j += 4) {
        int u0 = g_csr[j], u1 = g_csr[j + 1], u2 = g_csr[j + 2], u3 = g_csr[j + 3];
        float d0 = g_dinv[u0], d1 = g_dinv[u1], d2 = g_dinv[u2], d3 = g_dinv[u3];
        float2 a0 = __half22float2(X2[(size_t)u0 * 26 + c2]);
        float2 a1 = __half22float2(X2[(size_t)u1 * 26 + c2]);
        float2 a2 = __half22float2(X2[(size_t)u2 * 26 + c2]);
        float2 a3 = __half22float2(X2[(size_t)u3 * 26 + c2]);
        ax += d0 * a0.x; ay += d0 * a0.y;
        ax += d1 * a1.x; ay += d1 * a1.y;
        ax += d2 * a2.x; ay += d2 * a2.y;
        ax += d3 * a3.x; ay += d3 * a3.y;
    }
    for (; j < end; j++) {
        int u = g_csr[j];
        float d = g_dinv[u];
        float2 a = __half22float2(X2[(size_t)u * 26 + c2]);
        ax += d * a.x; ay += d * a.y;
    }
    float v0 = act ? dv * ax : 0.f;
    float v1 = act ? dv * ay : 0.f;
    *(__half2*)(g_A1 + (size_t)node * 64 + lane * 2) = __floats2half2_rn(v0, v1);
}

// layer-2 agg: h1 fp16 [N][256] (uint2 lanes = 4 halves), out fp16 [N][256]
__global__ void k_agg2() {
    const uint2* X4 = (const uint2*)g_h1h;      // row stride 64 uint2
    int gw = (blockIdx.x * blockDim.x + threadIdx.x) >> 5;
    int lane = threadIdx.x & 31;
    if (gw >= 2 * N_NODES) return;
    int chunk = gw >= N_NODES ? 1 : 0;          // chunk-major: 6.4MB slice L2-resident
    int node = gw - chunk * N_NODES;
    int c4 = chunk * 32 + lane;
    float dv = g_dinv[node];
    uint2 raw = X4[(size_t)node * 64 + c4];
    float2 f01 = __half22float2(*(__half2*)&raw.x);
    float2 f23 = __half22float2(*(__half2*)&raw.y);
    float a0 = dv * f01.x, a1 = dv * f01.y, a2 = dv * f23.x, a3 = dv * f23.y;
    int beg = g_beg[node], end = beg + g_deg[node] - 1;
    int j = beg;
    for (; j + 4 <= end; j += 4) {
        int u0 = g_csr[j], u1 = g_csr[j + 1], u2 = g_csr[j + 2], u3 = g_csr[j + 3];
        float d0 = g_dinv[u0], d1 = g_dinv[u1], d2 = g_dinv[u2], d3 = g_dinv[u3];
        uint2 r0 = X4[(size_t)u0 * 64 + c4];
        uint2 r1 = X4[(size_t)u1 * 64 + c4];
        uint2 r2 = X4[(size_t)u2 * 64 + c4];
        uint2 r3 = X4[(size_t)u3 * 64 + c4];
        float2 p0a = __half22float2(*(__half2*)&r0.x), p0b = __half22float2(*(__half2*)&r0.y);
        float2 p1a = __half22float2(*(__half2*)&r1.x), p1b = __half22float2(*(__half2*)&r1.y);
        float2 p2a = __half22float2(*(__half2*)&r2.x), p2b = __half22float2(*(__half2*)&r2.y);
        float2 p3a = __half22float2(*(__half2*)&r3.x), p3b = __half22float2(*(__half2*)&r3.y);
        a0 += d0 * p0a.x; a1 += d0 * p0a.y; a2 += d0 * p0b.x; a3 += d0 * p0b.y;
        a0 += d1 * p1a.x; a1 += d1 * p1a.y; a2 += d1 * p1b.x; a3 += d1 * p1b.y;
        a0 += d2 * p2a.x; a1 += d2 * p2a.y; a2 += d2 * p2b.x; a3 += d2 * p2b.y;
        a0 += d3 * p3a.x; a1 += d3 * p3a.y; a2 += d3 * p3b.x; a3 += d3 * p3b.y;
    }
    for (; j < end; j++) {
        int u = g_csr[j];
        float d = g_dinv[u];
        uint2 r = X4[(size_t)u * 64 + c4];
        float2 pa = __half22float2(*(__half2*)&r.x), pb = __half22float2(*(__half2*)&r.y);
        a0 += d * pa.x; a1 += d * pa.y; a2 += d * pb.x; a3 += d * pb.y;
    }
    a0 *= dv; a1 *= dv; a2 *= dv; a3 *= dv;
    uint2 outv;
    *(__half2*)&outv.x = __floats2half2_rn(a0, a1);
    *(__half2*)&outv.y = __floats2half2_rn(a2, a3);
    *(uint2*)(g_A2 + (size_t)node * 256 + c4 * 4) = outv;
}

// final agg: t3 fp16 [N][128] (uint2 lanes), +bias, out [N][121] fp32
__global__ void k_agg_out(float* __restrict__ OUT, const float* __restrict__ bias) {
    const uint2* X4 = (const uint2*)g_t3h;      // row stride 32 uint2
    int gw = (blockIdx.x * blockDim.x + threadIdx.x) >> 5;
    int lane = threadIdx.x & 31;
    if (gw >= N_NODES) return;
    int node = gw;
    float dv = g_dinv[node];
    uint2 raw = X4[(size_t)node * 32 + lane];
    float2 f01 = __half22float2(*(__half2*)&raw.x);
    float2 f23 = __half22float2(*(__half2*)&raw.y);
    float a0 = dv * f01.x, a1 = dv * f01.y, a2 = dv * f23.x, a3 = dv * f23.y;
    int beg = g_beg[node], end = beg + g_deg[node] - 1;
    int j = beg;
    for (; j + 4 <= end; j += 4) {
        int u0 = g_csr[j], u1 = g_csr[j + 1], u2 = g_csr[j + 2], u3 = g_csr[j + 3];
        float d0 = g_dinv[u0], d1 = g_dinv[u1], d2 = g_dinv[u2], d3 = g_dinv[u3];
        uint2 r0 = X4[(size_t)u0 * 32 + lane];
        uint2 r1 = X4[(size_t)u1 * 32 + lane];
        uint2 r2 = X4[(size_t)u2 * 32 + lane];
        uint2 r3 = X4[(size_t)u3 * 32 + lane];
        float2 p0a = __half22float2(*(__half2*)&r0.x), p0b = __half22float2(*(__half2*)&r0.y);
        float2 p1a = __half22float2(*(__half2*)&r1.x), p1b = __half22float2(*(__half2*)&r1.y);
        float2 p2a = __half22float2(*(__half2*)&r2.x), p2b = __half22float2(*(__half2*)&r2.y);
        float2 p3a = __half22float2(*(__half2*)&r3.x), p3b = __half22float2(*(__half2*)&r3.y);
        a0 += d0 * p0a.x; a1 += d0 * p0a.y; a2 += d0 * p0b.x; a3 += d0 * p0b.y;
        a0 += d1 * p1a.x; a1 += d1 * p1a.y; a2 += d1 * p1b.x; a3 += d1 * p1b.y;
        a0 += d2 * p2a.x; a1 += d2 * p2a.y; a2 += d2 * p2b.x; a3 += d2 * p2b.y;
        a0 += d3 * p3a.x; a1 += d3 * p3a.y; a2 += d3 * p3b.x; a3 += d3 * p3b.y;
    }
    for (; j < end; j++) {
        int u = g_csr[j];
        float d = g_dinv[u];
        uint2 r = X4[(size_t)u * 32 + lane];
        float2 pa = __half22float2(*(__half2*)&r.x), pb = __half22float2(*(__half2*)&r.y);
        a0 += d * pa.x; a1 += d * pa.y; a2 += d * pb.x; a3 += d * pb.y;
    }
    int c = lane * 4;
    float* dst = OUT + (size_t)node * OUT_F;
    if (c + 0 < OUT_F) dst[c + 0] = dv * a0 + bias[c + 0];
    if (c + 1 < OUT_F) dst[c + 1] = dv * a1 + bias[c + 1];
    if (c + 2 < OUT_F) dst[c + 2] = dv * a2 + bias[c + 2];
    if (c + 3 < OUT_F) dst[c + 3] = dv * a3 + bias[c + 3];
}

// ===================== warp-MMA GEMM (fp16, BK=64, 2-stage cp.async) ========
// C[M, NNTOT] (+bias,relu) = A[M, KT*64] @ B[NNTOT, KT*64]^T, fp32 accum.
// Block 128x128xBK=64, 8 warps (4M x 2N), warp tile 32x64. Output fp16.
template<int KT, int NNTOT, bool BIAS, bool RELU>
__global__ void __launch_bounds__(256, 2)
k_mma(const __half* __restrict__ A, const __half* __restrict__ B,
      const float* __restrict__ bias, __half* __restrict__ C) {
    constexpr int ASTR = KT * 64;
    constexpr int PAD = 72;                  // 64 + 8 halves (conflict-free)
    constexpr int ST = 128 * PAD;            // elements per array per stage
    extern __shared__ __half dsm[];

    const int tid = threadIdx.x;
    const int wid = tid >> 5, lane = tid & 31;
    const int wm = wid & 3, wn = wid >> 2;
    const int m0 = blockIdx.x * 128;
    const int n0 = blockIdx.y * 128;

    float acc[2][8][4];
    #pragma unroll
    for (int mt = 0; mt < 2; mt++)
        #pragma unroll
        for (int nt = 0; nt < 8; nt++)
            #pragma unroll
            for (int q = 0; q < 4; q++) acc[mt][nt][q] = 0.f;

    auto stage = [&](int s, int c) {
        __half* base = dsm + s * 2 * ST;
        #pragma unroll
        for (int it = 0; it < 4; it++) {
            int idx = it * 256 + tid;        // 0..1023: row=idx>>3, chk=idx&7
            int row = idx >> 3, chk = idx & 7;
            int m = m0 + row; if (m >= N_NODES) m = N_NODES - 1;
            size_t goA = (size_t)m * ASTR + c * 64 + chk * 8;
            size_t goB = (size_t)(n0 + row) * ASTR + c * 64 + chk * 8;
            int so = row * PAD + chk * 8;
            CP_ASYNC16(smem_u32(base + so), A + goA);
            CP_ASYNC16(smem_u32(base + ST + so), B + goB);
        }
        CP_COMMIT();
    };

    stage(0, 0);
    for (int c = 0; c < KT; c++) {
        if (c + 1 < KT) {
            stage((c + 1) & 1, c + 1);
            asm volatile("cp.async.wait_group 1;" ::: "memory");
        } else {
            asm volatile("cp.async.wait_group 0;" ::: "memory");
        }
        __syncthreads();

        const __half* sA = dsm + (c & 1) * 2 * ST;
        const __half* sB = sA + ST;

        #pragma unroll
        for (int ks = 0; ks < 4; ks++) {
            const int kc = ks * 16;
            uint32_t a_f[2][4];
            #pragma unroll
            for (int mt = 0; mt < 2; mt++) {
                int r = wm * 32 + mt * 16 + (lane & 15);
                int cA = kc + ((lane >> 4) << 3);
                LDM_X4(a_f[mt], smem_u32(sA + r * PAD + cA));
            }
            #pragma unroll
            for (int ntp = 0; ntp < 4; ntp++) {
                int br = wn * 64 + ntp * 16 + (lane & 7) + ((lane & 16) ? 8 : 0);
                int cB = kc + ((lane & 8) ? 8 : 0);
                uint32_t b_f[4];
                LDM_X4(b_f, smem_u32(sB + br * PAD + cB));
                #pragma unroll
                for (int half = 0; half < 2; half++) {
                    int nt = ntp * 2 + half;
                    #pragma unroll
                    for (int mt = 0; mt < 2; mt++)
                        mma16816h(acc[mt][nt], a_f[mt], b_f + 2 * half);
                }
            }
        }
        __syncthreads();
    }

    #pragma unroll
    for (int mt = 0; mt < 2; mt++) {
        int mrow = m0 + wm * 32 + mt * 16 + (lane >> 2);
        #pragma unroll
        for (int nt = 0; nt < 8; nt++) {
            int n = n0 + wn * 64 + nt * 8 + (lane & 3) * 2;
            float v0 = acc[mt][nt][0], v1 = acc[mt][nt][1];
            float v2 = acc[mt][nt][2], v3 = acc[mt][nt][3];
            if (BIAS) {
                float bb0 = bias[n], bb1 = bias[n + 1];
                v0 += bb0; v1 += bb1; v2 += bb0; v3 += bb1;
            }
            if (RELU) {
                v0 = fmaxf(v0, 0.f); v1 = fmaxf(v1, 0.f);
                v2 = fmaxf(v2, 0.f); v3 = fmaxf(v3, 0.f);
            }
            if (mrow < N_NODES)
                *(__half2*)(C + (size_t)mrow * NNTOT + n) = __floats2half2_rn(v0, v1);
            if (mrow + 8 < N_NODES)
                *(__half2*)(C + (size_t)(mrow + 8) * NNTOT + n) = __floats2half2_rn(v2, v3);
        }
    }
}

// ===================== launch ===============================================
static inline void* sym(const void* s) {
    void* p = nullptr;
    cudaGetSymbolAddress(&p, s);
    return p;
}

extern "C" void kernel_launch(void* const* d_in, const int* in_sizes, int n_in,
                              void* d_out, int out_size) {
    const float* x   = (const float*)d_in[0];
    const void*  ei  = d_in[1];
    const float* W1  = (const float*)d_in[2];
    const float* b1  = (const float*)d_in[3];
    const float* W2  = (const float*)d_in[4];
    const float* b2  = (const float*)d_in[5];
    const float* W3  = (const float*)d_in[6];
    const float* b3  = (const float*)d_in[7];
    float*       out = (float*)d_out;

    __half* pW1 = (__half*)sym(g_W1);
    __half* pW2 = (__half*)sym(g_W2);
    __half* pW3 = (__half*)sym(g_W3);
    __half* A1  = (__half*)sym(g_A1);
    __half* A2  = (__half*)sym(g_A2);
    __half* A3  = (__half*)sym(g_A3);
    __half* h1h = (__half*)sym(g_h1h);
    __half* t3h = (__half*)sym(g_t3h);

    const int NB_N = (N_NODES + 255) / 256;
    const int NB_E = (N_EDGES + 255) / 256;

    const int SMEM_MMA = 2 * 2 * 128 * 72 * (int)sizeof(__half);  // 73728
    cudaFuncSetAttribute(k_mma<1, 256, true,  true >, cudaFuncAttributeMaxDynamicSharedMemorySize, SMEM_MMA);
    cudaFuncSetAttribute(k_mma<4, 256, true,  true >, cudaFuncAttributeMaxDynamicSharedMemorySize, SMEM_MMA);
    cudaFuncSetAttribute(k_mma<4, 128, false, false>, cudaFuncAttributeMaxDynamicSharedMemorySize, SMEM_MMA);

    // preprocessing: detect+init -> (degcount||prepx||prepw) -> alloc -> scatter
    k_front  <<<NB_N, 256>>>((const long long*)ei);
    k_mid    <<<NB_CONV + NB_PX + NB_PW, 256>>>(ei, x, W1, W2, W3);
    k_alloc  <<<NB_N, 256>>>();
    k_scatter<<<NB_E, 256>>>(ei);

    // Layer 1: agg(xh) -> A1; GEMM K=64 -> h1 fp16 (+b1, relu)
    k_agg1<<<(N_NODES * 32 + 255) / 256, 256>>>();
    {
        dim3 grid(M_TILES, 2);
        k_mma<1, 256, true, true><<<grid, 256, SMEM_MMA>>>(A1, pW1, b1, h1h);
    }

    // Layer 2: agg(h1) -> A2; GEMM K=256 -> A3 fp16 (+b2, relu)
    k_agg2<<<(2 * N_NODES * 32 + 255) / 256, 256>>>();
    {
        dim3 grid(M_TILES, 2);
        k_mma<4, 256, true, true><<<grid, 256, SMEM_MMA>>>(A2, pW2, b2, A3);
    }

    // Layer 3: GEMM K=256 -> t3 fp16; agg(t3)+b3 -> out fp32
    {
        dim3 grid(M_TILES, 1);
        k_mma<4, 128, false, false><<<grid, 256, SMEM_MMA>>>(A3, pW3, nullptr, t3h);
    }
    k_agg_out<<<(N_NODES * 32 + 255) / 256, 256>>>(out, b3);
}

// round 12
// speedup vs baseline: 4.0993x; 1.0647x over previous
#include <cuda_runtime.h>
#include <cuda_fp16.h>
#include <stdint.h>

#define N_NODES 100000
#define N_EDGES 1600000
#define IN_F 50
#define HID 256
#define OUT_F 121
#define M_TILES ((N_NODES + 127) / 128)   // 782

// ===================== scratch (static __device__) ==========================
__device__ int   g_flag;
__device__ int   g_total;
__device__ int   g_deg[N_NODES];
__device__ int   g_beg[N_NODES];
__device__ float g_dinv[N_NODES];
__device__ int   g_cur[N_NODES];
__device__ int   g_csr[N_EDGES];

__device__ __half g_W1[256 * 64];     // W1^T padded K->64  [n][k]
__device__ __half g_W2[256 * 256];    // W2^T
__device__ __half g_W3[128 * 256];    // W3^T padded N->128

__device__ __half g_A1[(size_t)N_NODES * 64];    // agg1 out (GEMM1 A)
__device__ __half g_A2[(size_t)N_NODES * 256];   // agg2 out (GEMM2 A)
__device__ __half g_A3[(size_t)N_NODES * 256];   // relu(GEMM2 out) (GEMM3 A)
__device__ __half g_xh [(size_t)N_NODES * 52];   // x fp16, padded 50->52
__device__ __half g_h1h[(size_t)N_NODES * 256];  // h1 fp16 (51.2MB: L2-resident)
__device__ __half g_t3h[(size_t)N_NODES * 128];  // t3 fp16 (25.6MB: L2-resident)

// ===================== small PTX helpers (baseline features only) ===========
__device__ __forceinline__ uint32_t smem_u32(const void* p) {
    uint32_t a;
    asm("{ .reg .u64 t; cvta.to.shared.u64 t, %1; cvt.u32.u64 %0, t; }" : "=r"(a) : "l"(p));
    return a;
}

#define CP_ASYNC16(dst_u32, src_ptr) \
    asm volatile("cp.async.cg.shared.global [%0], [%1], 16;" :: "r"(dst_u32), "l"(src_ptr))
#define CP_COMMIT() asm volatile("cp.async.commit_group;" ::: "memory")

#define LDM_X4(R, ADDR) \
    asm volatile("ldmatrix.sync.aligned.m8n8.x4.shared.b16 {%0,%1,%2,%3}, [%4];" \
        : "=r"((R)[0]), "=r"((R)[1]), "=r"((R)[2]), "=r"((R)[3]) : "r"(ADDR))

__device__ __forceinline__ void mma16816h(float* d, const uint32_t* a, const uint32_t* b) {
    asm volatile(
        "mma.sync.aligned.m16n8k16.row.col.f32.f16.f16.f32 "
        "{%0,%1,%2,%3}, {%4,%5,%6,%7}, {%8,%9}, {%0,%1,%2,%3};"
        : "+f"(d[0]), "+f"(d[1]), "+f"(d[2]), "+f"(d[3])
        : "r"(a[0]), "r"(a[1]), "r"(a[2]), "r"(a[3]), "r"(b[0]), "r"(b[1]));
}

// ===================== kernel 1: detect (block 0) + init (all blocks) =======
__global__ void k_front(const long long* __restrict__ ei64) {
    int v = blockIdx.x * blockDim.x + threadIdx.x;
    if (v < N_NODES) { g_deg[v] = 1; g_cur[v] = 0; }
    if (blockIdx.x == 0) {
        __shared__ int bad;
        if (threadIdx.x == 0) { bad = 0; g_total = 0; }
        __syncthreads();
        int ok = 1;
        for (int i = threadIdx.x; i < 4096; i += 256) {
            long long t = ei64[i];
            if (t < 0 || t >= N_NODES) ok = 0;
        }
        if (!ok) atomicOr(&bad, 1);
        __syncthreads();
        if (threadIdx.x == 0) g_flag = bad;
    }
}

// ===================== kernel 2: degcount || prepx || prepw (block ranges) ==
#define NB_CONV ((N_EDGES / 2 + 255) / 256)            // 3125 (2 edges/thread)
#define NB_PX   ((N_NODES * 26 + 255) / 256)           // 10157 (1 half2/thread)
#define NB_PW   ((256*64 + 256*256 + 128*256 + 255) / 256)  // 480

__global__ void k_mid(const void* __restrict__ ei,
                      const float* __restrict__ x,
                      const float* __restrict__ W1, const float* __restrict__ W2,
                      const float* __restrict__ W3) {
    int b = blockIdx.x;
    if (b < NB_CONV) {
        // ---- degree count only (read col half of ei), 2 edges per thread ----
        int e2 = b * 256 + threadIdx.x;
        if (e2 * 2 >= N_EDGES) return;
        int c0, c1;
        if (g_flag) {
            int2 cc = ((const int2*)((const int*)ei + N_EDGES))[e2];
            c0 = cc.x; c1 = cc.y;
        } else {
            longlong2 cc = ((const longlong2*)((const long long*)ei + N_EDGES))[e2];
            c0 = (int)cc.x; c1 = (int)cc.y;
        }
        atomicAdd(&g_deg[c0], 1);
        atomicAdd(&g_deg[c1], 1);
    } else if (b < NB_CONV + NB_PX) {
        // ---- x -> fp16 padded [N][52], one half2 per thread ----
        int i = (b - NB_CONV) * 256 + threadIdx.x;
        if (i >= N_NODES * 26) return;
        int node = i / 26, c = i - node * 26;
        __half2 v;
        if (c < 25) {
            float2 f = *(const float2*)(x + (size_t)node * IN_F + c * 2);
            v = __floats2half2_rn(f.x, f.y);
        } else {
            v = __floats2half2_rn(0.f, 0.f);
        }
        *((__half2*)g_xh + i) = v;
    } else {
        // ---- weight prep fp16 transposed/padded ----
        int i = (b - NB_CONV - NB_PX) * 256 + threadIdx.x;
        if (i < 256 * 64) {
            int n = i >> 6, k = i & 63;
            g_W1[i] = __float2half((k < IN_F) ? W1[(size_t)k * 256 + n] : 0.f);
        } else if (i < 256 * 64 + 256 * 256) {
            int j = i - 256 * 64;
            int n = j >> 8, k = j & 255;
            g_W2[j] = __float2half(W2[(size_t)k * 256 + n]);
        } else if (i < 256 * 64 + 256 * 256 + 128 * 256) {
            int j = i - 256 * 64 - 256 * 256;
            int n = j >> 8, k = j & 255;
            g_W3[j] = __float2half((n < OUT_F) ? W3[(size_t)k * OUT_F + n] : 0.f);
        }
    }
}

// ===================== CSR range allocation (no scan): warp-agg atomic ======
__global__ void k_alloc() {
    int v = blockIdx.x * blockDim.x + threadIdx.x;
    int lane = threadIdx.x & 31;
    int d = (v < N_NODES) ? g_deg[v] : 1;
    if (v < N_NODES) g_dinv[v] = rsqrtf((float)d);
    int cnt = (v < N_NODES) ? (d - 1) : 0;
    int pre = cnt;
    #pragma unroll
    for (int o = 1; o < 32; o <<= 1) {
        int t = __shfl_up_sync(0xFFFFFFFFu, pre, o);
        if (lane >= o) pre += t;
    }
    int total = __shfl_sync(0xFFFFFFFFu, pre, 31);
    int base = 0;
    if (lane == 31 && total > 0) base = atomicAdd(&g_total, total);
    base = __shfl_sync(0xFFFFFFFFu, base, 31);
    if (v < N_NODES) g_beg[v] = base + pre - cnt;
}

// ===================== scatter: 2 edges/thread, vectorized ei reads =========
__global__ void k_scatter(const void* __restrict__ ei) {
    int e2 = blockIdx.x * blockDim.x + threadIdx.x;
    if (e2 * 2 >= N_EDGES) return;
    int r0, r1, c0, c1;
    if (g_flag) {
        int2 rr = ((const int2*)((const int*)ei))[e2];
        int2 cc = ((const int2*)((const int*)ei + N_EDGES))[e2];
        r0 = rr.x; r1 = rr.y; c0 = cc.x; c1 = cc.y;
    } else {
        longlong2 rr = ((const longlong2*)((const long long*)ei))[e2];
        longlong2 cc = ((const longlong2*)((const long long*)ei + N_EDGES))[e2];
        r0 = (int)rr.x; r1 = (int)rr.y; c0 = (int)cc.x; c1 = (int)cc.y;
    }
    int p0 = g_beg[c0] + atomicAdd(&g_cur[c0], 1);
    g_csr[p0] = r0;
    int p1 = g_beg[c1] + atomicAdd(&g_cur[c1], 1);
    g_csr[p1] = r1;
}

// ===================== aggregation (fp16 gather + fp16 out) =================
// layer-1 agg: xh fp16 [N][52] (half2 lanes), out fp16 [N][64]
__global__ void k_agg1() {
    const __half2* X2 = (const __half2*)g_xh;   // row stride 26
    int gw = (blockIdx.x * blockDim.x + threadIdx.x) >> 5;
    int lane = threadIdx.x & 31;
    if (gw >= N_NODES) return;
    int node = gw;
    bool act = lane < 25;
    int c2 = act ? lane : 0;
    float dv = g_dinv[node];
    float2 xv = __half22float2(X2[(size_t)node * 26 + c2]);
    float ax = dv * xv.x, ay = dv * xv.y;
    int beg = g_beg[node], end = beg + g_deg[node] - 1;
    int j = beg;
    for (; j + 4 <= end; j += 4) {
        int u0 = g_csr[j], u1 = g_csr[j + 1], u2 = g_csr[j + 2], u3 = g_csr[j + 3];
        float d0 = g_dinv[u0], d1 = g_dinv[u1], d2 = g_dinv[u2], d3 = g_dinv[u3];
        float2 a0 = __half22float2(X2[(size_t)u0 * 26 + c2]);
        float2 a1 = __half22float2(X2[(size_t)u1 * 26 + c2]);
        float2 a2 = __half22float2(X2[(size_t)u2 * 26 + c2]);
        float2 a3 = __half22float2(X2[(size_t)u3 * 26 + c2]);
        ax += d0 * a0.x; ay += d0 * a0.y;
        ax += d1 * a1.x; ay += d1 * a1.y;
        ax += d2 * a2.x; ay += d2 * a2.y;
        ax += d3 * a3.x; ay += d3 * a3.y;
    }
    for (; j < end; j++) {
        int u = g_csr[j];
        float d = g_dinv[u];
        float2 a = __half22float2(X2[(size_t)u * 26 + c2]);
        ax += d * a.x; ay += d * a.y;
    }
    float v0 = act ? dv * ax : 0.f;
    float v1 = act ? dv * ay : 0.f;
    *(__half2*)(g_A1 + (size_t)node * 64 + lane * 2) = __floats2half2_rn(v0, v1);
}

// layer-2 agg: SINGLE PASS. uint4 lanes (8 halves), 32 lanes cover 256 cols.
// h1h (51.2MB) is fully L2-resident; no chunk split needed.
__global__ void k_agg2() {
    const uint4* X = (const uint4*)g_h1h;       // row stride 32 uint4
    int gw = (blockIdx.x * blockDim.x + threadIdx.x) >> 5;
    int lane = threadIdx.x & 31;
    if (gw >= N_NODES) return;
    int node = gw;
    float dv = g_dinv[node];
    float a[8];
    {
        uint4 raw = X[(size_t)node * 32 + lane];
        float2 f0 = __half22float2(*(__half2*)&raw.x);
        float2 f1 = __half22float2(*(__half2*)&raw.y);
        float2 f2 = __half22float2(*(__half2*)&raw.z);
        float2 f3 = __half22float2(*(__half2*)&raw.w);
        a[0] = dv * f0.x; a[1] = dv * f0.y; a[2] = dv * f1.x; a[3] = dv * f1.y;
        a[4] = dv * f2.x; a[5] = dv * f2.y; a[6] = dv * f3.x; a[7] = dv * f3.y;
    }
    int beg = g_beg[node], end = beg + g_deg[node] - 1;
    int j = beg;
    for (; j + 4 <= end; j += 4) {
        int u0 = g_csr[j], u1 = g_csr[j + 1], u2 = g_csr[j + 2], u3 = g_csr[j + 3];
        float d0 = g_dinv[u0], d1 = g_dinv[u1], d2 = g_dinv[u2], d3 = g_dinv[u3];
        uint4 r0 = X[(size_t)u0 * 32 + lane];
        uint4 r1 = X[(size_t)u1 * 32 + lane];
        uint4 r2 = X[(size_t)u2 * 32 + lane];
        uint4 r3 = X[(size_t)u3 * 32 + lane];
        #pragma unroll
        for (int q = 0; q < 1; q++) { /* keep structure flat below */ }
        {
            float2 f0 = __half22float2(*(__half2*)&r0.x), f1 = __half22float2(*(__half2*)&r0.y);
            float2 f2 = __half22float2(*(__half2*)&r0.z), f3 = __half22float2(*(__half2*)&r0.w);
            a[0] += d0 * f0.x; a[1] += d0 * f0.y; a[2] += d0 * f1.x; a[3] += d0 * f1.y;
            a[4] += d0 * f2.x; a[5] += d0 * f2.y; a[6] += d0 * f3.x; a[7] += d0 * f3.y;
        }
        {
            float2 f0 = __half22float2(*(__half2*)&r1.x), f1 = __half22float2(*(__half2*)&r1.y);
            float2 f2 = __half22float2(*(__half2*)&r1.z), f3 = __half22float2(*(__half2*)&r1.w);
            a[0] += d1 * f0.x; a[1] += d1 * f0.y; a[2] += d1 * f1.x; a[3] += d1 * f1.y;
            a[4] += d1 * f2.x; a[5] += d1 * f2.y; a[6] += d1 * f3.x; a[7] += d1 * f3.y;
        }
        {
            float2 f0 = __half22float2(*(__half2*)&r2.x), f1 = __half22float2(*(__half2*)&r2.y);
            float2 f2 = __half22float2(*(__half2*)&r2.z), f3 = __half22float2(*(__half2*)&r2.w);
            a[0] += d2 * f0.x; a[1] += d2 * f0.y; a[2] += d2 * f1.x; a[3] += d2 * f1.y;
            a[4] += d2 * f2.x; a[5] += d2 * f2.y; a[6] += d2 * f3.x; a[7] += d2 * f3.y;
        }
        {
            float2 f0 = __half22float2(*(__half2*)&r3.x), f1 = __half22float2(*(__half2*)&r3.y);
            float2 f2 = __half22float2(*(__half2*)&r3.z), f3 = __half22float2(*(__half2*)&r3.w);
            a[0] += d3 * f0.x; a[1] += d3 * f0.y; a[2] += d3 * f1.x; a[3] += d3 * f1.y;
            a[4] += d3 * f2.x; a[5] += d3 * f2.y; a[6] += d3 * f3.x; a[7] += d3 * f3.y;
        }
    }
    for (; j < end; j++) {
        int u = g_csr[j];
        float d = g_dinv[u];
        uint4 r = X[(size_t)u * 32 + lane];
        float2 f0 = __half22float2(*(__half2*)&r.x), f1 = __half22float2(*(__half2*)&r.y);
        float2 f2 = __half22float2(*(__half2*)&r.z), f3 = __half22float2(*(__half2*)&r.w);
        a[0] += d * f0.x; a[1] += d * f0.y; a[2] += d * f1.x; a[3] += d * f1.y;
        a[4] += d * f2.x; a[5] += d * f2.y; a[6] += d * f3.x; a[7] += d * f3.y;
    }
    uint4 outv;
    *(__half2*)&outv.x = __floats2half2_rn(a[0] * dv, a[1] * dv);
    *(__half2*)&outv.y = __floats2half2_rn(a[2] * dv, a[3] * dv);
    *(__half2*)&outv.z = __floats2half2_rn(a[4] * dv, a[5] * dv);
    *(__half2*)&outv.w = __floats2half2_rn(a[6] * dv, a[7] * dv);
    *(uint4*)(g_A2 + (size_t)node * 256 + lane * 8) = outv;
}

// final agg: t3 fp16 [N][128] (uint2 lanes), +bias, out [N][121] fp32
__global__ void k_agg_out(float* __restrict__ OUT, const float* __restrict__ bias) {
    const uint2* X4 = (const uint2*)g_t3h;      // row stride 32 uint2
    int gw = (blockIdx.x * blockDim.x + threadIdx.x) >> 5;
    int lane = threadIdx.x & 31;
    if (gw >= N_NODES) return;
    int node = gw;
    float dv = g_dinv[node];
    uint2 raw = X4[(size_t)node * 32 + lane];
    float2 f01 = __half22float2(*(__half2*)&raw.x);
    float2 f23 = __half22float2(*(__half2*)&raw.y);
    float a0 = dv * f01.x, a1 = dv * f01.y, a2 = dv * f23.x, a3 = dv * f23.y;
    int beg = g_beg[node], end = beg + g_deg[node] - 1;
    int j = beg;
    for (; j + 4 <= end; j += 4) {
        int u0 = g_csr[j], u1 = g_csr[j + 1], u2 = g_csr[j + 2], u3 = g_csr[j + 3];
        float d0 = g_dinv[u0], d1 = g_dinv[u1], d2 = g_dinv[u2], d3 = g_dinv[u3];
        uint2 r0 = X4[(size_t)u0 * 32 + lane];
        uint2 r1 = X4[(size_t)u1 * 32 + lane];
        uint2 r2 = X4[(size_t)u2 * 32 + lane];
        uint2 r3 = X4[(size_t)u3 * 32 + lane];
        float2 p0a = __half22float2(*(__half2*)&r0.x), p0b = __half22float2(*(__half2*)&r0.y);
        float2 p1a = __half22float2(*(__half2*)&r1.x), p1b = __half22float2(*(__half2*)&r1.y);
        float2 p2a = __half22float2(*(__half2*)&r2.x), p2b = __half22float2(*(__half2*)&r2.y);
        float2 p3a = __half22float2(*(__half2*)&r3.x), p3b = __half22float2(*(__half2*)&r3.y);
        a0 += d0 * p0a.x; a1 += d0 * p0a.y; a2 += d0 * p0b.x; a3 += d0 * p0b.y;
        a0 += d1 * p1a.x; a1 += d1 * p1a.y; a2 += d1 * p1b.x; a3 += d1 * p1b.y;
        a0 += d2 * p2a.x; a1 += d2 * p2a.y; a2 += d2 * p2b.x; a3 += d2 * p2b.y;
        a0 += d3 * p3a.x; a1 += d3 * p3a.y; a2 += d3 * p3b.x; a3 += d3 * p3b.y;
    }
    for (; j < end; j++) {
        int u = g_csr[j];
        float d = g_dinv[u];
        uint2 r = X4[(size_t)u * 32 + lane];
        float2 pa = __half22float2(*(__half2*)&r.x), pb = __half22float2(*(__half2*)&r.y);
        a0 += d * pa.x; a1 += d * pa.y; a2 += d * pb.x; a3 += d * pb.y;
    }
    int c = lane * 4;
    float* dst = OUT + (size_t)node * OUT_F;
    if (c + 0 < OUT_F) dst[c + 0] = dv * a0 + bias[c + 0];
    if (c + 1 < OUT_F) dst[c + 1] = dv * a1 + bias[c + 1];
    if (c + 2 < OUT_F) dst[c + 2] = dv * a2 + bias[c + 2];
    if (c + 3 < OUT_F) dst[c + 3] = dv * a3 + bias[c + 3];
}

// ===================== warp-MMA GEMM (fp16, BK=64, 2-stage cp.async) ========
template<int KT, int NNTOT, bool BIAS, bool RELU>
__global__ void __launch_bounds__(256, 2)
k_mma(const __half* __restrict__ A, const __half* __restrict__ B,
      const float* __restrict__ bias, __half* __restrict__ C) {
    constexpr int ASTR = KT * 64;
    constexpr int PAD = 72;                  // 64 + 8 halves (conflict-free)
    constexpr int ST = 128 * PAD;            // elements per array per stage
    extern __shared__ __half dsm[];

    const int tid = threadIdx.x;
    const int wid = tid >> 5, lane = tid & 31;
    const int wm = wid & 3, wn = wid >> 2;
    const int m0 = blockIdx.x * 128;
    const int n0 = blockIdx.y * 128;

    float acc[2][8][4];
    #pragma unroll
    for (int mt = 0; mt < 2; mt++)
        #pragma unroll
        for (int nt = 0; nt < 8; nt++)
            #pragma unroll
            for (int q = 0; q < 4; q++) acc[mt][nt][q] = 0.f;

    auto stage = [&](int s, int c) {
        __half* base = dsm + s * 2 * ST;
        #pragma unroll
        for (int it = 0; it < 4; it++) {
            int idx = it * 256 + tid;        // 0..1023: row=idx>>3, chk=idx&7
            int row = idx >> 3, chk = idx & 7;
            int m = m0 + row; if (m >= N_NODES) m = N_NODES - 1;
            size_t goA = (size_t)m * ASTR + c * 64 + chk * 8;
            size_t goB = (size_t)(n0 + row) * ASTR + c * 64 + chk * 8;
            int so = row * PAD + chk * 8;
            CP_ASYNC16(smem_u32(base + so), A + goA);
            CP_ASYNC16(smem_u32(base + ST + so), B + goB);
        }
        CP_COMMIT();
    };

    stage(0, 0);
    for (int c = 0; c < KT; c++) {
        if (c + 1 < KT) {
            stage((c + 1) & 1, c + 1);
            asm volatile("cp.async.wait_group 1;" ::: "memory");
        } else {
            asm volatile("cp.async.wait_group 0;" ::: "memory");
        }
        __syncthreads();

        const __half* sA = dsm + (c & 1) * 2 * ST;
        const __half* sB = sA + ST;

        #pragma unroll
        for (int ks = 0; ks < 4; ks++) {
            const int kc = ks * 16;
            uint32_t a_f[2][4];
            #pragma unroll
            for (int mt = 0; mt < 2; mt++) {
                int r = wm * 32 + mt * 16 + (lane & 15);
                int cA = kc + ((lane >> 4) << 3);
                LDM_X4(a_f[mt], smem_u32(sA + r * PAD + cA));
            }
            #pragma unroll
            for (int ntp = 0; ntp < 4; ntp++) {
                int br = wn * 64 + ntp * 16 + (lane & 7) + ((lane & 16) ? 8 : 0);
                int cB = kc + ((lane & 8) ? 8 : 0);
                uint32_t b_f[4];
                LDM_X4(b_f, smem_u32(sB + br * PAD + cB));
                #pragma unroll
                for (int half = 0; half < 2; half++) {
                    int nt = ntp * 2 + half;
                    #pragma unroll
                    for (int mt = 0; mt < 2; mt++)
                        mma16816h(acc[mt][nt], a_f[mt], b_f + 2 * half);
                }
            }
        }
        __syncthreads();
    }

    #pragma unroll
    for (int mt = 0; mt < 2; mt++) {
        int mrow = m0 + wm * 32 + mt * 16 + (lane >> 2);
        #pragma unroll
        for (int nt = 0; nt < 8; nt++) {
            int n = n0 + wn * 64 + nt * 8 + (lane & 3) * 2;
            float v0 = acc[mt][nt][0], v1 = acc[mt][nt][1];
            float v2 = acc[mt][nt][2], v3 = acc[mt][nt][3];
            if (BIAS) {
                float bb0 = bias[n], bb1 = bias[n + 1];
                v0 += bb0; v1 += bb1; v2 += bb0; v3 += bb1;
            }
            if (RELU) {
                v0 = fmaxf(v0, 0.f); v1 = fmaxf(v1, 0.f);
                v2 = fmaxf(v2, 0.f); v3 = fmaxf(v3, 0.f);
            }
            if (mrow < N_NODES)
                *(__half2*)(C + (size_t)mrow * NNTOT + n) = __floats2half2_rn(v0, v1);
            if (mrow + 8 < N_NODES)
                *(__half2*)(C + (size_t)(mrow + 8) * NNTOT + n) = __floats2half2_rn(v2, v3);
        }
    }
}

// ===================== launch ===============================================
static inline void* sym(const void* s) {
    void* p = nullptr;
    cudaGetSymbolAddress(&p, s);
    return p;
}

extern "C" void kernel_launch(void* const* d_in, const int* in_sizes, int n_in,
                              void* d_out, int out_size) {
    const float* x   = (const float*)d_in[0];
    const void*  ei  = d_in[1];
    const float* W1  = (const float*)d_in[2];
    const float* b1  = (const float*)d_in[3];
    const float* W2  = (const float*)d_in[4];
    const float* b2  = (const float*)d_in[5];
    const float* W3  = (const float*)d_in[6];
    const float* b3  = (const float*)d_in[7];
    float*       out = (float*)d_out;

    __half* pW1 = (__half*)sym(g_W1);
    __half* pW2 = (__half*)sym(g_W2);
    __half* pW3 = (__half*)sym(g_W3);
    __half* A1  = (__half*)sym(g_A1);
    __half* A2  = (__half*)sym(g_A2);
    __half* A3  = (__half*)sym(g_A3);
    __half* h1h = (__half*)sym(g_h1h);
    __half* t3h = (__half*)sym(g_t3h);

    const int NB_N = (N_NODES + 255) / 256;

    const int SMEM_MMA = 2 * 2 * 128 * 72 * (int)sizeof(__half);  // 73728
    cudaFuncSetAttribute(k_mma<1, 256, true,  true >, cudaFuncAttributeMaxDynamicSharedMemorySize, SMEM_MMA);
    cudaFuncSetAttribute(k_mma<4, 256, true,  true >, cudaFuncAttributeMaxDynamicSharedMemorySize, SMEM_MMA);
    cudaFuncSetAttribute(k_mma<4, 128, false, false>, cudaFuncAttributeMaxDynamicSharedMemorySize, SMEM_MMA);

    // preprocessing: detect+init -> (degcount||prepx||prepw) -> alloc -> scatter
    k_front  <<<NB_N, 256>>>((const long long*)ei);
    k_mid    <<<NB_CONV + NB_PX + NB_PW, 256>>>(ei, x, W1, W2, W3);
    k_alloc  <<<NB_N, 256>>>();
    k_scatter<<<(N_EDGES / 2 + 255) / 256, 256>>>(ei);

    // Layer 1: agg(xh) -> A1; GEMM K=64 -> h1 fp16 (+b1, relu)
    k_agg1<<<(N_NODES * 32 + 255) / 256, 256>>>();
    {
        dim3 grid(M_TILES, 2);
        k_mma<1, 256, true, true><<<grid, 256, SMEM_MMA>>>(A1, pW1, b1, h1h);
    }

    // Layer 2: agg(h1) single-pass -> A2; GEMM K=256 -> A3 fp16 (+b2, relu)
    k_agg2<<<(N_NODES * 32 + 255) / 256, 256>>>();
    {
        dim3 grid(M_TILES, 2);
        k_mma<4, 256, true, true><<<grid, 256, SMEM_MMA>>>(A2, pW2, b2, A3);
    }

    // Layer 3: GEMM K=256 -> t3 fp16; agg(t3)+b3 -> out fp32
    {
        dim3 grid(M_TILES, 1);
        k_mma<4, 128, false, false><<<grid, 256, SMEM_MMA>>>(A3, pW3, nullptr, t3h);
    }
    k_agg_out<<<(N_NODES * 32 + 255) / 256, 256>>>(out, b3);
}